// round 5
// baseline (speedup 1.0000x reference)
#include <cuda_runtime.h>
#include <math.h>
#include <stdint.h>

// ---------------------------------------------------------------------------
// SimpleVQAutoEncoder on GB300 — fp32 SIMT + FFMA2 convs + mma.sync tf32 VQ
//
//   K0: setup (codebook half-norms, parity-folded decoder weights)
//   K1: conv1(1->16,3x3,SAME) + maxpool2 + gelu        -> g_h1 [32,16,128,128]
//   K2: conv2(16->32,3x3,SAME) + maxpool2 (FFMA2)      -> g_h2 [32,32,64,64]
//   K3: VQ via mma.sync tf32 4-way split + argmin      -> g_hq, indices, g_part
//   K4: up2 + conv d1(32->16) folded (FFMA2, uniform-p)-> g_gg [32,16,128,128]
//   K5: up2 + conv d2(16->1)  folded + clip (uniform-p)-> out y
//   K6: reduce commit-loss partials                    -> out[last]
//
// Output layout (float32): [ y (32*256*256) | indices (32*64*64) | loss (1) ]
// ---------------------------------------------------------------------------

#define IDX_OFF   2097152
#define LOSS_OFF  2228224

typedef unsigned long long u64;

__device__ __forceinline__ u64 ffma2(u64 a, u64 b, u64 c) {
    u64 d;
    asm("fma.rn.f32x2 %0, %1, %2, %3;" : "=l"(d) : "l"(a), "l"(b), "l"(c));
    return d;
}
__device__ __forceinline__ u64 packff(float lo, float hi) {
    u64 d;
    asm("mov.b64 %0, {%1, %2};" : "=l"(d) : "f"(lo), "f"(hi));
    return d;
}
__device__ __forceinline__ float2 unpackff(u64 v) {
    float lo, hi;
    asm("mov.b64 {%0, %1}, %2;" : "=f"(lo), "=f"(hi) : "l"(v));
    return make_float2(lo, hi);
}

// m16n8k8 tf32 mma (sm_80+, works at base sm_103 target)
__device__ __forceinline__ void mma8(float& c0, float& c1, float& c2, float& c3,
                                     uint32_t a0, uint32_t a1, uint32_t a2,
                                     uint32_t a3, uint32_t b0, uint32_t b1) {
    asm volatile(
        "mma.sync.aligned.m16n8k8.row.col.f32.tf32.tf32.f32 "
        "{%0,%1,%2,%3}, {%4,%5,%6,%7}, {%8,%9}, {%0,%1,%2,%3};"
        : "+f"(c0), "+f"(c1), "+f"(c2), "+f"(c3)
        : "r"(a0), "r"(a1), "r"(a2), "r"(a3), "r"(b0), "r"(b1));
}

// Intermediates (device globals: no allocation allowed)
__device__ float g_h1[32 * 16 * 128 * 128];   // 33.5 MB
__device__ float g_h2[32 * 32 * 64 * 64];     // 16.8 MB
__device__ float g_hq[32 * 32 * 64 * 64];     // 16.8 MB
__device__ float g_gg[32 * 16 * 128 * 128];   // 33.5 MB
__device__ float g_cnh[512];                  // 0.5*||codebook_k||^2
__device__ float g_Wf1t[4 * 32 * 4 * 16];     // folded d1 [p][ci][uv][c]
__device__ float g_Wf2[4 * 16 * 4];           // folded d2 [p][ci][uv]
__device__ float g_part[1024];                // commit-loss partials

// ---------------------------------------------------------------------------
// K0: setup. Nearest-up2 folding: output (y,x) reads a 2x2 hq patch; the 3x3
// taps collapse per output parity (py,px) onto the 4 corners.
// ---------------------------------------------------------------------------
__global__ void __launch_bounds__(256) k0_setup(const float* __restrict__ cb,
                                                const float* __restrict__ d1w,
                                                const float* __restrict__ d2w) {
    int t = blockIdx.x * 256 + threadIdx.x;
    if (t < 8192) {
        int c = t & 15, uv = (t >> 4) & 3, ci = (t >> 6) & 31, p = t >> 11;
        int py = p >> 1, px = p & 1, u = uv >> 1, v = uv & 1;
        float s = 0.f;
        #pragma unroll
        for (int dy = 0; dy < 3; ++dy) {
            int ug = (py == 0) ? (dy >= 1) : (dy >= 2);
            if (ug != u) continue;
            #pragma unroll
            for (int dx = 0; dx < 3; ++dx) {
                int vg = (px == 0) ? (dx >= 1) : (dx >= 2);
                if (vg != v) continue;
                s += d1w[((c * 32 + ci) * 3 + dy) * 3 + dx];
            }
        }
        g_Wf1t[t] = s;
    } else if (t < 8704) {
        int k = t - 8192;
        float s = 0.f;
        #pragma unroll
        for (int c = 0; c < 32; ++c) { float v = cb[k * 32 + c]; s = fmaf(v, v, s); }
        g_cnh[k] = 0.5f * s;
    } else if (t < 8960) {
        int e = t - 8704;
        int uv = e & 3, ci = (e >> 2) & 15, p = e >> 6;
        int py = p >> 1, px = p & 1, u = uv >> 1, v = uv & 1;
        float s = 0.f;
        #pragma unroll
        for (int dy = 0; dy < 3; ++dy) {
            int ug = (py == 0) ? (dy >= 1) : (dy >= 2);
            if (ug != u) continue;
            #pragma unroll
            for (int dx = 0; dx < 3; ++dx) {
                int vg = (px == 0) ? (dx >= 1) : (dx >= 2);
                if (vg != v) continue;
                s += d2w[ci * 9 + dy * 3 + dx];
            }
        }
        g_Wf2[(p * 16 + ci) * 4 + uv] = s;
    }
}

// ---------------------------------------------------------------------------
// K1: conv1 + maxpool2 + exact gelu. Thread = (b, i, j) pooled pixel, 16 ch.
// ---------------------------------------------------------------------------
__global__ void __launch_bounds__(256) k1_conv1(const float* __restrict__ x,
                                                const float* __restrict__ w,
                                                const float* __restrict__ bias) {
    __shared__ float sw[144];
    __shared__ float sb[16];
    int tid = threadIdx.x;
    if (tid < 144) sw[tid] = __ldg(w + tid);
    if (tid < 16)  sb[tid] = __ldg(bias + tid);
    __syncthreads();

    int lin = blockIdx.x * 256 + tid;
    int j = lin & 127, i = (lin >> 7) & 127, b = lin >> 14;
    const float* xb = x + (b << 16);

    float xv[4][4];
    #pragma unroll
    for (int r = 0; r < 4; ++r) {
        int ry = 2 * i - 1 + r;
        bool rok = (unsigned)ry < 256u;
        #pragma unroll
        for (int cc = 0; cc < 4; ++cc) {
            int cx = 2 * j - 1 + cc;
            xv[r][cc] = (rok && (unsigned)cx < 256u) ? __ldg(xb + ry * 256 + cx) : 0.f;
        }
    }

    #pragma unroll
    for (int c = 0; c < 16; ++c) {
        float wv[9];
        #pragma unroll
        for (int k = 0; k < 9; ++k) wv[k] = sw[c * 9 + k];
        float m = -1e30f;
        #pragma unroll
        for (int py = 0; py < 2; ++py)
            #pragma unroll
            for (int px = 0; px < 2; ++px) {
                float s = 0.f;
                #pragma unroll
                for (int dy = 0; dy < 3; ++dy)
                    #pragma unroll
                    for (int dx = 0; dx < 3; ++dx)
                        s = fmaf(wv[dy * 3 + dx], xv[py + dy][px + dx], s);
                m = fmaxf(m, s);
            }
        m += sb[c];
        g_h1[((b * 16 + c) << 14) + (i << 7) + j] = m * normcdff(m);
    }
}

// ---------------------------------------------------------------------------
// K2: conv2(16->32) + maxpool2, FFMA2 on channel pairs, prepacked patch.
// ---------------------------------------------------------------------------
__global__ void __launch_bounds__(128) k2_conv2(const float* __restrict__ w,
                                                const float* __restrict__ bias) {
    __shared__ __align__(16) float swt[2304];  // [ci*9+tap][16c]
    __shared__ float sb[16];
    int tid = threadIdx.x;
    int lin = blockIdx.x * 128 + tid;
    int j = lin & 63, i = (lin >> 6) & 63, half = (lin >> 12) & 1, b = lin >> 13;

    for (int t = tid; t < 2304; t += 128) {
        int ci = t / 144, r = t - ci * 144;
        int tap = r >> 4, c = r & 15;
        swt[t] = __ldg(w + (half * 16 + c) * 144 + ci * 9 + tap);
    }
    if (tid < 16) sb[tid] = __ldg(bias + half * 16 + tid);
    __syncthreads();

    int ry[4], cx[4];
    bool rok[4], cok[4];
    #pragma unroll
    for (int r = 0; r < 4; ++r) {
        ry[r] = 2 * i - 1 + r; rok[r] = (unsigned)ry[r] < 128u;
        cx[r] = 2 * j - 1 + r; cok[r] = (unsigned)cx[r] < 128u;
    }

    u64 acc[4][8];
    #pragma unroll
    for (int p = 0; p < 4; ++p)
        #pragma unroll
        for (int q = 0; q < 8; ++q) acc[p][q] = 0ull;

    #pragma unroll 1
    for (int ci = 0; ci < 16; ++ci) {
        const float* src = g_h1 + ((b * 16 + ci) << 14);
        u64 patch[4][4];
        #pragma unroll
        for (int r = 0; r < 4; ++r)
            #pragma unroll
            for (int cc = 0; cc < 4; ++cc) {
                float v = (rok[r] && cok[cc]) ? src[(ry[r] << 7) + cx[cc]] : 0.f;
                patch[r][cc] = packff(v, v);
            }

        #pragma unroll
        for (int dy = 0; dy < 3; ++dy)
            #pragma unroll
            for (int dx = 0; dx < 3; ++dx) {
                const ulonglong2* W2 =
                    (const ulonglong2*)(swt + (ci * 9 + dy * 3 + dx) * 16);
                ulonglong2 wA = W2[0], wB = W2[1], wC = W2[2], wD = W2[3];
                #pragma unroll
                for (int p = 0; p < 4; ++p) {
                    u64 vp = patch[(p >> 1) + dy][(p & 1) + dx];
                    acc[p][0] = ffma2(wA.x, vp, acc[p][0]);
                    acc[p][1] = ffma2(wA.y, vp, acc[p][1]);
                    acc[p][2] = ffma2(wB.x, vp, acc[p][2]);
                    acc[p][3] = ffma2(wB.y, vp, acc[p][3]);
                    acc[p][4] = ffma2(wC.x, vp, acc[p][4]);
                    acc[p][5] = ffma2(wC.y, vp, acc[p][5]);
                    acc[p][6] = ffma2(wD.x, vp, acc[p][6]);
                    acc[p][7] = ffma2(wD.y, vp, acc[p][7]);
                }
            }
    }

    float* dst = g_h2 + ((b * 32 + half * 16) << 12) + (i << 6) + j;
    #pragma unroll
    for (int q = 0; q < 8; ++q) {
        float2 m0 = unpackff(acc[0][q]);
        float2 m1 = unpackff(acc[1][q]);
        float2 m2 = unpackff(acc[2][q]);
        float2 m3 = unpackff(acc[3][q]);
        float lo = fmaxf(fmaxf(m0.x, m1.x), fmaxf(m2.x, m3.x)) + sb[2 * q];
        float hi = fmaxf(fmaxf(m0.y, m1.y), fmaxf(m2.y, m3.y)) + sb[2 * q + 1];
        dst[(2 * q) << 12]     = lo;
        dst[(2 * q + 1) << 12] = hi;
    }
}

// ---------------------------------------------------------------------------
// K3: VQ via mma.sync tf32. Per CTA: 128 tokens x 512 codes, K=32.
// 4-way split (hh+hl+lh+ll) -> fp32-accurate dot products; argmax of
// score = f.c - 0.5||c||^2 with lowest-index tie-break == jnp.argmin.
// Warp w owns the m16 tile of tokens [w*16, w*16+16); A frags live in regs.
// Codebook hi/lo staged to padded smem once per CTA.
// ---------------------------------------------------------------------------
#define K3_BHI   0                    // 512*33 floats
#define K3_BLO   (512 * 33)
#define K3_CN    (2 * 512 * 33)      // 512 floats
#define K3_WS    (2 * 512 * 33 + 512) // 8 floats
#define K3_SMEM  ((2 * 512 * 33 + 512 + 8) * 4)

__global__ void __launch_bounds__(256) k3_vq(const float* __restrict__ cb,
                                             float* __restrict__ out) {
    extern __shared__ float sm3[];
    float* sBhi = sm3 + K3_BHI;
    float* sBlo = sm3 + K3_BLO;
    float* sCn  = sm3 + K3_CN;
    float* sWs  = sm3 + K3_WS;

    int tid = threadIdx.x;
    int wid = tid >> 5, lane = tid & 31;
    int grp = lane >> 2, thr = lane & 3;
    int base = blockIdx.x * 128;           // global token base
    int b = base >> 12, ij0 = base & 4095; // image / in-image offset

    // ---- stage codebook hi/lo into smem (stride 33 to dodge conflicts) ----
    for (int t = tid; t < 16384; t += 256) {
        int k = t >> 5, c = t & 31;
        float v = __ldg(cb + t);
        float hi = __uint_as_float(__float_as_uint(v) & 0xFFFFE000u);
        sBhi[k * 33 + c] = hi;
        sBlo[k * 33 + c] = v - hi;
    }
    for (int t = tid; t < 512; t += 256) sCn[t] = g_cnh[t];

    // ---- A fragments (16 tokens x K=32) straight from global into regs ----
    const float* fbase = g_h2 + (b << 17) + ij0 + wid * 16 + grp;
    uint32_t ahi[16], alo[16];
    #pragma unroll
    for (int ks = 0; ks < 4; ++ks) {
        int c0 = ks * 8 + thr, c1 = c0 + 4;
        float v00 = fbase[c0 << 12];         // row grp
        float v10 = fbase[(c0 << 12) + 8];   // row grp+8
        float v01 = fbase[c1 << 12];
        float v11 = fbase[(c1 << 12) + 8];
        uint32_t h;
        h = __float_as_uint(v00) & 0xFFFFE000u;
        ahi[ks * 4 + 0] = h; alo[ks * 4 + 0] = __float_as_uint(v00 - __uint_as_float(h));
        h = __float_as_uint(v10) & 0xFFFFE000u;
        ahi[ks * 4 + 1] = h; alo[ks * 4 + 1] = __float_as_uint(v10 - __uint_as_float(h));
        h = __float_as_uint(v01) & 0xFFFFE000u;
        ahi[ks * 4 + 2] = h; alo[ks * 4 + 2] = __float_as_uint(v01 - __uint_as_float(h));
        h = __float_as_uint(v11) & 0xFFFFE000u;
        ahi[ks * 4 + 3] = h; alo[ks * 4 + 3] = __float_as_uint(v11 - __uint_as_float(h));
    }
    __syncthreads();

    // ---- main loop over 64 n-tiles of 8 codes ----
    float bv0 = -1e30f, bv1 = -1e30f;
    int bk0 = 0, bk1 = 0;

    #pragma unroll 2
    for (int nt = 0; nt < 64; ++nt) {
        const float* ph = sBhi + (nt * 8 + grp) * 33;
        const float* pl = sBlo + (nt * 8 + grp) * 33;
        uint32_t bh[8], bl[8];
        #pragma unroll
        for (int ks = 0; ks < 4; ++ks) {
            bh[ks * 2]     = __float_as_uint(ph[ks * 8 + thr]);
            bh[ks * 2 + 1] = __float_as_uint(ph[ks * 8 + thr + 4]);
            bl[ks * 2]     = __float_as_uint(pl[ks * 8 + thr]);
            bl[ks * 2 + 1] = __float_as_uint(pl[ks * 8 + thr + 4]);
        }
        float c0 = 0.f, c1 = 0.f, c2 = 0.f, c3 = 0.f;
        #pragma unroll
        for (int ks = 0; ks < 4; ++ks)
            mma8(c0, c1, c2, c3, ahi[ks*4], ahi[ks*4+1], ahi[ks*4+2], ahi[ks*4+3],
                 bh[ks*2], bh[ks*2+1]);
        #pragma unroll
        for (int ks = 0; ks < 4; ++ks)
            mma8(c0, c1, c2, c3, ahi[ks*4], ahi[ks*4+1], ahi[ks*4+2], ahi[ks*4+3],
                 bl[ks*2], bl[ks*2+1]);
        #pragma unroll
        for (int ks = 0; ks < 4; ++ks)
            mma8(c0, c1, c2, c3, alo[ks*4], alo[ks*4+1], alo[ks*4+2], alo[ks*4+3],
                 bh[ks*2], bh[ks*2+1]);
        #pragma unroll
        for (int ks = 0; ks < 4; ++ks)
            mma8(c0, c1, c2, c3, alo[ks*4], alo[ks*4+1], alo[ks*4+2], alo[ks*4+3],
                 bl[ks*2], bl[ks*2+1]);

        int col = nt * 8 + 2 * thr;
        float cn0 = sCn[col], cn1 = sCn[col + 1];
        float v;
        v = c0 - cn0; if (v > bv0) { bv0 = v; bk0 = col; }
        v = c1 - cn1; if (v > bv0) { bv0 = v; bk0 = col + 1; }
        v = c2 - cn0; if (v > bv1) { bv1 = v; bk1 = col; }
        v = c3 - cn1; if (v > bv1) { bv1 = v; bk1 = col + 1; }
    }

    // ---- reduce across the 4 lanes of each row-group (lowest k on ties) ----
    #pragma unroll
    for (int o = 1; o <= 2; o <<= 1) {
        float ov = __shfl_xor_sync(0xffffffffu, bv0, o);
        int   ok = __shfl_xor_sync(0xffffffffu, bk0, o);
        if (ov > bv0 || (ov == bv0 && ok < bk0)) { bv0 = ov; bk0 = ok; }
        ov = __shfl_xor_sync(0xffffffffu, bv1, o);
        ok = __shfl_xor_sync(0xffffffffu, bk1, o);
        if (ov > bv1 || (ov == bv1 && ok < bk1)) { bv1 = ov; bk1 = ok; }
    }

    int tokl = wid * 16 + grp;       // local token for row grp
    if (thr == 0) out[IDX_OFF + base + tokl] = (float)bk0;
    if (thr == 2) out[IDX_OFF + base + tokl + 8] = (float)bk1;

    // ---- gather + commit-loss partials: 4 lanes split 2 tokens x 2 halves --
    int mytok = tokl + ((thr >> 1) << 3);       // thr<2 -> tokl, thr>=2 -> +8
    int myk   = (thr < 2) ? bk0 : bk1;
    int cbase = (thr & 1) << 4;                 // channels [cbase, cbase+16)
    const float* cbr = cb + myk * 32 + cbase;
    const float* h2p = g_h2 + (b << 17) + (cbase << 12) + ij0 + mytok;
    float*       hqp = g_hq + (b << 17) + (cbase << 12) + ij0 + mytok;
    float part = 0.f;
    #pragma unroll
    for (int c = 0; c < 16; ++c) {
        float qv = __ldg(cbr + c);
        float fv = h2p[c << 12];
        float d = qv - fv;
        part = fmaf(d, d, part);
        hqp[c << 12] = qv;
    }

    // deterministic block reduction
    #pragma unroll
    for (int o = 16; o > 0; o >>= 1)
        part += __shfl_down_sync(0xffffffffu, part, o);
    if (lane == 0) sWs[wid] = part;
    __syncthreads();
    if (tid == 0) {
        float s = 0.f;
        #pragma unroll
        for (int q = 0; q < 8; ++q) s += sWs[q];
        g_part[blockIdx.x] = s;
    }
}

// ---------------------------------------------------------------------------
// K4: up2 + conv d1 (parity-folded) + gelu, FFMA2 channel pairs.
// Warp-parity mapping: each warp covers one x-parity -> p warp-uniform.
// ---------------------------------------------------------------------------
__global__ void __launch_bounds__(256) k4_dec1(const float* __restrict__ bias) {
    __shared__ __align__(16) float sW[8192];  // [p][ci][uv][16c]
    __shared__ float sb[16];
    int tid = threadIdx.x;
    for (int t = tid; t < 8192; t += 256) sW[t] = g_Wf1t[t];
    if (tid < 16) sb[tid] = __ldg(bias + tid);
    __syncthreads();

    int lin = blockIdx.x * 256 + tid;
    int lane = lin & 31;
    int wq = (lin >> 5) & 3;
    int y = (lin >> 7) & 127;
    int b = lin >> 14;
    int px = wq & 1;
    int xi = lane + ((wq >> 1) << 5);
    int x = 2 * xi + px;

    int p = (y & 1) * 2 + px;
    int ra = (y - 1) >> 1, rb = (y + 1) >> 1;
    int cb2 = (x + 1) >> 1;
    bool raok = y > 0, rbok = rb < 64, caok = x > 0, cbok = cb2 < 64;
    int ca = (x - 1) >> 1, cc = cb2;

    u64 acc[8];
    #pragma unroll
    for (int q = 0; q < 8; ++q) acc[q] = 0ull;

    #pragma unroll 1
    for (int ci = 0; ci < 32; ++ci) {
        const float* base = g_hq + (b << 17) + (ci << 12);
        float v[4];
        v[0] = (raok && caok) ? base[(ra << 6) + ca] : 0.f;
        v[1] = (raok && cbok) ? base[(ra << 6) + cc] : 0.f;
        v[2] = (rbok && caok) ? base[(rb << 6) + ca] : 0.f;
        v[3] = (rbok && cbok) ? base[(rb << 6) + cc] : 0.f;

        #pragma unroll
        for (int uv = 0; uv < 4; ++uv) {
            u64 vp = packff(v[uv], v[uv]);
            const ulonglong2* W = (const ulonglong2*)(sW + ((p * 32 + ci) * 4 + uv) * 16);
            ulonglong2 wA = W[0], wB = W[1], wC = W[2], wD = W[3];
            acc[0] = ffma2(wA.x, vp, acc[0]);
            acc[1] = ffma2(wA.y, vp, acc[1]);
            acc[2] = ffma2(wB.x, vp, acc[2]);
            acc[3] = ffma2(wB.y, vp, acc[3]);
            acc[4] = ffma2(wC.x, vp, acc[4]);
            acc[5] = ffma2(wC.y, vp, acc[5]);
            acc[6] = ffma2(wD.x, vp, acc[6]);
            acc[7] = ffma2(wD.y, vp, acc[7]);
        }
    }

    float* dst = g_gg + ((b * 16) << 14) + (y << 7) + x;
    #pragma unroll
    for (int q = 0; q < 8; ++q) {
        float2 m = unpackff(acc[q]);
        float lo = m.x + sb[2 * q];
        float hi = m.y + sb[2 * q + 1];
        dst[(2 * q) << 14]     = lo * normcdff(lo);
        dst[(2 * q + 1) << 14] = hi * normcdff(hi);
    }
}

// ---------------------------------------------------------------------------
// K5: up2 + conv d2 (parity-folded) + clip, warp-parity mapping (uniform p).
// ---------------------------------------------------------------------------
__global__ void __launch_bounds__(256) k5_dec2(const float* __restrict__ bias,
                                               float* __restrict__ out) {
    __shared__ __align__(16) float sW[256];
    int tid = threadIdx.x;
    sW[tid] = g_Wf2[tid];
    __syncthreads();

    int lin = blockIdx.x * 256 + tid;
    int lane = lin & 31;
    int wq = (lin >> 5) & 7;
    int y = (lin >> 8) & 255;
    int b = lin >> 16;
    int px = wq & 1;
    int xi = lane + ((wq >> 1) << 5);
    int x = 2 * xi + px;

    int p = (y & 1) * 2 + px;
    int ra = (y - 1) >> 1, rb = (y + 1) >> 1;
    int ca = (x - 1) >> 1, cc = (x + 1) >> 1;
    bool raok = y > 0, rbok = rb < 128, caok = x > 0, cbok = cc < 128;

    float s = 0.f;
    #pragma unroll
    for (int ci = 0; ci < 16; ++ci) {
        const float* base = g_gg + ((b * 16 + ci) << 14);
        float v00 = (raok && caok) ? base[(ra << 7) + ca] : 0.f;
        float v01 = (raok && cbok) ? base[(ra << 7) + cc] : 0.f;
        float v10 = (rbok && caok) ? base[(rb << 7) + ca] : 0.f;
        float v11 = (rbok && cbok) ? base[(rb << 7) + cc] : 0.f;
        float4 wqv = *((const float4*)(sW + (p * 16 + ci) * 4));
        s = fmaf(wqv.x, v00, s);
        s = fmaf(wqv.y, v01, s);
        s = fmaf(wqv.z, v10, s);
        s = fmaf(wqv.w, v11, s);
    }
    s += __ldg(bias);
    out[(b << 16) + (y << 8) + x] = fminf(fmaxf(s, -1.f), 1.f);
}

// ---------------------------------------------------------------------------
// K6: final commit-loss reduction (deterministic tree over 1024 partials).
// ---------------------------------------------------------------------------
__global__ void __launch_bounds__(256) k6_loss(float* __restrict__ out) {
    __shared__ float sm[256];
    int tid = threadIdx.x;
    sm[tid] = (g_part[tid] + g_part[tid + 256]) +
              (g_part[tid + 512] + g_part[tid + 768]);
    __syncthreads();
    #pragma unroll
    for (int o = 128; o > 0; o >>= 1) {
        if (tid < o) sm[tid] += sm[tid + o];
        __syncthreads();
    }
    if (tid == 0) out[LOSS_OFF] = sm[0] * (1.0f / 4194304.0f);
}

// ---------------------------------------------------------------------------
extern "C" void kernel_launch(void* const* d_in, const int* in_sizes, int n_in,
                              void* d_out, int out_size) {
    const float* x   = (const float*)d_in[0];
    const float* e1w = (const float*)d_in[1];
    const float* e1b = (const float*)d_in[2];
    const float* e2w = (const float*)d_in[3];
    const float* e2b = (const float*)d_in[4];
    const float* cb  = (const float*)d_in[5];
    const float* d1w = (const float*)d_in[6];
    const float* d1b = (const float*)d_in[7];
    const float* d2w = (const float*)d_in[8];
    const float* d2b = (const float*)d_in[9];
    float* out = (float*)d_out;

    static int s_attr_done = 0;
    if (!s_attr_done) {
        cudaFuncSetAttribute(k3_vq, cudaFuncAttributeMaxDynamicSharedMemorySize,
                             K3_SMEM);
        s_attr_done = 1;
    }

    k0_setup<<<35, 256>>>(cb, d1w, d2w);
    k1_conv1<<<2048, 256>>>(x, e1w, e1b);
    k2_conv2<<<2048, 128>>>(e2w, e2b);
    k3_vq<<<1024, 256, K3_SMEM>>>(cb, out);
    k4_dec1<<<2048, 256>>>(d1b);
    k5_dec2<<<8192, 256>>>(d2b, out);
    k6_loss<<<1, 256>>>(out);
}

// round 6
// speedup vs baseline: 1.2048x; 1.2048x over previous
#include <cuda_runtime.h>
#include <math.h>
#include <stdint.h>

// ---------------------------------------------------------------------------
// SimpleVQAutoEncoder on GB300 — fp32 SIMT + FFMA2 convs + mma.sync tf32 VQ
//
//   K0: setup (codebook norms + fragment packing, folded decoder weights)
//   K1: conv1(1->16,3x3,SAME) + maxpool2 + gelu        -> g_h1 [32,16,128,128]
//   K2: conv2(16->32,3x3,SAME) + maxpool2 (FFMA2)      -> g_h2 [32,32,64,64]
//   K3: VQ mma.sync tf32 4-way split, 512thr/2CTA-SM   -> g_hq, indices, g_part
//   K4: up2 + conv d1(32->16) folded (FFMA2, uniform-p)-> g_gg [32,16,128,128]
//   K5: up2 + conv d2(16->1)  folded + clip (uniform-p)-> out y
//   K6: reduce commit-loss partials                    -> out[last]
//
// Output layout (float32): [ y (32*256*256) | indices (32*64*64) | loss (1) ]
// ---------------------------------------------------------------------------

#define IDX_OFF   2097152
#define LOSS_OFF  2228224

typedef unsigned long long u64;

__device__ __forceinline__ u64 ffma2(u64 a, u64 b, u64 c) {
    u64 d;
    asm("fma.rn.f32x2 %0, %1, %2, %3;" : "=l"(d) : "l"(a), "l"(b), "l"(c));
    return d;
}
__device__ __forceinline__ u64 packff(float lo, float hi) {
    u64 d;
    asm("mov.b64 %0, {%1, %2};" : "=l"(d) : "f"(lo), "f"(hi));
    return d;
}
__device__ __forceinline__ float2 unpackff(u64 v) {
    float lo, hi;
    asm("mov.b64 {%0, %1}, %2;" : "=f"(lo), "=f"(hi) : "l"(v));
    return make_float2(lo, hi);
}

// m16n8k8 tf32 mma (sm_80+ PTX, valid at base sm_103 target)
__device__ __forceinline__ void mma8(float& c0, float& c1, float& c2, float& c3,
                                     uint32_t a0, uint32_t a1, uint32_t a2,
                                     uint32_t a3, uint32_t b0, uint32_t b1) {
    asm volatile(
        "mma.sync.aligned.m16n8k8.row.col.f32.tf32.tf32.f32 "
        "{%0,%1,%2,%3}, {%4,%5,%6,%7}, {%8,%9}, {%0,%1,%2,%3};"
        : "+f"(c0), "+f"(c1), "+f"(c2), "+f"(c3)
        : "r"(a0), "r"(a1), "r"(a2), "r"(a3), "r"(b0), "r"(b1));
}

// Intermediates (device globals: no allocation allowed)
__device__ float g_h1[32 * 16 * 128 * 128];   // 33.5 MB
__device__ float g_h2[32 * 32 * 64 * 64];     // 16.8 MB
__device__ float g_hq[32 * 32 * 64 * 64];     // 16.8 MB
__device__ float g_gg[32 * 16 * 128 * 128];   // 33.5 MB
__device__ float g_cnh[512];                  // 0.5*||codebook_k||^2
__device__ float g_cbF[64 * 32 * 16];         // packed codebook frags (128 KB)
__device__ float g_Wf1t[4 * 32 * 4 * 16];     // folded d1 [p][ci][uv][c]
__device__ float g_Wf2[4 * 16 * 4];           // folded d2 [p][ci][uv]
__device__ float g_part[512];                 // commit-loss partials

// ---------------------------------------------------------------------------
// K0: setup. Decoder weight folding + codebook half-norms + fragment packing.
// g_cbF plane-interleaved layout: float4 plane q of tile nt, lane l at
//   g_cbF[ ((nt*4+q)*32 + l)*4 .. +3 ],  element j = q*4+e:
//   j<8 -> hi part of codebook[nt*8 + (l>>2)][ (j>>1)*8 + (l&3) + ((j&1)?4:0) ]
//   j>=8 -> lo part (v - hi), same channel with j-8.
// -> in k3 each LDS.128 has lanes at 16B stride (conflict-free).
// ---------------------------------------------------------------------------
__global__ void __launch_bounds__(256) k0_setup(const float* __restrict__ cb,
                                                const float* __restrict__ d1w,
                                                const float* __restrict__ d2w) {
    int t = blockIdx.x * 256 + threadIdx.x;
    if (t < 8192) {
        int c = t & 15, uv = (t >> 4) & 3, ci = (t >> 6) & 31, p = t >> 11;
        int py = p >> 1, px = p & 1, u = uv >> 1, v = uv & 1;
        float s = 0.f;
        #pragma unroll
        for (int dy = 0; dy < 3; ++dy) {
            int ug = (py == 0) ? (dy >= 1) : (dy >= 2);
            if (ug != u) continue;
            #pragma unroll
            for (int dx = 0; dx < 3; ++dx) {
                int vg = (px == 0) ? (dx >= 1) : (dx >= 2);
                if (vg != v) continue;
                s += d1w[((c * 32 + ci) * 3 + dy) * 3 + dx];
            }
        }
        g_Wf1t[t] = s;
    } else if (t < 8704) {
        int k = t - 8192;
        float s = 0.f;
        #pragma unroll
        for (int c = 0; c < 32; ++c) { float v = cb[k * 32 + c]; s = fmaf(v, v, s); }
        g_cnh[k] = 0.5f * s;
    } else if (t < 8960) {
        int e = t - 8704;
        int uv = e & 3, ci = (e >> 2) & 15, p = e >> 6;
        int py = p >> 1, px = p & 1, u = uv >> 1, v = uv & 1;
        float s = 0.f;
        #pragma unroll
        for (int dy = 0; dy < 3; ++dy) {
            int ug = (py == 0) ? (dy >= 1) : (dy >= 2);
            if (ug != u) continue;
            #pragma unroll
            for (int dx = 0; dx < 3; ++dx) {
                int vg = (px == 0) ? (dx >= 1) : (dx >= 2);
                if (vg != v) continue;
                s += d2w[ci * 9 + dy * 3 + dx];
            }
        }
        g_Wf2[(p * 16 + ci) * 4 + uv] = s;
    } else if (t < 41728) {
        int v = t - 8960;                 // 0..32767
        int e = v & 3, lane = (v >> 2) & 31, q = (v >> 7) & 3, nt = v >> 9;
        int grp = lane >> 2, thr = lane & 3;
        int j = q * 4 + e;
        int jj = j & 7;
        int ks = jj >> 1, half = jj & 1;
        int c = ks * 8 + thr + (half ? 4 : 0);
        float val = cb[(nt * 8 + grp) * 32 + c];
        float hi = __uint_as_float(__float_as_uint(val) & 0xFFFFE000u);
        g_cbF[v] = (j < 8) ? hi : (val - hi);
    }
}

// ---------------------------------------------------------------------------
// K1: conv1 + maxpool2 + exact gelu. Thread = (b, i, j) pooled pixel, 16 ch.
// ---------------------------------------------------------------------------
__global__ void __launch_bounds__(256) k1_conv1(const float* __restrict__ x,
                                                const float* __restrict__ w,
                                                const float* __restrict__ bias) {
    __shared__ float sw[144];
    __shared__ float sb[16];
    int tid = threadIdx.x;
    if (tid < 144) sw[tid] = __ldg(w + tid);
    if (tid < 16)  sb[tid] = __ldg(bias + tid);
    __syncthreads();

    int lin = blockIdx.x * 256 + tid;
    int j = lin & 127, i = (lin >> 7) & 127, b = lin >> 14;
    const float* xb = x + (b << 16);

    float xv[4][4];
    #pragma unroll
    for (int r = 0; r < 4; ++r) {
        int ry = 2 * i - 1 + r;
        bool rok = (unsigned)ry < 256u;
        #pragma unroll
        for (int cc = 0; cc < 4; ++cc) {
            int cx = 2 * j - 1 + cc;
            xv[r][cc] = (rok && (unsigned)cx < 256u) ? __ldg(xb + ry * 256 + cx) : 0.f;
        }
    }

    #pragma unroll
    for (int c = 0; c < 16; ++c) {
        float wv[9];
        #pragma unroll
        for (int k = 0; k < 9; ++k) wv[k] = sw[c * 9 + k];
        float m = -1e30f;
        #pragma unroll
        for (int py = 0; py < 2; ++py)
            #pragma unroll
            for (int px = 0; px < 2; ++px) {
                float s = 0.f;
                #pragma unroll
                for (int dy = 0; dy < 3; ++dy)
                    #pragma unroll
                    for (int dx = 0; dx < 3; ++dx)
                        s = fmaf(wv[dy * 3 + dx], xv[py + dy][px + dx], s);
                m = fmaxf(m, s);
            }
        m += sb[c];
        g_h1[((b * 16 + c) << 14) + (i << 7) + j] = m * normcdff(m);
    }
}

// ---------------------------------------------------------------------------
// K2: conv2(16->32) + maxpool2, FFMA2 on channel pairs, prepacked patch.
// ---------------------------------------------------------------------------
__global__ void __launch_bounds__(128) k2_conv2(const float* __restrict__ w,
                                                const float* __restrict__ bias) {
    __shared__ __align__(16) float swt[2304];  // [ci*9+tap][16c]
    __shared__ float sb[16];
    int tid = threadIdx.x;
    int lin = blockIdx.x * 128 + tid;
    int j = lin & 63, i = (lin >> 6) & 63, half = (lin >> 12) & 1, b = lin >> 13;

    for (int t = tid; t < 2304; t += 128) {
        int ci = t / 144, r = t - ci * 144;
        int tap = r >> 4, c = r & 15;
        swt[t] = __ldg(w + (half * 16 + c) * 144 + ci * 9 + tap);
    }
    if (tid < 16) sb[tid] = __ldg(bias + half * 16 + tid);
    __syncthreads();

    int ry[4], cx[4];
    bool rok[4], cok[4];
    #pragma unroll
    for (int r = 0; r < 4; ++r) {
        ry[r] = 2 * i - 1 + r; rok[r] = (unsigned)ry[r] < 128u;
        cx[r] = 2 * j - 1 + r; cok[r] = (unsigned)cx[r] < 128u;
    }

    u64 acc[4][8];
    #pragma unroll
    for (int p = 0; p < 4; ++p)
        #pragma unroll
        for (int q = 0; q < 8; ++q) acc[p][q] = 0ull;

    #pragma unroll 1
    for (int ci = 0; ci < 16; ++ci) {
        const float* src = g_h1 + ((b * 16 + ci) << 14);
        u64 patch[4][4];
        #pragma unroll
        for (int r = 0; r < 4; ++r)
            #pragma unroll
            for (int cc = 0; cc < 4; ++cc) {
                float v = (rok[r] && cok[cc]) ? src[(ry[r] << 7) + cx[cc]] : 0.f;
                patch[r][cc] = packff(v, v);
            }

        #pragma unroll
        for (int dy = 0; dy < 3; ++dy)
            #pragma unroll
            for (int dx = 0; dx < 3; ++dx) {
                const ulonglong2* W2 =
                    (const ulonglong2*)(swt + (ci * 9 + dy * 3 + dx) * 16);
                ulonglong2 wA = W2[0], wB = W2[1], wC = W2[2], wD = W2[3];
                #pragma unroll
                for (int p = 0; p < 4; ++p) {
                    u64 vp = patch[(p >> 1) + dy][(p & 1) + dx];
                    acc[p][0] = ffma2(wA.x, vp, acc[p][0]);
                    acc[p][1] = ffma2(wA.y, vp, acc[p][1]);
                    acc[p][2] = ffma2(wB.x, vp, acc[p][2]);
                    acc[p][3] = ffma2(wB.y, vp, acc[p][3]);
                    acc[p][4] = ffma2(wC.x, vp, acc[p][4]);
                    acc[p][5] = ffma2(wC.y, vp, acc[p][5]);
                    acc[p][6] = ffma2(wD.x, vp, acc[p][6]);
                    acc[p][7] = ffma2(wD.y, vp, acc[p][7]);
                }
            }
    }

    float* dst = g_h2 + ((b * 32 + half * 16) << 12) + (i << 6) + j;
    #pragma unroll
    for (int q = 0; q < 8; ++q) {
        float2 m0 = unpackff(acc[0][q]);
        float2 m1 = unpackff(acc[1][q]);
        float2 m2 = unpackff(acc[2][q]);
        float2 m3 = unpackff(acc[3][q]);
        float lo = fmaxf(fmaxf(m0.x, m1.x), fmaxf(m2.x, m3.x)) + sb[2 * q];
        float hi = fmaxf(fmaxf(m0.y, m1.y), fmaxf(m2.y, m3.y)) + sb[2 * q + 1];
        dst[(2 * q) << 12]     = lo;
        dst[(2 * q + 1) << 12] = hi;
    }
}

// ---------------------------------------------------------------------------
// K3: VQ via mma.sync tf32 4-way split (hh+hl+lh+ll -> fp32-exact scores).
// 512 threads/CTA (16 warps x m16 tokens = 256 tokens), 2 CTAs/SM.
// Codebook processed in 2 chunks of 256 codes; fragments staged to smem in
// plane-interleaved order -> conflict-free LDS.128.
// argmax of f.c - 0.5||c||^2, lowest-index tie-break == jnp.argmin.
// ---------------------------------------------------------------------------
#define K3_CN   16384
#define K3_WS   (16384 + 512)
#define K3_SMEM ((16384 + 512 + 16) * 4)

__global__ void __launch_bounds__(512, 2) k3_vq(const float* __restrict__ cb,
                                                float* __restrict__ out) {
    extern __shared__ float sm3[];
    float* sF  = sm3;               // 16384 floats: one 256-code chunk
    float* sCn = sm3 + K3_CN;       // 512 half-norms
    float* sWs = sm3 + K3_WS;       // 16 warp partials

    int tid = threadIdx.x;
    int wid = tid >> 5, lane = tid & 31;
    int grp = lane >> 2, thr = lane & 3;
    int base = blockIdx.x * 256;           // global token base
    int b = base >> 12, ij0 = base & 4095;

    // ---- A fragments (16 tokens x K=32) from global into regs, hi/lo ----
    const float* fbase = g_h2 + (b << 17) + ij0 + wid * 16 + grp;
    uint32_t ahi[16], alo[16];
    #pragma unroll
    for (int ks = 0; ks < 4; ++ks) {
        int c0 = ks * 8 + thr, c1 = c0 + 4;
        float v00 = fbase[c0 << 12];
        float v10 = fbase[(c0 << 12) + 8];
        float v01 = fbase[c1 << 12];
        float v11 = fbase[(c1 << 12) + 8];
        uint32_t h;
        h = __float_as_uint(v00) & 0xFFFFE000u;
        ahi[ks * 4 + 0] = h; alo[ks * 4 + 0] = __float_as_uint(v00 - __uint_as_float(h));
        h = __float_as_uint(v10) & 0xFFFFE000u;
        ahi[ks * 4 + 1] = h; alo[ks * 4 + 1] = __float_as_uint(v10 - __uint_as_float(h));
        h = __float_as_uint(v01) & 0xFFFFE000u;
        ahi[ks * 4 + 2] = h; alo[ks * 4 + 2] = __float_as_uint(v01 - __uint_as_float(h));
        h = __float_as_uint(v11) & 0xFFFFE000u;
        ahi[ks * 4 + 3] = h; alo[ks * 4 + 3] = __float_as_uint(v11 - __uint_as_float(h));
    }
    if (tid < 512) sCn[tid] = g_cnh[tid];

    float bv0 = -1e30f, bv1 = -1e30f;
    int bk0 = 0, bk1 = 0;

    #pragma unroll 1
    for (int ch = 0; ch < 2; ++ch) {
        __syncthreads();   // previous chunk fully consumed
        {
            const float4* src = (const float4*)(g_cbF + ch * 16384);
            float4* dst = (float4*)sF;
            #pragma unroll
            for (int t = 0; t < 8; ++t)
                dst[tid + t * 512] = __ldg(src + tid + t * 512);
        }
        __syncthreads();

        #pragma unroll 2
        for (int nt = 0; nt < 32; ++nt) {
            const float4* fp = (const float4*)sF + (nt * 4) * 32 + lane;
            float c0 = 0.f, c1 = 0.f, c2 = 0.f, c3 = 0.f;
            // hi planes (b = hi): hh + lh passes
            {
                float4 h0 = fp[0], h1 = fp[32];
                uint32_t b0, b1;
                b0 = __float_as_uint(h0.x); b1 = __float_as_uint(h0.y);
                mma8(c0, c1, c2, c3, ahi[0], ahi[1], ahi[2], ahi[3], b0, b1);
                mma8(c0, c1, c2, c3, alo[0], alo[1], alo[2], alo[3], b0, b1);
                b0 = __float_as_uint(h0.z); b1 = __float_as_uint(h0.w);
                mma8(c0, c1, c2, c3, ahi[4], ahi[5], ahi[6], ahi[7], b0, b1);
                mma8(c0, c1, c2, c3, alo[4], alo[5], alo[6], alo[7], b0, b1);
                b0 = __float_as_uint(h1.x); b1 = __float_as_uint(h1.y);
                mma8(c0, c1, c2, c3, ahi[8], ahi[9], ahi[10], ahi[11], b0, b1);
                mma8(c0, c1, c2, c3, alo[8], alo[9], alo[10], alo[11], b0, b1);
                b0 = __float_as_uint(h1.z); b1 = __float_as_uint(h1.w);
                mma8(c0, c1, c2, c3, ahi[12], ahi[13], ahi[14], ahi[15], b0, b1);
                mma8(c0, c1, c2, c3, alo[12], alo[13], alo[14], alo[15], b0, b1);
            }
            // lo planes (b = lo): hl + ll passes
            {
                float4 l0 = fp[64], l1 = fp[96];
                uint32_t b0, b1;
                b0 = __float_as_uint(l0.x); b1 = __float_as_uint(l0.y);
                mma8(c0, c1, c2, c3, ahi[0], ahi[1], ahi[2], ahi[3], b0, b1);
                mma8(c0, c1, c2, c3, alo[0], alo[1], alo[2], alo[3], b0, b1);
                b0 = __float_as_uint(l0.z); b1 = __float_as_uint(l0.w);
                mma8(c0, c1, c2, c3, ahi[4], ahi[5], ahi[6], ahi[7], b0, b1);
                mma8(c0, c1, c2, c3, alo[4], alo[5], alo[6], alo[7], b0, b1);
                b0 = __float_as_uint(l1.x); b1 = __float_as_uint(l1.y);
                mma8(c0, c1, c2, c3, ahi[8], ahi[9], ahi[10], ahi[11], b0, b1);
                mma8(c0, c1, c2, c3, alo[8], alo[9], alo[10], alo[11], b0, b1);
                b0 = __float_as_uint(l1.z); b1 = __float_as_uint(l1.w);
                mma8(c0, c1, c2, c3, ahi[12], ahi[13], ahi[14], ahi[15], b0, b1);
                mma8(c0, c1, c2, c3, alo[12], alo[13], alo[14], alo[15], b0, b1);
            }

            int col = ch * 256 + nt * 8 + 2 * thr;
            float cn0 = sCn[col], cn1 = sCn[col + 1];
            float v;
            v = c0 - cn0; if (v > bv0) { bv0 = v; bk0 = col; }
            v = c1 - cn1; if (v > bv0) { bv0 = v; bk0 = col + 1; }
            v = c2 - cn0; if (v > bv1) { bv1 = v; bk1 = col; }
            v = c3 - cn1; if (v > bv1) { bv1 = v; bk1 = col + 1; }
        }
    }

    // ---- reduce across the 4 lanes of each row-group (lowest k on ties) ----
    #pragma unroll
    for (int o = 1; o <= 2; o <<= 1) {
        float ov = __shfl_xor_sync(0xffffffffu, bv0, o);
        int   ok = __shfl_xor_sync(0xffffffffu, bk0, o);
        if (ov > bv0 || (ov == bv0 && ok < bk0)) { bv0 = ov; bk0 = ok; }
        ov = __shfl_xor_sync(0xffffffffu, bv1, o);
        ok = __shfl_xor_sync(0xffffffffu, bk1, o);
        if (ov > bv1 || (ov == bv1 && ok < bk1)) { bv1 = ov; bk1 = ok; }
    }

    int tokl = wid * 16 + grp;
    if (thr == 0) out[IDX_OFF + base + tokl] = (float)bk0;
    if (thr == 2) out[IDX_OFF + base + tokl + 8] = (float)bk1;

    // ---- gather + commit-loss partials: 4 lanes = 2 tokens x 2 halves ----
    int mytok = tokl + ((thr >> 1) << 3);
    int myk   = (thr < 2) ? bk0 : bk1;
    int cbase = (thr & 1) << 4;
    const float* cbr = cb + myk * 32 + cbase;
    const float* h2p = g_h2 + (b << 17) + (cbase << 12) + ij0 + mytok;
    float*       hqp = g_hq + (b << 17) + (cbase << 12) + ij0 + mytok;
    float part = 0.f;
    #pragma unroll
    for (int c = 0; c < 16; ++c) {
        float qv = __ldg(cbr + c);
        float fv = h2p[c << 12];
        float d = qv - fv;
        part = fmaf(d, d, part);
        hqp[c << 12] = qv;
    }

    // deterministic block reduction (16 warps)
    #pragma unroll
    for (int o = 16; o > 0; o >>= 1)
        part += __shfl_down_sync(0xffffffffu, part, o);
    if (lane == 0) sWs[wid] = part;
    __syncthreads();
    if (tid == 0) {
        float s = 0.f;
        #pragma unroll
        for (int q = 0; q < 16; ++q) s += sWs[q];
        g_part[blockIdx.x] = s;
    }
}

// ---------------------------------------------------------------------------
// K4: up2 + conv d1 (parity-folded) + gelu, FFMA2 channel pairs.
// Warp-parity mapping: each warp covers one x-parity -> p warp-uniform.
// ---------------------------------------------------------------------------
__global__ void __launch_bounds__(256) k4_dec1(const float* __restrict__ bias) {
    __shared__ __align__(16) float sW[8192];  // [p][ci][uv][16c]
    __shared__ float sb[16];
    int tid = threadIdx.x;
    for (int t = tid; t < 8192; t += 256) sW[t] = g_Wf1t[t];
    if (tid < 16) sb[tid] = __ldg(bias + tid);
    __syncthreads();

    int lin = blockIdx.x * 256 + tid;
    int lane = lin & 31;
    int wq = (lin >> 5) & 3;
    int y = (lin >> 7) & 127;
    int b = lin >> 14;
    int px = wq & 1;
    int xi = lane + ((wq >> 1) << 5);
    int x = 2 * xi + px;

    int p = (y & 1) * 2 + px;
    int ra = (y - 1) >> 1, rb = (y + 1) >> 1;
    int cb2 = (x + 1) >> 1;
    bool raok = y > 0, rbok = rb < 64, caok = x > 0, cbok = cb2 < 64;
    int ca = (x - 1) >> 1, cc = cb2;

    u64 acc[8];
    #pragma unroll
    for (int q = 0; q < 8; ++q) acc[q] = 0ull;

    #pragma unroll 1
    for (int ci = 0; ci < 32; ++ci) {
        const float* base = g_hq + (b << 17) + (ci << 12);
        float v[4];
        v[0] = (raok && caok) ? base[(ra << 6) + ca] : 0.f;
        v[1] = (raok && cbok) ? base[(ra << 6) + cc] : 0.f;
        v[2] = (rbok && caok) ? base[(rb << 6) + ca] : 0.f;
        v[3] = (rbok && cbok) ? base[(rb << 6) + cc] : 0.f;

        #pragma unroll
        for (int uv = 0; uv < 4; ++uv) {
            u64 vp = packff(v[uv], v[uv]);
            const ulonglong2* W = (const ulonglong2*)(sW + ((p * 32 + ci) * 4 + uv) * 16);
            ulonglong2 wA = W[0], wB = W[1], wC = W[2], wD = W[3];
            acc[0] = ffma2(wA.x, vp, acc[0]);
            acc[1] = ffma2(wA.y, vp, acc[1]);
            acc[2] = ffma2(wB.x, vp, acc[2]);
            acc[3] = ffma2(wB.y, vp, acc[3]);
            acc[4] = ffma2(wC.x, vp, acc[4]);
            acc[5] = ffma2(wC.y, vp, acc[5]);
            acc[6] = ffma2(wD.x, vp, acc[6]);
            acc[7] = ffma2(wD.y, vp, acc[7]);
        }
    }

    float* dst = g_gg + ((b * 16) << 14) + (y << 7) + x;
    #pragma unroll
    for (int q = 0; q < 8; ++q) {
        float2 m = unpackff(acc[q]);
        float lo = m.x + sb[2 * q];
        float hi = m.y + sb[2 * q + 1];
        dst[(2 * q) << 14]     = lo * normcdff(lo);
        dst[(2 * q + 1) << 14] = hi * normcdff(hi);
    }
}

// ---------------------------------------------------------------------------
// K5: up2 + conv d2 (parity-folded) + clip, warp-parity mapping (uniform p).
// ---------------------------------------------------------------------------
__global__ void __launch_bounds__(256) k5_dec2(const float* __restrict__ bias,
                                               float* __restrict__ out) {
    __shared__ __align__(16) float sW[256];
    int tid = threadIdx.x;
    sW[tid] = g_Wf2[tid];
    __syncthreads();

    int lin = blockIdx.x * 256 + tid;
    int lane = lin & 31;
    int wq = (lin >> 5) & 7;
    int y = (lin >> 8) & 255;
    int b = lin >> 16;
    int px = wq & 1;
    int xi = lane + ((wq >> 1) << 5);
    int x = 2 * xi + px;

    int p = (y & 1) * 2 + px;
    int ra = (y - 1) >> 1, rb = (y + 1) >> 1;
    int ca = (x - 1) >> 1, cc = (x + 1) >> 1;
    bool raok = y > 0, rbok = rb < 128, caok = x > 0, cbok = cc < 128;

    float s = 0.f;
    #pragma unroll
    for (int ci = 0; ci < 16; ++ci) {
        const float* base = g_gg + ((b * 16 + ci) << 14);
        float v00 = (raok && caok) ? base[(ra << 7) + ca] : 0.f;
        float v01 = (raok && cbok) ? base[(ra << 7) + cc] : 0.f;
        float v10 = (rbok && caok) ? base[(rb << 7) + ca] : 0.f;
        float v11 = (rbok && cbok) ? base[(rb << 7) + cc] : 0.f;
        float4 wqv = *((const float4*)(sW + (p * 16 + ci) * 4));
        s = fmaf(wqv.x, v00, s);
        s = fmaf(wqv.y, v01, s);
        s = fmaf(wqv.z, v10, s);
        s = fmaf(wqv.w, v11, s);
    }
    s += __ldg(bias);
    out[(b << 16) + (y << 8) + x] = fminf(fmaxf(s, -1.f), 1.f);
}

// ---------------------------------------------------------------------------
// K6: final commit-loss reduction (deterministic tree over 512 partials).
// ---------------------------------------------------------------------------
__global__ void __launch_bounds__(256) k6_loss(float* __restrict__ out) {
    __shared__ float sm[256];
    int tid = threadIdx.x;
    sm[tid] = g_part[tid] + g_part[tid + 256];
    __syncthreads();
    #pragma unroll
    for (int o = 128; o > 0; o >>= 1) {
        if (tid < o) sm[tid] += sm[tid + o];
        __syncthreads();
    }
    if (tid == 0) out[LOSS_OFF] = sm[0] * (1.0f / 4194304.0f);
}

// ---------------------------------------------------------------------------
extern "C" void kernel_launch(void* const* d_in, const int* in_sizes, int n_in,
                              void* d_out, int out_size) {
    const float* x   = (const float*)d_in[0];
    const float* e1w = (const float*)d_in[1];
    const float* e1b = (const float*)d_in[2];
    const float* e2w = (const float*)d_in[3];
    const float* e2b = (const float*)d_in[4];
    const float* cb  = (const float*)d_in[5];
    const float* d1w = (const float*)d_in[6];
    const float* d1b = (const float*)d_in[7];
    const float* d2w = (const float*)d_in[8];
    const float* d2b = (const float*)d_in[9];
    float* out = (float*)d_out;

    static int s_attr_done = 0;
    if (!s_attr_done) {
        cudaFuncSetAttribute(k3_vq, cudaFuncAttributeMaxDynamicSharedMemorySize,
                             K3_SMEM);
        s_attr_done = 1;
    }

    k0_setup<<<163, 256>>>(cb, d1w, d2w);
    k1_conv1<<<2048, 256>>>(x, e1w, e1b);
    k2_conv2<<<2048, 128>>>(e2w, e2b);
    k3_vq<<<512, 512, K3_SMEM>>>(cb, out);
    k4_dec1<<<2048, 256>>>(d1b);
    k5_dec2<<<8192, 256>>>(d2b, out);
    k6_loss<<<1, 256>>>(out);
}

// round 7
// speedup vs baseline: 1.3693x; 1.1365x over previous
#include <cuda_runtime.h>
#include <math.h>
#include <stdint.h>

// ---------------------------------------------------------------------------
// SimpleVQAutoEncoder on GB300 — FFMA2 encoder + mma.sync tf32 VQ + tf32 decoder
//
//   K0: setup (codebook norms + VQ frags + tf32 decoder weight frags)
//   K1: conv1(1->16,3x3,SAME) + maxpool2 + gelu        -> g_h1 [32,16,128,128]
//   K2: conv2(16->32,3x3,SAME) + maxpool2 (FFMA2)      -> g_h2 [32,32,64,64]
//   K3: VQ mma.sync tf32 4-way split                   -> g_hq, indices, g_part
//   K4: up2 + conv d1(32->16) folded, tf32 mma GEMM    -> g_gg [32,16,128,128]
//   K5: up2 + conv d2(16->1)  folded + clip, 4px/thr   -> out y
//   K6: reduce commit-loss partials                    -> out[last]
//
// Output layout (float32): [ y (32*256*256) | indices (32*64*64) | loss (1) ]
// ---------------------------------------------------------------------------

#define IDX_OFF   2097152
#define LOSS_OFF  2228224

typedef unsigned long long u64;

__device__ __forceinline__ u64 ffma2(u64 a, u64 b, u64 c) {
    u64 d;
    asm("fma.rn.f32x2 %0, %1, %2, %3;" : "=l"(d) : "l"(a), "l"(b), "l"(c));
    return d;
}
__device__ __forceinline__ u64 packff(float lo, float hi) {
    u64 d;
    asm("mov.b64 %0, {%1, %2};" : "=l"(d) : "f"(lo), "f"(hi));
    return d;
}
__device__ __forceinline__ float2 unpackff(u64 v) {
    float lo, hi;
    asm("mov.b64 {%0, %1}, %2;" : "=f"(lo), "=f"(hi) : "l"(v));
    return make_float2(lo, hi);
}

// m16n8k8 tf32 mma (sm_80+ PTX, valid at base sm_103 target)
__device__ __forceinline__ void mma8(float& c0, float& c1, float& c2, float& c3,
                                     uint32_t a0, uint32_t a1, uint32_t a2,
                                     uint32_t a3, uint32_t b0, uint32_t b1) {
    asm volatile(
        "mma.sync.aligned.m16n8k8.row.col.f32.tf32.tf32.f32 "
        "{%0,%1,%2,%3}, {%4,%5,%6,%7}, {%8,%9}, {%0,%1,%2,%3};"
        : "+f"(c0), "+f"(c1), "+f"(c2), "+f"(c3)
        : "r"(a0), "r"(a1), "r"(a2), "r"(a3), "r"(b0), "r"(b1));
}

// Intermediates (device globals: no allocation allowed)
__device__ float g_h1[32 * 16 * 128 * 128];   // 33.5 MB
__device__ float g_h2[32 * 32 * 64 * 64];     // 16.8 MB
__device__ float g_hq[32 * 32 * 64 * 64];     // 16.8 MB
__device__ float g_gg[32 * 16 * 128 * 128];   // 33.5 MB
__device__ float g_cnh[512];                  // 0.5*||codebook_k||^2
__device__ float g_cbF[64 * 32 * 16];         // packed VQ codebook frags
__device__ float g_W4[4 * 16 * 32 * 4];       // tf32 d1 weight A-fragments
__device__ float g_Wf2[4 * 16 * 4];           // folded d2 [p][ci][uv]
__device__ float g_part[512];                 // commit-loss partials

// ---------------------------------------------------------------------------
// K0: setup.
// - g_W4: decoder-1 folded weights in m16n8k8 A-fragment order, tf32-rounded.
//   Entry ((p*16+kk)*32+lane)*4+j  ->  W[p][c = grp + (j&1)*8]
//   [K = kk*8 + thr + (j>>1)*4] with K -> (uv = K>>5, ci = K&31).
// - g_cbF: VQ codebook hi/lo fragment planes (as in R6).
// - g_cnh half-norms, g_Wf2 folded d2 weights.
// Nearest-up2 folding: output (y,x) reads a 2x2 hq patch; the 3x3 taps
// collapse per output parity (py,px) onto the 4 corners.
// ---------------------------------------------------------------------------
__global__ void __launch_bounds__(256) k0_setup(const float* __restrict__ cb,
                                                const float* __restrict__ d1w,
                                                const float* __restrict__ d2w) {
    int t = blockIdx.x * 256 + threadIdx.x;
    if (t < 8192) {
        int j = t & 3, lane = (t >> 2) & 31, kk = (t >> 7) & 15, p = t >> 11;
        int grp = lane >> 2, thr = lane & 3;
        int c = grp + (j & 1) * 8;
        int K = kk * 8 + thr + (j >> 1) * 4;
        int ci = K & 31, uv = K >> 5;
        int u = uv >> 1, v = uv & 1;
        int py = p >> 1, px = p & 1;
        float s = 0.f;
        #pragma unroll
        for (int dy = 0; dy < 3; ++dy) {
            int ug = (py == 0) ? (dy >= 1) : (dy >= 2);
            if (ug != u) continue;
            #pragma unroll
            for (int dx = 0; dx < 3; ++dx) {
                int vg = (px == 0) ? (dx >= 1) : (dx >= 2);
                if (vg != v) continue;
                s += d1w[((c * 32 + ci) * 3 + dy) * 3 + dx];
            }
        }
        uint32_t tf;
        asm("cvt.rna.tf32.f32 %0, %1;" : "=r"(tf) : "f"(s));
        g_W4[t] = __uint_as_float(tf);
    } else if (t < 8704) {
        int k = t - 8192;
        float s = 0.f;
        #pragma unroll
        for (int c = 0; c < 32; ++c) { float v = cb[k * 32 + c]; s = fmaf(v, v, s); }
        g_cnh[k] = 0.5f * s;
    } else if (t < 8960) {
        int e = t - 8704;
        int uv = e & 3, ci = (e >> 2) & 15, p = e >> 6;
        int py = p >> 1, px = p & 1, u = uv >> 1, v = uv & 1;
        float s = 0.f;
        #pragma unroll
        for (int dy = 0; dy < 3; ++dy) {
            int ug = (py == 0) ? (dy >= 1) : (dy >= 2);
            if (ug != u) continue;
            #pragma unroll
            for (int dx = 0; dx < 3; ++dx) {
                int vg = (px == 0) ? (dx >= 1) : (dx >= 2);
                if (vg != v) continue;
                s += d2w[ci * 9 + dy * 3 + dx];
            }
        }
        g_Wf2[(p * 16 + ci) * 4 + uv] = s;
    } else if (t < 41728) {
        int v = t - 8960;                 // 0..32767
        int e = v & 3, lane = (v >> 2) & 31, q = (v >> 7) & 3, nt = v >> 9;
        int grp = lane >> 2, thr = lane & 3;
        int j = q * 4 + e;
        int jj = j & 7;
        int ks = jj >> 1, half = jj & 1;
        int c = ks * 8 + thr + (half ? 4 : 0);
        float val = cb[(nt * 8 + grp) * 32 + c];
        float hi = __uint_as_float(__float_as_uint(val) & 0xFFFFE000u);
        g_cbF[v] = (j < 8) ? hi : (val - hi);
    }
}

// ---------------------------------------------------------------------------
// K1: conv1 + maxpool2 + exact gelu. Thread = (b, i, j) pooled pixel, 16 ch.
// ---------------------------------------------------------------------------
__global__ void __launch_bounds__(256) k1_conv1(const float* __restrict__ x,
                                                const float* __restrict__ w,
                                                const float* __restrict__ bias) {
    __shared__ float sw[144];
    __shared__ float sb[16];
    int tid = threadIdx.x;
    if (tid < 144) sw[tid] = __ldg(w + tid);
    if (tid < 16)  sb[tid] = __ldg(bias + tid);
    __syncthreads();

    int lin = blockIdx.x * 256 + tid;
    int j = lin & 127, i = (lin >> 7) & 127, b = lin >> 14;
    const float* xb = x + (b << 16);

    float xv[4][4];
    #pragma unroll
    for (int r = 0; r < 4; ++r) {
        int ry = 2 * i - 1 + r;
        bool rok = (unsigned)ry < 256u;
        #pragma unroll
        for (int cc = 0; cc < 4; ++cc) {
            int cx = 2 * j - 1 + cc;
            xv[r][cc] = (rok && (unsigned)cx < 256u) ? __ldg(xb + ry * 256 + cx) : 0.f;
        }
    }

    #pragma unroll
    for (int c = 0; c < 16; ++c) {
        float wv[9];
        #pragma unroll
        for (int k = 0; k < 9; ++k) wv[k] = sw[c * 9 + k];
        float m = -1e30f;
        #pragma unroll
        for (int py = 0; py < 2; ++py)
            #pragma unroll
            for (int px = 0; px < 2; ++px) {
                float s = 0.f;
                #pragma unroll
                for (int dy = 0; dy < 3; ++dy)
                    #pragma unroll
                    for (int dx = 0; dx < 3; ++dx)
                        s = fmaf(wv[dy * 3 + dx], xv[py + dy][px + dx], s);
                m = fmaxf(m, s);
            }
        m += sb[c];
        g_h1[((b * 16 + c) << 14) + (i << 7) + j] = m * normcdff(m);
    }
}

// ---------------------------------------------------------------------------
// K2: conv2(16->32) + maxpool2, FFMA2 on channel pairs, prepacked patch.
// ---------------------------------------------------------------------------
__global__ void __launch_bounds__(128) k2_conv2(const float* __restrict__ w,
                                                const float* __restrict__ bias) {
    __shared__ __align__(16) float swt[2304];  // [ci*9+tap][16c]
    __shared__ float sb[16];
    int tid = threadIdx.x;
    int lin = blockIdx.x * 128 + tid;
    int j = lin & 63, i = (lin >> 6) & 63, half = (lin >> 12) & 1, b = lin >> 13;

    for (int t = tid; t < 2304; t += 128) {
        int ci = t / 144, r = t - ci * 144;
        int tap = r >> 4, c = r & 15;
        swt[t] = __ldg(w + (half * 16 + c) * 144 + ci * 9 + tap);
    }
    if (tid < 16) sb[tid] = __ldg(bias + half * 16 + tid);
    __syncthreads();

    int ry[4], cx[4];
    bool rok[4], cok[4];
    #pragma unroll
    for (int r = 0; r < 4; ++r) {
        ry[r] = 2 * i - 1 + r; rok[r] = (unsigned)ry[r] < 128u;
        cx[r] = 2 * j - 1 + r; cok[r] = (unsigned)cx[r] < 128u;
    }

    u64 acc[4][8];
    #pragma unroll
    for (int p = 0; p < 4; ++p)
        #pragma unroll
        for (int q = 0; q < 8; ++q) acc[p][q] = 0ull;

    #pragma unroll 1
    for (int ci = 0; ci < 16; ++ci) {
        const float* src = g_h1 + ((b * 16 + ci) << 14);
        u64 patch[4][4];
        #pragma unroll
        for (int r = 0; r < 4; ++r)
            #pragma unroll
            for (int cc = 0; cc < 4; ++cc) {
                float v = (rok[r] && cok[cc]) ? src[(ry[r] << 7) + cx[cc]] : 0.f;
                patch[r][cc] = packff(v, v);
            }

        #pragma unroll
        for (int dy = 0; dy < 3; ++dy)
            #pragma unroll
            for (int dx = 0; dx < 3; ++dx) {
                const ulonglong2* W2 =
                    (const ulonglong2*)(swt + (ci * 9 + dy * 3 + dx) * 16);
                ulonglong2 wA = W2[0], wB = W2[1], wC = W2[2], wD = W2[3];
                #pragma unroll
                for (int p = 0; p < 4; ++p) {
                    u64 vp = patch[(p >> 1) + dy][(p & 1) + dx];
                    acc[p][0] = ffma2(wA.x, vp, acc[p][0]);
                    acc[p][1] = ffma2(wA.y, vp, acc[p][1]);
                    acc[p][2] = ffma2(wB.x, vp, acc[p][2]);
                    acc[p][3] = ffma2(wB.y, vp, acc[p][3]);
                    acc[p][4] = ffma2(wC.x, vp, acc[p][4]);
                    acc[p][5] = ffma2(wC.y, vp, acc[p][5]);
                    acc[p][6] = ffma2(wD.x, vp, acc[p][6]);
                    acc[p][7] = ffma2(wD.y, vp, acc[p][7]);
                }
            }
    }

    float* dst = g_h2 + ((b * 32 + half * 16) << 12) + (i << 6) + j;
    #pragma unroll
    for (int q = 0; q < 8; ++q) {
        float2 m0 = unpackff(acc[0][q]);
        float2 m1 = unpackff(acc[1][q]);
        float2 m2 = unpackff(acc[2][q]);
        float2 m3 = unpackff(acc[3][q]);
        float lo = fmaxf(fmaxf(m0.x, m1.x), fmaxf(m2.x, m3.x)) + sb[2 * q];
        float hi = fmaxf(fmaxf(m0.y, m1.y), fmaxf(m2.y, m3.y)) + sb[2 * q + 1];
        dst[(2 * q) << 12]     = lo;
        dst[(2 * q + 1) << 12] = hi;
    }
}

// ---------------------------------------------------------------------------
// K3: VQ via mma.sync tf32 4-way split (hh+hl+lh+ll -> fp32-exact scores).
// 512 threads/CTA (16 warps x m16 tokens = 256 tokens), 2 CTAs/SM.
// Codebook processed in 2 chunks of 256 codes; fragments staged to smem in
// plane-interleaved order -> conflict-free LDS.128.
// argmax of f.c - 0.5||c||^2, lowest-index tie-break == jnp.argmin.
// ---------------------------------------------------------------------------
#define K3_CN   16384
#define K3_WS   (16384 + 512)
#define K3_SMEM ((16384 + 512 + 16) * 4)

__global__ void __launch_bounds__(512, 2) k3_vq(const float* __restrict__ cb,
                                                float* __restrict__ out) {
    extern __shared__ float sm3[];
    float* sF  = sm3;               // 16384 floats: one 256-code chunk
    float* sCn = sm3 + K3_CN;       // 512 half-norms
    float* sWs = sm3 + K3_WS;       // 16 warp partials

    int tid = threadIdx.x;
    int wid = tid >> 5, lane = tid & 31;
    int grp = lane >> 2, thr = lane & 3;
    int base = blockIdx.x * 256;           // global token base
    int b = base >> 12, ij0 = base & 4095;

    // ---- A fragments (16 tokens x K=32) from global into regs, hi/lo ----
    const float* fbase = g_h2 + (b << 17) + ij0 + wid * 16 + grp;
    uint32_t ahi[16], alo[16];
    #pragma unroll
    for (int ks = 0; ks < 4; ++ks) {
        int c0 = ks * 8 + thr, c1 = c0 + 4;
        float v00 = fbase[c0 << 12];
        float v10 = fbase[(c0 << 12) + 8];
        float v01 = fbase[c1 << 12];
        float v11 = fbase[(c1 << 12) + 8];
        uint32_t h;
        h = __float_as_uint(v00) & 0xFFFFE000u;
        ahi[ks * 4 + 0] = h; alo[ks * 4 + 0] = __float_as_uint(v00 - __uint_as_float(h));
        h = __float_as_uint(v10) & 0xFFFFE000u;
        ahi[ks * 4 + 1] = h; alo[ks * 4 + 1] = __float_as_uint(v10 - __uint_as_float(h));
        h = __float_as_uint(v01) & 0xFFFFE000u;
        ahi[ks * 4 + 2] = h; alo[ks * 4 + 2] = __float_as_uint(v01 - __uint_as_float(h));
        h = __float_as_uint(v11) & 0xFFFFE000u;
        ahi[ks * 4 + 3] = h; alo[ks * 4 + 3] = __float_as_uint(v11 - __uint_as_float(h));
    }
    if (tid < 512) sCn[tid] = g_cnh[tid];

    float bv0 = -1e30f, bv1 = -1e30f;
    int bk0 = 0, bk1 = 0;

    #pragma unroll 1
    for (int ch = 0; ch < 2; ++ch) {
        __syncthreads();   // previous chunk fully consumed
        {
            const float4* src = (const float4*)(g_cbF + ch * 16384);
            float4* dst = (float4*)sF;
            #pragma unroll
            for (int t = 0; t < 8; ++t)
                dst[tid + t * 512] = __ldg(src + tid + t * 512);
        }
        __syncthreads();

        #pragma unroll 2
        for (int nt = 0; nt < 32; ++nt) {
            const float4* fp = (const float4*)sF + (nt * 4) * 32 + lane;
            float c0 = 0.f, c1 = 0.f, c2 = 0.f, c3 = 0.f;
            // hi planes (b = hi): hh + lh passes
            {
                float4 h0 = fp[0], h1 = fp[32];
                uint32_t b0, b1;
                b0 = __float_as_uint(h0.x); b1 = __float_as_uint(h0.y);
                mma8(c0, c1, c2, c3, ahi[0], ahi[1], ahi[2], ahi[3], b0, b1);
                mma8(c0, c1, c2, c3, alo[0], alo[1], alo[2], alo[3], b0, b1);
                b0 = __float_as_uint(h0.z); b1 = __float_as_uint(h0.w);
                mma8(c0, c1, c2, c3, ahi[4], ahi[5], ahi[6], ahi[7], b0, b1);
                mma8(c0, c1, c2, c3, alo[4], alo[5], alo[6], alo[7], b0, b1);
                b0 = __float_as_uint(h1.x); b1 = __float_as_uint(h1.y);
                mma8(c0, c1, c2, c3, ahi[8], ahi[9], ahi[10], ahi[11], b0, b1);
                mma8(c0, c1, c2, c3, alo[8], alo[9], alo[10], alo[11], b0, b1);
                b0 = __float_as_uint(h1.z); b1 = __float_as_uint(h1.w);
                mma8(c0, c1, c2, c3, ahi[12], ahi[13], ahi[14], ahi[15], b0, b1);
                mma8(c0, c1, c2, c3, alo[12], alo[13], alo[14], alo[15], b0, b1);
            }
            // lo planes (b = lo): hl + ll passes
            {
                float4 l0 = fp[64], l1 = fp[96];
                uint32_t b0, b1;
                b0 = __float_as_uint(l0.x); b1 = __float_as_uint(l0.y);
                mma8(c0, c1, c2, c3, ahi[0], ahi[1], ahi[2], ahi[3], b0, b1);
                mma8(c0, c1, c2, c3, alo[0], alo[1], alo[2], alo[3], b0, b1);
                b0 = __float_as_uint(l0.z); b1 = __float_as_uint(l0.w);
                mma8(c0, c1, c2, c3, ahi[4], ahi[5], ahi[6], ahi[7], b0, b1);
                mma8(c0, c1, c2, c3, alo[4], alo[5], alo[6], alo[7], b0, b1);
                b0 = __float_as_uint(l1.x); b1 = __float_as_uint(l1.y);
                mma8(c0, c1, c2, c3, ahi[8], ahi[9], ahi[10], ahi[11], b0, b1);
                mma8(c0, c1, c2, c3, alo[8], alo[9], alo[10], alo[11], b0, b1);
                b0 = __float_as_uint(l1.z); b1 = __float_as_uint(l1.w);
                mma8(c0, c1, c2, c3, ahi[12], ahi[13], ahi[14], ahi[15], b0, b1);
                mma8(c0, c1, c2, c3, alo[12], alo[13], alo[14], alo[15], b0, b1);
            }

            int col = ch * 256 + nt * 8 + 2 * thr;
            float cn0 = sCn[col], cn1 = sCn[col + 1];
            float v;
            v = c0 - cn0; if (v > bv0) { bv0 = v; bk0 = col; }
            v = c1 - cn1; if (v > bv0) { bv0 = v; bk0 = col + 1; }
            v = c2 - cn0; if (v > bv1) { bv1 = v; bk1 = col; }
            v = c3 - cn1; if (v > bv1) { bv1 = v; bk1 = col + 1; }
        }
    }

    // ---- reduce across the 4 lanes of each row-group (lowest k on ties) ----
    #pragma unroll
    for (int o = 1; o <= 2; o <<= 1) {
        float ov = __shfl_xor_sync(0xffffffffu, bv0, o);
        int   ok = __shfl_xor_sync(0xffffffffu, bk0, o);
        if (ov > bv0 || (ov == bv0 && ok < bk0)) { bv0 = ov; bk0 = ok; }
        ov = __shfl_xor_sync(0xffffffffu, bv1, o);
        ok = __shfl_xor_sync(0xffffffffu, bk1, o);
        if (ov > bv1 || (ov == bv1 && ok < bk1)) { bv1 = ov; bk1 = ok; }
    }

    int tokl = wid * 16 + grp;
    if (thr == 0) out[IDX_OFF + base + tokl] = (float)bk0;
    if (thr == 2) out[IDX_OFF + base + tokl + 8] = (float)bk1;

    // ---- gather + commit-loss partials: 4 lanes = 2 tokens x 2 halves ----
    int mytok = tokl + ((thr >> 1) << 3);
    int myk   = (thr < 2) ? bk0 : bk1;
    int cbase = (thr & 1) << 4;
    const float* cbr = cb + myk * 32 + cbase;
    const float* h2p = g_h2 + (b << 17) + (cbase << 12) + ij0 + mytok;
    float*       hqp = g_hq + (b << 17) + (cbase << 12) + ij0 + mytok;
    float part = 0.f;
    #pragma unroll
    for (int c = 0; c < 16; ++c) {
        float qv = __ldg(cbr + c);
        float fv = h2p[c << 12];
        float d = qv - fv;
        part = fmaf(d, d, part);
        hqp[c << 12] = qv;
    }

    // deterministic block reduction (16 warps)
    #pragma unroll
    for (int o = 16; o > 0; o >>= 1)
        part += __shfl_down_sync(0xffffffffu, part, o);
    if (lane == 0) sWs[wid] = part;
    __syncthreads();
    if (tid == 0) {
        float s = 0.f;
        #pragma unroll
        for (int q = 0; q < 16; ++q) s += sWs[q];
        g_part[blockIdx.x] = s;
    }
}

// ---------------------------------------------------------------------------
// K4: up2 + conv d1 (parity-folded) via single-pass tf32 mma GEMM + gelu.
// Block = (image b, yi-quad): stages hq rows yi0-1..yi0+4 (zero halo) in smem
// (ci stride 456 == 8 mod 32 -> conflict-free B loads), computes
// out[16c][8y][128x] with warp = (parity, x-half), stages result in smem,
// writes coalesced float4.
// ---------------------------------------------------------------------------
#define K4_UN   8192
#define K4_BIAS (8192 + 17408)
#define K4_SMEM ((8192 + 17408 + 16) * 4)

__global__ void __launch_bounds__(256) k4_dec1(const float* __restrict__ bias) {
    extern __shared__ float sm4[];
    float* sWA = sm4;                 // 8192: A fragments (all parities)
    float* sHq = sm4 + K4_UN;         // 17408 union: hq tile / out tile
    float* sB  = sm4 + K4_BIAS;       // 16 bias

    int tid = threadIdx.x;
    int wid = tid >> 5, lane = tid & 31;
    int grp = lane >> 2, thr = lane & 3;
    int b = blockIdx.x >> 4, yq = blockIdx.x & 15;
    int yi0 = yq * 4;

    // stage A fragments
    {
        const float4* src = (const float4*)g_W4;
        float4* dst = (float4*)sWA;
        #pragma unroll
        for (int q = 0; q < 8; ++q) dst[tid + q * 256] = __ldg(src + tid + q * 256);
    }
    if (tid < 16) sB[tid] = __ldg(bias + tid);
    // stage hq tile rows yi0-1..yi0+4, cols -4..67 layout (data at +4)
    if (tid < 192) {
        int ci = tid / 6, r6 = tid - ci * 6;
        float* dst = sHq + ci * 456 + r6 * 72;
        int r = yi0 - 1 + r6;
        float4 z = make_float4(0.f, 0.f, 0.f, 0.f);
        *(float4*)(dst) = z;
        *(float4*)(dst + 68) = z;
        if ((unsigned)r < 64u) {
            const float* srow = g_hq + ((b * 32 + ci) << 12) + (r << 6);
            #pragma unroll
            for (int q = 0; q < 16; ++q)
                *(float4*)(dst + 4 + q * 4) = *(const float4*)(srow + q * 4);
        } else {
            #pragma unroll
            for (int q = 0; q < 16; ++q) *(float4*)(dst + 4 + q * 4) = z;
        }
    }
    __syncthreads();

    int p = wid & 3, xh = wid >> 2;
    int py = p >> 1, px = p & 1;

    float acc[4][4][4];
    #pragma unroll
    for (int r = 0; r < 4; ++r)
        #pragma unroll
        for (int n = 0; n < 4; ++n)
            #pragma unroll
            for (int q = 0; q < 4; ++q) acc[r][n][q] = 0.f;

    #pragma unroll
    for (int kk = 0; kk < 16; ++kk) {
        float4 af = *(const float4*)(sWA + ((p * 16 + kk) * 32 + lane) * 4);
        int uv = kk >> 2;
        int du = (uv >> 1) + py - 1, dv = (uv & 1) + px - 1;
        int ci0 = (kk & 3) * 8;
        const float* B0 = sHq + (ci0 + thr) * 456 + (1 + du) * 72 + 4 + dv
                          + xh * 32 + grp;
        uint32_t a0 = __float_as_uint(af.x), a1 = __float_as_uint(af.y);
        uint32_t a2 = __float_as_uint(af.z), a3 = __float_as_uint(af.w);
        #pragma unroll
        for (int row = 0; row < 4; ++row)
            #pragma unroll
            for (int nt = 0; nt < 4; ++nt) {
                uint32_t b0 = __float_as_uint(B0[row * 72 + nt * 8]);
                uint32_t b1 = __float_as_uint(B0[row * 72 + nt * 8 + 1824]);
                mma8(acc[row][nt][0], acc[row][nt][1],
                     acc[row][nt][2], acc[row][nt][3],
                     a0, a1, a2, a3, b0, b1);
            }
    }

    __syncthreads();   // all warps done reading sHq
    float bias_lo = sB[grp], bias_hi = sB[grp + 8];
    float* sOut = sHq;   // reuse union: [8y][16c][136]
    #pragma unroll
    for (int row = 0; row < 4; ++row) {
        int yl = 2 * row + py;
        #pragma unroll
        for (int nt = 0; nt < 4; ++nt) {
            int x = 64 * xh + 16 * nt + 4 * thr + px;
            float* o = sOut + yl * 2176 + x;
            float v0 = acc[row][nt][0] + bias_lo;
            float v1 = acc[row][nt][1] + bias_lo;
            float v2 = acc[row][nt][2] + bias_hi;
            float v3 = acc[row][nt][3] + bias_hi;
            o[grp * 136]           = v0 * normcdff(v0);
            o[grp * 136 + 2]       = v1 * normcdff(v1);
            o[(grp + 8) * 136]     = v2 * normcdff(v2);
            o[(grp + 8) * 136 + 2] = v3 * normcdff(v3);
        }
    }
    __syncthreads();
    // coalesced writeout: 16c x 8y x 128x
    #pragma unroll
    for (int i = 0; i < 16; ++i) {
        int idx = i * 256 + tid;          // float4 id
        int x4 = idx & 31, ch = (idx >> 5) & 15, yy = idx >> 9;
        float4 val = *(const float4*)(sOut + yy * 2176 + ch * 136 + x4 * 4);
        *(float4*)(g_gg + ((b * 16 + ch) << 14) + (((yq << 3) + yy) << 7) + x4 * 4) = val;
    }
}

// ---------------------------------------------------------------------------
// K5: up2 + conv d2 (parity-folded) + clip. Warp = (b, y, px); 4 px/thread
// with float4 shared row loads. p warp-uniform.
// ---------------------------------------------------------------------------
__global__ void __launch_bounds__(256) k5_dec2(const float* __restrict__ bias,
                                               float* __restrict__ out) {
    __shared__ __align__(16) float sW[256];
    int tid = threadIdx.x;
    sW[tid] = g_Wf2[tid];
    __syncthreads();

    int unit = blockIdx.x * 8 + (tid >> 5);
    int lane = tid & 31;
    int px = unit & 1, y = (unit >> 1) & 255, b = unit >> 9;
    int p = (y & 1) * 2 + px;
    int ra = (y - 1) >> 1, rb = (y + 1) >> 1;
    bool raok = y > 0, rbok = rb < 128;
    int x0 = 4 * lane;   // xi base, 0..124

    float acc0 = 0.f, acc1 = 0.f, acc2 = 0.f, acc3 = 0.f;
    float bz = __ldg(bias);

    #pragma unroll 1
    for (int ci = 0; ci < 16; ++ci) {
        const float* base = g_gg + ((b * 16 + ci) << 14);
        float4 fa = make_float4(0.f, 0.f, 0.f, 0.f);
        float4 fb = fa;
        float ea = 0.f, eb = 0.f;
        if (raok) fa = *(const float4*)(base + (ra << 7) + x0);
        if (rbok) fb = *(const float4*)(base + (rb << 7) + x0);
        if (px == 0) {
            bool ok = x0 > 0;
            if (raok && ok) ea = base[(ra << 7) + x0 - 1];
            if (rbok && ok) eb = base[(rb << 7) + x0 - 1];
        } else {
            bool ok = x0 + 4 < 128;
            if (raok && ok) ea = base[(ra << 7) + x0 + 4];
            if (rbok && ok) eb = base[(rb << 7) + x0 + 4];
        }
        float4 wq = *((const float4*)(sW + (p * 16 + ci) * 4));

        float caA0, caA1, caA2, caA3, ccA0, ccA1, ccA2, ccA3;
        float caB0, caB1, caB2, caB3, ccB0, ccB1, ccB2, ccB3;
        if (px == 0) {
            caA0 = ea;   caA1 = fa.x; caA2 = fa.y; caA3 = fa.z;
            ccA0 = fa.x; ccA1 = fa.y; ccA2 = fa.z; ccA3 = fa.w;
            caB0 = eb;   caB1 = fb.x; caB2 = fb.y; caB3 = fb.z;
            ccB0 = fb.x; ccB1 = fb.y; ccB2 = fb.z; ccB3 = fb.w;
        } else {
            caA0 = fa.x; caA1 = fa.y; caA2 = fa.z; caA3 = fa.w;
            ccA0 = fa.y; ccA1 = fa.z; ccA2 = fa.w; ccA3 = ea;
            caB0 = fb.x; caB1 = fb.y; caB2 = fb.z; caB3 = fb.w;
            ccB0 = fb.y; ccB1 = fb.z; ccB2 = fb.w; ccB3 = eb;
        }
        acc0 = fmaf(wq.x, caA0, fmaf(wq.y, ccA0, fmaf(wq.z, caB0, fmaf(wq.w, ccB0, acc0))));
        acc1 = fmaf(wq.x, caA1, fmaf(wq.y, ccA1, fmaf(wq.z, caB1, fmaf(wq.w, ccB1, acc1))));
        acc2 = fmaf(wq.x, caA2, fmaf(wq.y, ccA2, fmaf(wq.z, caB2, fmaf(wq.w, ccB2, acc2))));
        acc3 = fmaf(wq.x, caA3, fmaf(wq.y, ccA3, fmaf(wq.z, caB3, fmaf(wq.w, ccB3, acc3))));
    }

    float* o = out + (b << 16) + (y << 8) + 8 * lane + px;
    o[0] = fminf(fmaxf(acc0 + bz, -1.f), 1.f);
    o[2] = fminf(fmaxf(acc1 + bz, -1.f), 1.f);
    o[4] = fminf(fmaxf(acc2 + bz, -1.f), 1.f);
    o[6] = fminf(fmaxf(acc3 + bz, -1.f), 1.f);
}

// ---------------------------------------------------------------------------
// K6: final commit-loss reduction (deterministic tree over 512 partials).
// ---------------------------------------------------------------------------
__global__ void __launch_bounds__(256) k6_loss(float* __restrict__ out) {
    __shared__ float sm[256];
    int tid = threadIdx.x;
    sm[tid] = g_part[tid] + g_part[tid + 256];
    __syncthreads();
    #pragma unroll
    for (int o = 128; o > 0; o >>= 1) {
        if (tid < o) sm[tid] += sm[tid + o];
        __syncthreads();
    }
    if (tid == 0) out[LOSS_OFF] = sm[0] * (1.0f / 4194304.0f);
}

// ---------------------------------------------------------------------------
extern "C" void kernel_launch(void* const* d_in, const int* in_sizes, int n_in,
                              void* d_out, int out_size) {
    const float* x   = (const float*)d_in[0];
    const float* e1w = (const float*)d_in[1];
    const float* e1b = (const float*)d_in[2];
    const float* e2w = (const float*)d_in[3];
    const float* e2b = (const float*)d_in[4];
    const float* cb  = (const float*)d_in[5];
    const float* d1w = (const float*)d_in[6];
    const float* d1b = (const float*)d_in[7];
    const float* d2w = (const float*)d_in[8];
    const float* d2b = (const float*)d_in[9];
    float* out = (float*)d_out;

    static int s_attr_done = 0;
    if (!s_attr_done) {
        cudaFuncSetAttribute(k3_vq, cudaFuncAttributeMaxDynamicSharedMemorySize,
                             K3_SMEM);
        cudaFuncSetAttribute(k4_dec1, cudaFuncAttributeMaxDynamicSharedMemorySize,
                             K4_SMEM);
        s_attr_done = 1;
    }

    k0_setup<<<163, 256>>>(cb, d1w, d2w);
    k1_conv1<<<2048, 256>>>(x, e1w, e1b);
    k2_conv2<<<2048, 128>>>(e2w, e2b);
    k3_vq<<<512, 512, K3_SMEM>>>(cb, out);
    k4_dec1<<<512, 256, K4_SMEM>>>(d1b);
    k5_dec2<<<2048, 256>>>(d2b, out);
    k6_loss<<<1, 256>>>(out);
}

// round 8
// speedup vs baseline: 1.3794x; 1.0074x over previous
#include <cuda_runtime.h>
#include <math.h>
#include <stdint.h>

// ---------------------------------------------------------------------------
// SimpleVQAutoEncoder on GB300 — FFMA2 encoder + mma.sync tf32 VQ + tf32 decoder
//
//   K0: setup (codebook norms + VQ frags + tf32 decoder weight frags)
//   K1: conv1(1->16,3x3,SAME) + maxpool2 + gelu        -> g_h1 [32,16,128,128]
//   K2: conv2(16->32,3x3,SAME) + maxpool2 (FFMA2)      -> g_h2 [32,32,64,64]
//   K3: VQ mma.sync tf32 4-way split                   -> g_hq, indices, g_part
//   K4: up2 + conv d1(32->16) folded, tf32 mma GEMM    -> g_gg [32,16,128,128]
//   K5: up2 + conv d2(16->1)  folded + clip, 8px/thr   -> out y
//   K6: reduce commit-loss partials                    -> out[last]
//
// Output layout (float32): [ y (32*256*256) | indices (32*64*64) | loss (1) ]
// ---------------------------------------------------------------------------

#define IDX_OFF   2097152
#define LOSS_OFF  2228224

typedef unsigned long long u64;

__device__ __forceinline__ u64 ffma2(u64 a, u64 b, u64 c) {
    u64 d;
    asm("fma.rn.f32x2 %0, %1, %2, %3;" : "=l"(d) : "l"(a), "l"(b), "l"(c));
    return d;
}
__device__ __forceinline__ u64 packff(float lo, float hi) {
    u64 d;
    asm("mov.b64 %0, {%1, %2};" : "=l"(d) : "f"(lo), "f"(hi));
    return d;
}
__device__ __forceinline__ float2 unpackff(u64 v) {
    float lo, hi;
    asm("mov.b64 {%0, %1}, %2;" : "=f"(lo), "=f"(hi) : "l"(v));
    return make_float2(lo, hi);
}
__device__ __forceinline__ float tf32r(float v) {
    uint32_t t;
    asm("cvt.rna.tf32.f32 %0, %1;" : "=r"(t) : "f"(v));
    return __uint_as_float(t);
}

// m16n8k8 tf32 mma (sm_80+ PTX, valid at base sm_103 target)
__device__ __forceinline__ void mma8(float& c0, float& c1, float& c2, float& c3,
                                     uint32_t a0, uint32_t a1, uint32_t a2,
                                     uint32_t a3, uint32_t b0, uint32_t b1) {
    asm volatile(
        "mma.sync.aligned.m16n8k8.row.col.f32.tf32.tf32.f32 "
        "{%0,%1,%2,%3}, {%4,%5,%6,%7}, {%8,%9}, {%0,%1,%2,%3};"
        : "+f"(c0), "+f"(c1), "+f"(c2), "+f"(c3)
        : "r"(a0), "r"(a1), "r"(a2), "r"(a3), "r"(b0), "r"(b1));
}

// Intermediates (device globals: no allocation allowed)
__device__ float g_h1[32 * 16 * 128 * 128];   // 33.5 MB
__device__ float g_h2[32 * 32 * 64 * 64];     // 16.8 MB
__device__ float g_hq[32 * 32 * 64 * 64];     // 16.8 MB
__device__ float g_gg[32 * 16 * 128 * 128];   // 33.5 MB
__device__ float g_cnh[512];                  // 0.5*||codebook_k||^2
__device__ float g_cbF[64 * 32 * 16];         // packed VQ codebook frags
__device__ float g_W4[4 * 16 * 32 * 4];       // tf32 d1 weight A-fragments
__device__ float g_Wf2[4 * 16 * 4];           // folded d2 [p][ci][uv]
__device__ float g_part[512];                 // commit-loss partials

// ---------------------------------------------------------------------------
// K0: setup.
// - g_W4: decoder-1 folded weights in m16n8k8 A-fragment order, tf32-rounded.
// - g_cbF: VQ codebook hi/lo fragment planes.
// - g_cnh half-norms, g_Wf2 folded d2 weights.
// Nearest-up2 folding: output (y,x) reads a 2x2 hq patch; the 3x3 taps
// collapse per output parity (py,px) onto the 4 corners.
// ---------------------------------------------------------------------------
__global__ void __launch_bounds__(256) k0_setup(const float* __restrict__ cb,
                                                const float* __restrict__ d1w,
                                                const float* __restrict__ d2w) {
    int t = blockIdx.x * 256 + threadIdx.x;
    if (t < 8192) {
        int j = t & 3, lane = (t >> 2) & 31, kk = (t >> 7) & 15, p = t >> 11;
        int grp = lane >> 2, thr = lane & 3;
        int c = grp + (j & 1) * 8;
        int K = kk * 8 + thr + (j >> 1) * 4;
        int ci = K & 31, uv = K >> 5;
        int u = uv >> 1, v = uv & 1;
        int py = p >> 1, px = p & 1;
        float s = 0.f;
        #pragma unroll
        for (int dy = 0; dy < 3; ++dy) {
            int ug = (py == 0) ? (dy >= 1) : (dy >= 2);
            if (ug != u) continue;
            #pragma unroll
            for (int dx = 0; dx < 3; ++dx) {
                int vg = (px == 0) ? (dx >= 1) : (dx >= 2);
                if (vg != v) continue;
                s += d1w[((c * 32 + ci) * 3 + dy) * 3 + dx];
            }
        }
        g_W4[t] = tf32r(s);
    } else if (t < 8704) {
        int k = t - 8192;
        float s = 0.f;
        #pragma unroll
        for (int c = 0; c < 32; ++c) { float v = cb[k * 32 + c]; s = fmaf(v, v, s); }
        g_cnh[k] = 0.5f * s;
    } else if (t < 8960) {
        int e = t - 8704;
        int uv = e & 3, ci = (e >> 2) & 15, p = e >> 6;
        int py = p >> 1, px = p & 1, u = uv >> 1, v = uv & 1;
        float s = 0.f;
        #pragma unroll
        for (int dy = 0; dy < 3; ++dy) {
            int ug = (py == 0) ? (dy >= 1) : (dy >= 2);
            if (ug != u) continue;
            #pragma unroll
            for (int dx = 0; dx < 3; ++dx) {
                int vg = (px == 0) ? (dx >= 1) : (dx >= 2);
                if (vg != v) continue;
                s += d2w[ci * 9 + dy * 3 + dx];
            }
        }
        g_Wf2[(p * 16 + ci) * 4 + uv] = s;
    } else if (t < 41728) {
        int v = t - 8960;                 // 0..32767
        int e = v & 3, lane = (v >> 2) & 31, q = (v >> 7) & 3, nt = v >> 9;
        int grp = lane >> 2, thr = lane & 3;
        int j = q * 4 + e;
        int jj = j & 7;
        int ks = jj >> 1, half = jj & 1;
        int c = ks * 8 + thr + (half ? 4 : 0);
        float val = cb[(nt * 8 + grp) * 32 + c];
        float hi = __uint_as_float(__float_as_uint(val) & 0xFFFFE000u);
        g_cbF[v] = (j < 8) ? hi : (val - hi);
    }
}

// ---------------------------------------------------------------------------
// K1: conv1 + maxpool2 + exact gelu. Thread = (b, i, j) pooled pixel, 16 ch.
// ---------------------------------------------------------------------------
__global__ void __launch_bounds__(256) k1_conv1(const float* __restrict__ x,
                                                const float* __restrict__ w,
                                                const float* __restrict__ bias) {
    __shared__ float sw[144];
    __shared__ float sb[16];
    int tid = threadIdx.x;
    if (tid < 144) sw[tid] = __ldg(w + tid);
    if (tid < 16)  sb[tid] = __ldg(bias + tid);
    __syncthreads();

    int lin = blockIdx.x * 256 + tid;
    int j = lin & 127, i = (lin >> 7) & 127, b = lin >> 14;
    const float* xb = x + (b << 16);

    float xv[4][4];
    #pragma unroll
    for (int r = 0; r < 4; ++r) {
        int ry = 2 * i - 1 + r;
        bool rok = (unsigned)ry < 256u;
        #pragma unroll
        for (int cc = 0; cc < 4; ++cc) {
            int cx = 2 * j - 1 + cc;
            xv[r][cc] = (rok && (unsigned)cx < 256u) ? __ldg(xb + ry * 256 + cx) : 0.f;
        }
    }

    #pragma unroll
    for (int c = 0; c < 16; ++c) {
        float wv[9];
        #pragma unroll
        for (int k = 0; k < 9; ++k) wv[k] = sw[c * 9 + k];
        float m = -1e30f;
        #pragma unroll
        for (int py = 0; py < 2; ++py)
            #pragma unroll
            for (int px = 0; px < 2; ++px) {
                float s = 0.f;
                #pragma unroll
                for (int dy = 0; dy < 3; ++dy)
                    #pragma unroll
                    for (int dx = 0; dx < 3; ++dx)
                        s = fmaf(wv[dy * 3 + dx], xv[py + dy][px + dx], s);
                m = fmaxf(m, s);
            }
        m += sb[c];
        g_h1[((b * 16 + c) << 14) + (i << 7) + j] = m * normcdff(m);
    }
}

// ---------------------------------------------------------------------------
// K2: conv2(16->32) + maxpool2, FFMA2 on channel pairs, prepacked patch.
// ---------------------------------------------------------------------------
__global__ void __launch_bounds__(128) k2_conv2(const float* __restrict__ w,
                                                const float* __restrict__ bias) {
    __shared__ __align__(16) float swt[2304];  // [ci*9+tap][16c]
    __shared__ float sb[16];
    int tid = threadIdx.x;
    int lin = blockIdx.x * 128 + tid;
    int j = lin & 63, i = (lin >> 6) & 63, half = (lin >> 12) & 1, b = lin >> 13;

    for (int t = tid; t < 2304; t += 128) {
        int ci = t / 144, r = t - ci * 144;
        int tap = r >> 4, c = r & 15;
        swt[t] = __ldg(w + (half * 16 + c) * 144 + ci * 9 + tap);
    }
    if (tid < 16) sb[tid] = __ldg(bias + half * 16 + tid);
    __syncthreads();

    int ry[4], cx[4];
    bool rok[4], cok[4];
    #pragma unroll
    for (int r = 0; r < 4; ++r) {
        ry[r] = 2 * i - 1 + r; rok[r] = (unsigned)ry[r] < 128u;
        cx[r] = 2 * j - 1 + r; cok[r] = (unsigned)cx[r] < 128u;
    }

    u64 acc[4][8];
    #pragma unroll
    for (int p = 0; p < 4; ++p)
        #pragma unroll
        for (int q = 0; q < 8; ++q) acc[p][q] = 0ull;

    #pragma unroll 1
    for (int ci = 0; ci < 16; ++ci) {
        const float* src = g_h1 + ((b * 16 + ci) << 14);
        u64 patch[4][4];
        #pragma unroll
        for (int r = 0; r < 4; ++r)
            #pragma unroll
            for (int cc = 0; cc < 4; ++cc) {
                float v = (rok[r] && cok[cc]) ? src[(ry[r] << 7) + cx[cc]] : 0.f;
                patch[r][cc] = packff(v, v);
            }

        #pragma unroll
        for (int dy = 0; dy < 3; ++dy)
            #pragma unroll
            for (int dx = 0; dx < 3; ++dx) {
                const ulonglong2* W2 =
                    (const ulonglong2*)(swt + (ci * 9 + dy * 3 + dx) * 16);
                ulonglong2 wA = W2[0], wB = W2[1], wC = W2[2], wD = W2[3];
                #pragma unroll
                for (int p = 0; p < 4; ++p) {
                    u64 vp = patch[(p >> 1) + dy][(p & 1) + dx];
                    acc[p][0] = ffma2(wA.x, vp, acc[p][0]);
                    acc[p][1] = ffma2(wA.y, vp, acc[p][1]);
                    acc[p][2] = ffma2(wB.x, vp, acc[p][2]);
                    acc[p][3] = ffma2(wB.y, vp, acc[p][3]);
                    acc[p][4] = ffma2(wC.x, vp, acc[p][4]);
                    acc[p][5] = ffma2(wC.y, vp, acc[p][5]);
                    acc[p][6] = ffma2(wD.x, vp, acc[p][6]);
                    acc[p][7] = ffma2(wD.y, vp, acc[p][7]);
                }
            }
    }

    float* dst = g_h2 + ((b * 32 + half * 16) << 12) + (i << 6) + j;
    #pragma unroll
    for (int q = 0; q < 8; ++q) {
        float2 m0 = unpackff(acc[0][q]);
        float2 m1 = unpackff(acc[1][q]);
        float2 m2 = unpackff(acc[2][q]);
        float2 m3 = unpackff(acc[3][q]);
        float lo = fmaxf(fmaxf(m0.x, m1.x), fmaxf(m2.x, m3.x)) + sb[2 * q];
        float hi = fmaxf(fmaxf(m0.y, m1.y), fmaxf(m2.y, m3.y)) + sb[2 * q + 1];
        dst[(2 * q) << 12]     = lo;
        dst[(2 * q + 1) << 12] = hi;
    }
}

// ---------------------------------------------------------------------------
// K3: VQ via mma.sync tf32 4-way split (hh+hl+lh+ll -> fp32-exact scores).
// 512 threads/CTA (16 warps x m16 tokens = 256 tokens), 2 CTAs/SM.
// Codebook processed in 2 chunks of 256 codes; fragments staged to smem in
// plane-interleaved order -> conflict-free LDS.128.
// argmax of f.c - 0.5||c||^2, lowest-index tie-break == jnp.argmin.
// ---------------------------------------------------------------------------
#define K3_CN   16384
#define K3_WS   (16384 + 512)
#define K3_SMEM ((16384 + 512 + 16) * 4)

__global__ void __launch_bounds__(512, 2) k3_vq(const float* __restrict__ cb,
                                                float* __restrict__ out) {
    extern __shared__ float sm3[];
    float* sF  = sm3;               // 16384 floats: one 256-code chunk
    float* sCn = sm3 + K3_CN;       // 512 half-norms
    float* sWs = sm3 + K3_WS;       // 16 warp partials

    int tid = threadIdx.x;
    int wid = tid >> 5, lane = tid & 31;
    int grp = lane >> 2, thr = lane & 3;
    int base = blockIdx.x * 256;           // global token base
    int b = base >> 12, ij0 = base & 4095;

    // ---- A fragments (16 tokens x K=32) from global into regs, hi/lo ----
    const float* fbase = g_h2 + (b << 17) + ij0 + wid * 16 + grp;
    uint32_t ahi[16], alo[16];
    #pragma unroll
    for (int ks = 0; ks < 4; ++ks) {
        int c0 = ks * 8 + thr, c1 = c0 + 4;
        float v00 = fbase[c0 << 12];
        float v10 = fbase[(c0 << 12) + 8];
        float v01 = fbase[c1 << 12];
        float v11 = fbase[(c1 << 12) + 8];
        uint32_t h;
        h = __float_as_uint(v00) & 0xFFFFE000u;
        ahi[ks * 4 + 0] = h; alo[ks * 4 + 0] = __float_as_uint(v00 - __uint_as_float(h));
        h = __float_as_uint(v10) & 0xFFFFE000u;
        ahi[ks * 4 + 1] = h; alo[ks * 4 + 1] = __float_as_uint(v10 - __uint_as_float(h));
        h = __float_as_uint(v01) & 0xFFFFE000u;
        ahi[ks * 4 + 2] = h; alo[ks * 4 + 2] = __float_as_uint(v01 - __uint_as_float(h));
        h = __float_as_uint(v11) & 0xFFFFE000u;
        ahi[ks * 4 + 3] = h; alo[ks * 4 + 3] = __float_as_uint(v11 - __uint_as_float(h));
    }
    if (tid < 512) sCn[tid] = g_cnh[tid];

    float bv0 = -1e30f, bv1 = -1e30f;
    int bk0 = 0, bk1 = 0;

    #pragma unroll 1
    for (int ch = 0; ch < 2; ++ch) {
        __syncthreads();   // previous chunk fully consumed
        {
            const float4* src = (const float4*)(g_cbF + ch * 16384);
            float4* dst = (float4*)sF;
            #pragma unroll
            for (int t = 0; t < 8; ++t)
                dst[tid + t * 512] = __ldg(src + tid + t * 512);
        }
        __syncthreads();

        #pragma unroll 2
        for (int nt = 0; nt < 32; ++nt) {
            const float4* fp = (const float4*)sF + (nt * 4) * 32 + lane;
            float c0 = 0.f, c1 = 0.f, c2 = 0.f, c3 = 0.f;
            // hi planes (b = hi): hh + lh passes
            {
                float4 h0 = fp[0], h1 = fp[32];
                uint32_t b0, b1;
                b0 = __float_as_uint(h0.x); b1 = __float_as_uint(h0.y);
                mma8(c0, c1, c2, c3, ahi[0], ahi[1], ahi[2], ahi[3], b0, b1);
                mma8(c0, c1, c2, c3, alo[0], alo[1], alo[2], alo[3], b0, b1);
                b0 = __float_as_uint(h0.z); b1 = __float_as_uint(h0.w);
                mma8(c0, c1, c2, c3, ahi[4], ahi[5], ahi[6], ahi[7], b0, b1);
                mma8(c0, c1, c2, c3, alo[4], alo[5], alo[6], alo[7], b0, b1);
                b0 = __float_as_uint(h1.x); b1 = __float_as_uint(h1.y);
                mma8(c0, c1, c2, c3, ahi[8], ahi[9], ahi[10], ahi[11], b0, b1);
                mma8(c0, c1, c2, c3, alo[8], alo[9], alo[10], alo[11], b0, b1);
                b0 = __float_as_uint(h1.z); b1 = __float_as_uint(h1.w);
                mma8(c0, c1, c2, c3, ahi[12], ahi[13], ahi[14], ahi[15], b0, b1);
                mma8(c0, c1, c2, c3, alo[12], alo[13], alo[14], alo[15], b0, b1);
            }
            // lo planes (b = lo): hl + ll passes
            {
                float4 l0 = fp[64], l1 = fp[96];
                uint32_t b0, b1;
                b0 = __float_as_uint(l0.x); b1 = __float_as_uint(l0.y);
                mma8(c0, c1, c2, c3, ahi[0], ahi[1], ahi[2], ahi[3], b0, b1);
                mma8(c0, c1, c2, c3, alo[0], alo[1], alo[2], alo[3], b0, b1);
                b0 = __float_as_uint(l0.z); b1 = __float_as_uint(l0.w);
                mma8(c0, c1, c2, c3, ahi[4], ahi[5], ahi[6], ahi[7], b0, b1);
                mma8(c0, c1, c2, c3, alo[4], alo[5], alo[6], alo[7], b0, b1);
                b0 = __float_as_uint(l1.x); b1 = __float_as_uint(l1.y);
                mma8(c0, c1, c2, c3, ahi[8], ahi[9], ahi[10], ahi[11], b0, b1);
                mma8(c0, c1, c2, c3, alo[8], alo[9], alo[10], alo[11], b0, b1);
                b0 = __float_as_uint(l1.z); b1 = __float_as_uint(l1.w);
                mma8(c0, c1, c2, c3, ahi[12], ahi[13], ahi[14], ahi[15], b0, b1);
                mma8(c0, c1, c2, c3, alo[12], alo[13], alo[14], alo[15], b0, b1);
            }

            int col = ch * 256 + nt * 8 + 2 * thr;
            float cn0 = sCn[col], cn1 = sCn[col + 1];
            float v;
            v = c0 - cn0; if (v > bv0) { bv0 = v; bk0 = col; }
            v = c1 - cn1; if (v > bv0) { bv0 = v; bk0 = col + 1; }
            v = c2 - cn0; if (v > bv1) { bv1 = v; bk1 = col; }
            v = c3 - cn1; if (v > bv1) { bv1 = v; bk1 = col + 1; }
        }
    }

    // ---- reduce across the 4 lanes of each row-group (lowest k on ties) ----
    #pragma unroll
    for (int o = 1; o <= 2; o <<= 1) {
        float ov = __shfl_xor_sync(0xffffffffu, bv0, o);
        int   ok = __shfl_xor_sync(0xffffffffu, bk0, o);
        if (ov > bv0 || (ov == bv0 && ok < bk0)) { bv0 = ov; bk0 = ok; }
        ov = __shfl_xor_sync(0xffffffffu, bv1, o);
        ok = __shfl_xor_sync(0xffffffffu, bk1, o);
        if (ov > bv1 || (ov == bv1 && ok < bk1)) { bv1 = ov; bk1 = ok; }
    }

    int tokl = wid * 16 + grp;
    if (thr == 0) out[IDX_OFF + base + tokl] = (float)bk0;
    if (thr == 2) out[IDX_OFF + base + tokl + 8] = (float)bk1;

    // ---- gather + commit-loss partials: 4 lanes = 2 tokens x 2 halves ----
    int mytok = tokl + ((thr >> 1) << 3);
    int myk   = (thr < 2) ? bk0 : bk1;
    int cbase = (thr & 1) << 4;
    const float* cbr = cb + myk * 32 + cbase;
    const float* h2p = g_h2 + (b << 17) + (cbase << 12) + ij0 + mytok;
    float*       hqp = g_hq + (b << 17) + (cbase << 12) + ij0 + mytok;
    float part = 0.f;
    #pragma unroll
    for (int c = 0; c < 16; ++c) {
        float qv = __ldg(cbr + c);
        float fv = h2p[c << 12];
        float d = qv - fv;
        part = fmaf(d, d, part);
        hqp[c << 12] = qv;
    }

    // deterministic block reduction (16 warps)
    #pragma unroll
    for (int o = 16; o > 0; o >>= 1)
        part += __shfl_down_sync(0xffffffffu, part, o);
    if (lane == 0) sWs[wid] = part;
    __syncthreads();
    if (tid == 0) {
        float s = 0.f;
        #pragma unroll
        for (int q = 0; q < 16; ++q) s += sWs[q];
        g_part[blockIdx.x] = s;
    }
}

// ---------------------------------------------------------------------------
// K4: up2 + conv d1 (parity-folded) via single-pass tf32 mma GEMM + gelu.
// Block = (image b, yi-quad): stages hq rows yi0-1..yi0+4 (zero halo, rna-
// rounded to tf32 so the HW sees unbiased-rounded operands instead of
// truncated ones), computes out[16c][8y][128x], coalesced float4 writeout.
// ---------------------------------------------------------------------------
#define K4_UN   8192
#define K4_BIAS (8192 + 17408)
#define K4_SMEM ((8192 + 17408 + 16) * 4)

__global__ void __launch_bounds__(256) k4_dec1(const float* __restrict__ bias) {
    extern __shared__ float sm4[];
    float* sWA = sm4;                 // 8192: A fragments (all parities)
    float* sHq = sm4 + K4_UN;         // 17408 union: hq tile / out tile
    float* sB  = sm4 + K4_BIAS;       // 16 bias

    int tid = threadIdx.x;
    int wid = tid >> 5, lane = tid & 31;
    int grp = lane >> 2, thr = lane & 3;
    int b = blockIdx.x >> 4, yq = blockIdx.x & 15;
    int yi0 = yq * 4;

    // stage A fragments
    {
        const float4* src = (const float4*)g_W4;
        float4* dst = (float4*)sWA;
        #pragma unroll
        for (int q = 0; q < 8; ++q) dst[tid + q * 256] = __ldg(src + tid + q * 256);
    }
    if (tid < 16) sB[tid] = __ldg(bias + tid);
    // stage hq tile rows yi0-1..yi0+4, cols -4..67 layout (data at +4)
    if (tid < 192) {
        int ci = tid / 6, r6 = tid - ci * 6;
        float* dst = sHq + ci * 456 + r6 * 72;
        int r = yi0 - 1 + r6;
        float4 z = make_float4(0.f, 0.f, 0.f, 0.f);
        *(float4*)(dst) = z;
        *(float4*)(dst + 68) = z;
        if ((unsigned)r < 64u) {
            const float* srow = g_hq + ((b * 32 + ci) << 12) + (r << 6);
            #pragma unroll
            for (int q = 0; q < 16; ++q) {
                float4 v = *(const float4*)(srow + q * 4);
                v.x = tf32r(v.x); v.y = tf32r(v.y);
                v.z = tf32r(v.z); v.w = tf32r(v.w);
                *(float4*)(dst + 4 + q * 4) = v;
            }
        } else {
            #pragma unroll
            for (int q = 0; q < 16; ++q) *(float4*)(dst + 4 + q * 4) = z;
        }
    }
    __syncthreads();

    int p = wid & 3, xh = wid >> 2;
    int py = p >> 1, px = p & 1;

    float acc[4][4][4];
    #pragma unroll
    for (int r = 0; r < 4; ++r)
        #pragma unroll
        for (int n = 0; n < 4; ++n)
            #pragma unroll
            for (int q = 0; q < 4; ++q) acc[r][n][q] = 0.f;

    #pragma unroll
    for (int kk = 0; kk < 16; ++kk) {
        float4 af = *(const float4*)(sWA + ((p * 16 + kk) * 32 + lane) * 4);
        int uv = kk >> 2;
        int du = (uv >> 1) + py - 1, dv = (uv & 1) + px - 1;
        int ci0 = (kk & 3) * 8;
        const float* B0 = sHq + (ci0 + thr) * 456 + (1 + du) * 72 + 4 + dv
                          + xh * 32 + grp;
        uint32_t a0 = __float_as_uint(af.x), a1 = __float_as_uint(af.y);
        uint32_t a2 = __float_as_uint(af.z), a3 = __float_as_uint(af.w);
        #pragma unroll
        for (int row = 0; row < 4; ++row)
            #pragma unroll
            for (int nt = 0; nt < 4; ++nt) {
                uint32_t b0 = __float_as_uint(B0[row * 72 + nt * 8]);
                uint32_t b1 = __float_as_uint(B0[row * 72 + nt * 8 + 1824]);
                mma8(acc[row][nt][0], acc[row][nt][1],
                     acc[row][nt][2], acc[row][nt][3],
                     a0, a1, a2, a3, b0, b1);
            }
    }

    __syncthreads();   // all warps done reading sHq
    float bias_lo = sB[grp], bias_hi = sB[grp + 8];
    float* sOut = sHq;   // reuse union: [8y][16c][136]
    #pragma unroll
    for (int row = 0; row < 4; ++row) {
        int yl = 2 * row + py;
        #pragma unroll
        for (int nt = 0; nt < 4; ++nt) {
            int x = 64 * xh + 16 * nt + 4 * thr + px;
            float* o = sOut + yl * 2176 + x;
            float v0 = acc[row][nt][0] + bias_lo;
            float v1 = acc[row][nt][1] + bias_lo;
            float v2 = acc[row][nt][2] + bias_hi;
            float v3 = acc[row][nt][3] + bias_hi;
            o[grp * 136]           = v0 * normcdff(v0);
            o[grp * 136 + 2]       = v1 * normcdff(v1);
            o[(grp + 8) * 136]     = v2 * normcdff(v2);
            o[(grp + 8) * 136 + 2] = v3 * normcdff(v3);
        }
    }
    __syncthreads();
    // coalesced writeout: 16c x 8y x 128x
    #pragma unroll
    for (int i = 0; i < 16; ++i) {
        int idx = i * 256 + tid;          // float4 id
        int x4 = idx & 31, ch = (idx >> 5) & 15, yy = idx >> 9;
        float4 val = *(const float4*)(sOut + yy * 2176 + ch * 136 + x4 * 4);
        *(float4*)(g_gg + ((b * 16 + ch) << 14) + (((yq << 3) + yy) << 7) + x4 * 4) = val;
    }
}

// ---------------------------------------------------------------------------
// K5: up2 + conv d2 (parity-folded) + clip. Thread = (b, y-pair i, x-quad j):
// computes 2x4 output pixels from a 3-row x 4-col gg window (float2 + edge
// singles, all aligned) -> ~4x fewer gg re-reads than 1px/thread.
// ---------------------------------------------------------------------------
__global__ void __launch_bounds__(256) k5_dec2(const float* __restrict__ bias,
                                               float* __restrict__ out) {
    __shared__ __align__(16) float sW[256];
    int tid = threadIdx.x;
    sW[tid] = g_Wf2[tid];
    __syncthreads();

    int lin = blockIdx.x * 256 + tid;
    int j = lin & 63, i = (lin >> 6) & 127, b = lin >> 13;
    bool topok = i > 0, botok = i < 127;
    bool eok = j > 0, fok = j < 63;
    float bz = __ldg(bias);

    float a00 = 0.f, a01 = 0.f, a02 = 0.f, a03 = 0.f;
    float a10 = 0.f, a11 = 0.f, a12 = 0.f, a13 = 0.f;

    #pragma unroll 1
    for (int ci = 0; ci < 16; ++ci) {
        const float* base = g_gg + ((b * 16 + ci) << 14) + 2 * j;
        float eA = 0.f, fA = 0.f, eB = 0.f, fB = 0.f, eC = 0.f, fC = 0.f;
        float2 dA = make_float2(0.f, 0.f), dC = dA, dB;
        const float* rB = base + (i << 7);
        dB = *(const float2*)rB;
        if (eok) eB = rB[-1];
        if (fok) fB = rB[2];
        if (topok) {
            const float* rA = base + ((i - 1) << 7);
            dA = *(const float2*)rA;
            if (eok) eA = rA[-1];
            if (fok) fA = rA[2];
        }
        if (botok) {
            const float* rC = base + ((i + 1) << 7);
            dC = *(const float2*)rC;
            if (eok) eC = rC[-1];
            if (fok) fC = rC[2];
        }
        float4 w00 = *(const float4*)(sW + ci * 4);          // p=0 (ye, xe)
        float4 w01 = *(const float4*)(sW + 64 + ci * 4);     // p=1 (ye, xo)
        float4 w10 = *(const float4*)(sW + 128 + ci * 4);    // p=2 (yo, xe)
        float4 w11 = *(const float4*)(sW + 192 + ci * 4);    // p=3 (yo, xo)
        // y = 2i (top=row i-1, bot=row i)
        a00 = fmaf(w00.x, eA,   fmaf(w00.y, dA.x, fmaf(w00.z, eB,   fmaf(w00.w, dB.x, a00))));
        a01 = fmaf(w01.x, dA.x, fmaf(w01.y, dA.y, fmaf(w01.z, dB.x, fmaf(w01.w, dB.y, a01))));
        a02 = fmaf(w00.x, dA.x, fmaf(w00.y, dA.y, fmaf(w00.z, dB.x, fmaf(w00.w, dB.y, a02))));
        a03 = fmaf(w01.x, dA.y, fmaf(w01.y, fA,   fmaf(w01.z, dB.y, fmaf(w01.w, fB,   a03))));
        // y = 2i+1 (top=row i, bot=row i+1)
        a10 = fmaf(w10.x, eB,   fmaf(w10.y, dB.x, fmaf(w10.z, eC,   fmaf(w10.w, dC.x, a10))));
        a11 = fmaf(w11.x, dB.x, fmaf(w11.y, dB.y, fmaf(w11.z, dC.x, fmaf(w11.w, dC.y, a11))));
        a12 = fmaf(w10.x, dB.x, fmaf(w10.y, dB.y, fmaf(w10.z, dC.x, fmaf(w10.w, dC.y, a12))));
        a13 = fmaf(w11.x, dB.y, fmaf(w11.y, fB,   fmaf(w11.z, dC.y, fmaf(w11.w, fC,   a13))));
    }

    float* o = out + (b << 16) + ((2 * i) << 8) + 4 * j;
    float4 r0 = make_float4(fminf(fmaxf(a00 + bz, -1.f), 1.f),
                            fminf(fmaxf(a01 + bz, -1.f), 1.f),
                            fminf(fmaxf(a02 + bz, -1.f), 1.f),
                            fminf(fmaxf(a03 + bz, -1.f), 1.f));
    *(float4*)o = r0;
    float4 r1 = make_float4(fminf(fmaxf(a10 + bz, -1.f), 1.f),
                            fminf(fmaxf(a11 + bz, -1.f), 1.f),
                            fminf(fmaxf(a12 + bz, -1.f), 1.f),
                            fminf(fmaxf(a13 + bz, -1.f), 1.f));
    *(float4*)(o + 256) = r1;
}

// ---------------------------------------------------------------------------
// K6: final commit-loss reduction (deterministic tree over 512 partials).
// ---------------------------------------------------------------------------
__global__ void __launch_bounds__(256) k6_loss(float* __restrict__ out) {
    __shared__ float sm[256];
    int tid = threadIdx.x;
    sm[tid] = g_part[tid] + g_part[tid + 256];
    __syncthreads();
    #pragma unroll
    for (int o = 128; o > 0; o >>= 1) {
        if (tid < o) sm[tid] += sm[tid + o];
        __syncthreads();
    }
    if (tid == 0) out[LOSS_OFF] = sm[0] * (1.0f / 4194304.0f);
}

// ---------------------------------------------------------------------------
extern "C" void kernel_launch(void* const* d_in, const int* in_sizes, int n_in,
                              void* d_out, int out_size) {
    const float* x   = (const float*)d_in[0];
    const float* e1w = (const float*)d_in[1];
    const float* e1b = (const float*)d_in[2];
    const float* e2w = (const float*)d_in[3];
    const float* e2b = (const float*)d_in[4];
    const float* cb  = (const float*)d_in[5];
    const float* d1w = (const float*)d_in[6];
    const float* d1b = (const float*)d_in[7];
    const float* d2w = (const float*)d_in[8];
    const float* d2b = (const float*)d_in[9];
    float* out = (float*)d_out;

    static int s_attr_done = 0;
    if (!s_attr_done) {
        cudaFuncSetAttribute(k3_vq, cudaFuncAttributeMaxDynamicSharedMemorySize,
                             K3_SMEM);
        cudaFuncSetAttribute(k4_dec1, cudaFuncAttributeMaxDynamicSharedMemorySize,
                             K4_SMEM);
        s_attr_done = 1;
    }

    k0_setup<<<163, 256>>>(cb, d1w, d2w);
    k1_conv1<<<2048, 256>>>(x, e1w, e1b);
    k2_conv2<<<2048, 128>>>(e2w, e2b);
    k3_vq<<<512, 512, K3_SMEM>>>(cb, out);
    k4_dec1<<<512, 256, K4_SMEM>>>(d1b);
    k5_dec2<<<1024, 256>>>(d2b, out);
    k6_loss<<<1, 256>>>(out);
}

// round 9
// speedup vs baseline: 1.4802x; 1.0731x over previous
#include <cuda_runtime.h>
#include <math.h>
#include <stdint.h>

// ---------------------------------------------------------------------------
// SimpleVQAutoEncoder on GB300 — FFMA2 encoder + mma.sync tf32 VQ + tf32 decoder
//
//   K1: [blocks <2048] conv1+maxpool2+gelu (FFMA2 pairs) -> g_h1
//       [blocks>=2048] setup: codebook norms/frags, decoder weight frags
//   K2: conv2(16->32,3x3,SAME) + maxpool2 (FFMA2)      -> g_h2 [32,32,64,64]
//   K3: VQ mma.sync tf32 3-pass split (hh+lh+hl)       -> g_hq, indices, g_part
//   K4: up2 + conv d1(32->16) folded, tf32 mma GEMM    -> g_gg [32,16,128,128]
//   K5: up2 + conv d2(16->1)  folded + clip, 8px/thr   -> out y
//   K6: reduce commit-loss partials                    -> out[last]
//
// Output layout (float32): [ y (32*256*256) | indices (32*64*64) | loss (1) ]
// ---------------------------------------------------------------------------

#define IDX_OFF   2097152
#define LOSS_OFF  2228224

typedef unsigned long long u64;

__device__ __forceinline__ u64 ffma2(u64 a, u64 b, u64 c) {
    u64 d;
    asm("fma.rn.f32x2 %0, %1, %2, %3;" : "=l"(d) : "l"(a), "l"(b), "l"(c));
    return d;
}
__device__ __forceinline__ u64 packff(float lo, float hi) {
    u64 d;
    asm("mov.b64 %0, {%1, %2};" : "=l"(d) : "f"(lo), "f"(hi));
    return d;
}
__device__ __forceinline__ float2 unpackff(u64 v) {
    float lo, hi;
    asm("mov.b64 {%0, %1}, %2;" : "=f"(lo), "=f"(hi) : "l"(v));
    return make_float2(lo, hi);
}
__device__ __forceinline__ float tf32r(float v) {
    uint32_t t;
    asm("cvt.rna.tf32.f32 %0, %1;" : "=r"(t) : "f"(v));
    return __uint_as_float(t);
}

// m16n8k8 tf32 mma (sm_80+ PTX, valid at base sm_103 target)
__device__ __forceinline__ void mma8(float& c0, float& c1, float& c2, float& c3,
                                     uint32_t a0, uint32_t a1, uint32_t a2,
                                     uint32_t a3, uint32_t b0, uint32_t b1) {
    asm volatile(
        "mma.sync.aligned.m16n8k8.row.col.f32.tf32.tf32.f32 "
        "{%0,%1,%2,%3}, {%4,%5,%6,%7}, {%8,%9}, {%0,%1,%2,%3};"
        : "+f"(c0), "+f"(c1), "+f"(c2), "+f"(c3)
        : "r"(a0), "r"(a1), "r"(a2), "r"(a3), "r"(b0), "r"(b1));
}

// Intermediates (device globals: no allocation allowed)
__device__ float g_h1[32 * 16 * 128 * 128];   // 33.5 MB
__device__ float g_h2[32 * 32 * 64 * 64];     // 16.8 MB
__device__ float g_hq[32 * 32 * 64 * 64];     // 16.8 MB
__device__ float g_gg[32 * 16 * 128 * 128];   // 33.5 MB
__device__ float g_cnh[512];                  // 0.5*||codebook_k||^2
__device__ float g_cbF[64 * 32 * 16];         // packed VQ codebook frags
__device__ float g_W4[4 * 16 * 32 * 4];       // tf32 d1 weight A-fragments
__device__ float g_Wf2[4 * 16 * 4];           // folded d2 [p][ci][uv]
__device__ float g_part[512];                 // commit-loss partials

// ---------------------------------------------------------------------------
// Setup body (runs in K1's tail blocks).
// - g_W4: decoder-1 folded weights in m16n8k8 A-fragment order, tf32-rounded.
// - g_cbF: VQ codebook hi/lo fragment planes.
// - g_cnh half-norms, g_Wf2 folded d2 weights.
// Nearest-up2 folding: output (y,x) reads a 2x2 hq patch; the 3x3 taps
// collapse per output parity (py,px) onto the 4 corners.
// ---------------------------------------------------------------------------
__device__ void setup_body(int t, const float* __restrict__ cb,
                           const float* __restrict__ d1w,
                           const float* __restrict__ d2w) {
    if (t < 8192) {
        int j = t & 3, lane = (t >> 2) & 31, kk = (t >> 7) & 15, p = t >> 11;
        int grp = lane >> 2, thr = lane & 3;
        int c = grp + (j & 1) * 8;
        int K = kk * 8 + thr + (j >> 1) * 4;
        int ci = K & 31, uv = K >> 5;
        int u = uv >> 1, v = uv & 1;
        int py = p >> 1, px = p & 1;
        float s = 0.f;
        #pragma unroll
        for (int dy = 0; dy < 3; ++dy) {
            int ug = (py == 0) ? (dy >= 1) : (dy >= 2);
            if (ug != u) continue;
            #pragma unroll
            for (int dx = 0; dx < 3; ++dx) {
                int vg = (px == 0) ? (dx >= 1) : (dx >= 2);
                if (vg != v) continue;
                s += d1w[((c * 32 + ci) * 3 + dy) * 3 + dx];
            }
        }
        g_W4[t] = tf32r(s);
    } else if (t < 8704) {
        int k = t - 8192;
        float s = 0.f;
        #pragma unroll
        for (int c = 0; c < 32; ++c) { float v = cb[k * 32 + c]; s = fmaf(v, v, s); }
        g_cnh[k] = 0.5f * s;
    } else if (t < 8960) {
        int e = t - 8704;
        int uv = e & 3, ci = (e >> 2) & 15, p = e >> 6;
        int py = p >> 1, px = p & 1, u = uv >> 1, v = uv & 1;
        float s = 0.f;
        #pragma unroll
        for (int dy = 0; dy < 3; ++dy) {
            int ug = (py == 0) ? (dy >= 1) : (dy >= 2);
            if (ug != u) continue;
            #pragma unroll
            for (int dx = 0; dx < 3; ++dx) {
                int vg = (px == 0) ? (dx >= 1) : (dx >= 2);
                if (vg != v) continue;
                s += d2w[ci * 9 + dy * 3 + dx];
            }
        }
        g_Wf2[(p * 16 + ci) * 4 + uv] = s;
    } else if (t < 41728) {
        int v = t - 8960;                 // 0..32767
        int e = v & 3, lane = (v >> 2) & 31, q = (v >> 7) & 3, nt = v >> 9;
        int grp = lane >> 2, thr = lane & 3;
        int j = q * 4 + e;
        int jj = j & 7;
        int ks = jj >> 1, half = jj & 1;
        int c = ks * 8 + thr + (half ? 4 : 0);
        float val = cb[(nt * 8 + grp) * 32 + c];
        float hi = __uint_as_float(__float_as_uint(val) & 0xFFFFE000u);
        g_cbF[v] = (j < 8) ? hi : (val - hi);
    }
}

// ---------------------------------------------------------------------------
// K1: conv1 + maxpool2 + exact gelu, FFMA2 channel pairs.
// Thread = (b, i, j) pooled pixel, 16 channels (8 pairs).
// Blocks >= 2048 run the setup body instead.
// ---------------------------------------------------------------------------
__global__ void __launch_bounds__(256) k1_conv1(const float* __restrict__ x,
                                                const float* __restrict__ w,
                                                const float* __restrict__ bias,
                                                const float* __restrict__ cb,
                                                const float* __restrict__ d1w,
                                                const float* __restrict__ d2w) {
    int tid = threadIdx.x;
    if (blockIdx.x >= 2048) {
        setup_body((blockIdx.x - 2048) * 256 + tid, cb, d1w, d2w);
        return;
    }

    __shared__ __align__(8) float2 sw2[72];   // [pair*9+tap] = (w[2p], w[2p+1])
    __shared__ float sb[16];
    if (tid < 72) {
        int pr = tid / 9, tap = tid - pr * 9;
        sw2[tid] = make_float2(__ldg(w + (2 * pr) * 9 + tap),
                               __ldg(w + (2 * pr + 1) * 9 + tap));
    }
    if (tid < 16) sb[tid] = __ldg(bias + tid);
    __syncthreads();

    int lin = blockIdx.x * 256 + tid;
    int j = lin & 127, i = (lin >> 7) & 127, b = lin >> 14;
    const float* xb = x + (b << 16);

    u64 xv[4][4];
    #pragma unroll
    for (int r = 0; r < 4; ++r) {
        int ry = 2 * i - 1 + r;
        bool rok = (unsigned)ry < 256u;
        #pragma unroll
        for (int cc = 0; cc < 4; ++cc) {
            int cx = 2 * j - 1 + cc;
            float v = (rok && (unsigned)cx < 256u) ? __ldg(xb + ry * 256 + cx) : 0.f;
            xv[r][cc] = packff(v, v);
        }
    }

    #pragma unroll
    for (int pr = 0; pr < 8; ++pr) {
        u64 wv[9];
        #pragma unroll
        for (int k = 0; k < 9; ++k) wv[k] = *(const u64*)(sw2 + pr * 9 + k);
        u64 acc[4];
        #pragma unroll
        for (int q = 0; q < 4; ++q) acc[q] = 0ull;
        #pragma unroll
        for (int dy = 0; dy < 3; ++dy)
            #pragma unroll
            for (int dx = 0; dx < 3; ++dx) {
                u64 wk = wv[dy * 3 + dx];
                acc[0] = ffma2(wk, xv[dy][dx], acc[0]);
                acc[1] = ffma2(wk, xv[dy][dx + 1], acc[1]);
                acc[2] = ffma2(wk, xv[dy + 1][dx], acc[2]);
                acc[3] = ffma2(wk, xv[dy + 1][dx + 1], acc[3]);
            }
        float2 m0 = unpackff(acc[0]);
        float2 m1 = unpackff(acc[1]);
        float2 m2 = unpackff(acc[2]);
        float2 m3 = unpackff(acc[3]);
        float lo = fmaxf(fmaxf(m0.x, m1.x), fmaxf(m2.x, m3.x)) + sb[2 * pr];
        float hi = fmaxf(fmaxf(m0.y, m1.y), fmaxf(m2.y, m3.y)) + sb[2 * pr + 1];
        g_h1[((b * 16 + 2 * pr) << 14) + (i << 7) + j]     = lo * normcdff(lo);
        g_h1[((b * 16 + 2 * pr + 1) << 14) + (i << 7) + j] = hi * normcdff(hi);
    }
}

// ---------------------------------------------------------------------------
// K2: conv2(16->32) + maxpool2, FFMA2 on channel pairs, prepacked patch.
// ---------------------------------------------------------------------------
__global__ void __launch_bounds__(128) k2_conv2(const float* __restrict__ w,
                                                const float* __restrict__ bias) {
    __shared__ __align__(16) float swt[2304];  // [ci*9+tap][16c]
    __shared__ float sb[16];
    int tid = threadIdx.x;
    int lin = blockIdx.x * 128 + tid;
    int j = lin & 63, i = (lin >> 6) & 63, half = (lin >> 12) & 1, b = lin >> 13;

    for (int t = tid; t < 2304; t += 128) {
        int ci = t / 144, r = t - ci * 144;
        int tap = r >> 4, c = r & 15;
        swt[t] = __ldg(w + (half * 16 + c) * 144 + ci * 9 + tap);
    }
    if (tid < 16) sb[tid] = __ldg(bias + half * 16 + tid);
    __syncthreads();

    int ry[4], cx[4];
    bool rok[4], cok[4];
    #pragma unroll
    for (int r = 0; r < 4; ++r) {
        ry[r] = 2 * i - 1 + r; rok[r] = (unsigned)ry[r] < 128u;
        cx[r] = 2 * j - 1 + r; cok[r] = (unsigned)cx[r] < 128u;
    }

    u64 acc[4][8];
    #pragma unroll
    for (int p = 0; p < 4; ++p)
        #pragma unroll
        for (int q = 0; q < 8; ++q) acc[p][q] = 0ull;

    #pragma unroll 1
    for (int ci = 0; ci < 16; ++ci) {
        const float* src = g_h1 + ((b * 16 + ci) << 14);
        u64 patch[4][4];
        #pragma unroll
        for (int r = 0; r < 4; ++r)
            #pragma unroll
            for (int cc = 0; cc < 4; ++cc) {
                float v = (rok[r] && cok[cc]) ? src[(ry[r] << 7) + cx[cc]] : 0.f;
                patch[r][cc] = packff(v, v);
            }

        #pragma unroll
        for (int dy = 0; dy < 3; ++dy)
            #pragma unroll
            for (int dx = 0; dx < 3; ++dx) {
                const ulonglong2* W2 =
                    (const ulonglong2*)(swt + (ci * 9 + dy * 3 + dx) * 16);
                ulonglong2 wA = W2[0], wB = W2[1], wC = W2[2], wD = W2[3];
                #pragma unroll
                for (int p = 0; p < 4; ++p) {
                    u64 vp = patch[(p >> 1) + dy][(p & 1) + dx];
                    acc[p][0] = ffma2(wA.x, vp, acc[p][0]);
                    acc[p][1] = ffma2(wA.y, vp, acc[p][1]);
                    acc[p][2] = ffma2(wB.x, vp, acc[p][2]);
                    acc[p][3] = ffma2(wB.y, vp, acc[p][3]);
                    acc[p][4] = ffma2(wC.x, vp, acc[p][4]);
                    acc[p][5] = ffma2(wC.y, vp, acc[p][5]);
                    acc[p][6] = ffma2(wD.x, vp, acc[p][6]);
                    acc[p][7] = ffma2(wD.y, vp, acc[p][7]);
                }
            }
    }

    float* dst = g_h2 + ((b * 32 + half * 16) << 12) + (i << 6) + j;
    #pragma unroll
    for (int q = 0; q < 8; ++q) {
        float2 m0 = unpackff(acc[0][q]);
        float2 m1 = unpackff(acc[1][q]);
        float2 m2 = unpackff(acc[2][q]);
        float2 m3 = unpackff(acc[3][q]);
        float lo = fmaxf(fmaxf(m0.x, m1.x), fmaxf(m2.x, m3.x)) + sb[2 * q];
        float hi = fmaxf(fmaxf(m0.y, m1.y), fmaxf(m2.y, m3.y)) + sb[2 * q + 1];
        dst[(2 * q) << 12]     = lo;
        dst[(2 * q + 1) << 12] = hi;
    }
}

// ---------------------------------------------------------------------------
// K3: VQ via mma.sync tf32 3-pass split (hh + lh + hl; the ll term is
// <= ~3e-7 relative — below the reordering noise already shown tolerable by
// two independent formulations producing identical indices).
// 512 threads/CTA (16 warps x m16 tokens = 256 tokens), 2 CTAs/SM.
// Codebook in 2 chunks of 256 codes; plane-interleaved frags in smem ->
// conflict-free LDS.128. argmax of f.c - 0.5||c||^2, lowest-index tie-break.
// ---------------------------------------------------------------------------
#define K3_CN   16384
#define K3_WS   (16384 + 512)
#define K3_SMEM ((16384 + 512 + 16) * 4)

__global__ void __launch_bounds__(512, 2) k3_vq(const float* __restrict__ cb,
                                                float* __restrict__ out) {
    extern __shared__ float sm3[];
    float* sF  = sm3;               // 16384 floats: one 256-code chunk
    float* sCn = sm3 + K3_CN;       // 512 half-norms
    float* sWs = sm3 + K3_WS;       // 16 warp partials

    int tid = threadIdx.x;
    int wid = tid >> 5, lane = tid & 31;
    int grp = lane >> 2, thr = lane & 3;
    int base = blockIdx.x * 256;           // global token base
    int b = base >> 12, ij0 = base & 4095;

    // ---- A fragments (16 tokens x K=32) from global into regs, hi/lo ----
    const float* fbase = g_h2 + (b << 17) + ij0 + wid * 16 + grp;
    uint32_t ahi[16], alo[16];
    #pragma unroll
    for (int ks = 0; ks < 4; ++ks) {
        int c0 = ks * 8 + thr, c1 = c0 + 4;
        float v00 = fbase[c0 << 12];
        float v10 = fbase[(c0 << 12) + 8];
        float v01 = fbase[c1 << 12];
        float v11 = fbase[(c1 << 12) + 8];
        uint32_t h;
        h = __float_as_uint(v00) & 0xFFFFE000u;
        ahi[ks * 4 + 0] = h; alo[ks * 4 + 0] = __float_as_uint(v00 - __uint_as_float(h));
        h = __float_as_uint(v10) & 0xFFFFE000u;
        ahi[ks * 4 + 1] = h; alo[ks * 4 + 1] = __float_as_uint(v10 - __uint_as_float(h));
        h = __float_as_uint(v01) & 0xFFFFE000u;
        ahi[ks * 4 + 2] = h; alo[ks * 4 + 2] = __float_as_uint(v01 - __uint_as_float(h));
        h = __float_as_uint(v11) & 0xFFFFE000u;
        ahi[ks * 4 + 3] = h; alo[ks * 4 + 3] = __float_as_uint(v11 - __uint_as_float(h));
    }
    if (tid < 512) sCn[tid] = g_cnh[tid];

    float bv0 = -1e30f, bv1 = -1e30f;
    int bk0 = 0, bk1 = 0;

    #pragma unroll 1
    for (int ch = 0; ch < 2; ++ch) {
        __syncthreads();   // previous chunk fully consumed
        {
            const float4* src = (const float4*)(g_cbF + ch * 16384);
            float4* dst = (float4*)sF;
            #pragma unroll
            for (int t = 0; t < 8; ++t)
                dst[tid + t * 512] = __ldg(src + tid + t * 512);
        }
        __syncthreads();

        #pragma unroll 2
        for (int nt = 0; nt < 32; ++nt) {
            const float4* fp = (const float4*)sF + (nt * 4) * 32 + lane;
            float c0 = 0.f, c1 = 0.f, c2 = 0.f, c3 = 0.f;
            // hi planes (b = hi): hh + lh passes
            {
                float4 h0 = fp[0], h1 = fp[32];
                uint32_t b0, b1;
                b0 = __float_as_uint(h0.x); b1 = __float_as_uint(h0.y);
                mma8(c0, c1, c2, c3, ahi[0], ahi[1], ahi[2], ahi[3], b0, b1);
                mma8(c0, c1, c2, c3, alo[0], alo[1], alo[2], alo[3], b0, b1);
                b0 = __float_as_uint(h0.z); b1 = __float_as_uint(h0.w);
                mma8(c0, c1, c2, c3, ahi[4], ahi[5], ahi[6], ahi[7], b0, b1);
                mma8(c0, c1, c2, c3, alo[4], alo[5], alo[6], alo[7], b0, b1);
                b0 = __float_as_uint(h1.x); b1 = __float_as_uint(h1.y);
                mma8(c0, c1, c2, c3, ahi[8], ahi[9], ahi[10], ahi[11], b0, b1);
                mma8(c0, c1, c2, c3, alo[8], alo[9], alo[10], alo[11], b0, b1);
                b0 = __float_as_uint(h1.z); b1 = __float_as_uint(h1.w);
                mma8(c0, c1, c2, c3, ahi[12], ahi[13], ahi[14], ahi[15], b0, b1);
                mma8(c0, c1, c2, c3, alo[12], alo[13], alo[14], alo[15], b0, b1);
            }
            // lo planes (b = lo): hl pass only (ll dropped)
            {
                float4 l0 = fp[64], l1 = fp[96];
                uint32_t b0, b1;
                b0 = __float_as_uint(l0.x); b1 = __float_as_uint(l0.y);
                mma8(c0, c1, c2, c3, ahi[0], ahi[1], ahi[2], ahi[3], b0, b1);
                b0 = __float_as_uint(l0.z); b1 = __float_as_uint(l0.w);
                mma8(c0, c1, c2, c3, ahi[4], ahi[5], ahi[6], ahi[7], b0, b1);
                b0 = __float_as_uint(l1.x); b1 = __float_as_uint(l1.y);
                mma8(c0, c1, c2, c3, ahi[8], ahi[9], ahi[10], ahi[11], b0, b1);
                b0 = __float_as_uint(l1.z); b1 = __float_as_uint(l1.w);
                mma8(c0, c1, c2, c3, ahi[12], ahi[13], ahi[14], ahi[15], b0, b1);
            }

            int col = ch * 256 + nt * 8 + 2 * thr;
            float cn0 = sCn[col], cn1 = sCn[col + 1];
            float v;
            v = c0 - cn0; if (v > bv0) { bv0 = v; bk0 = col; }
            v = c1 - cn1; if (v > bv0) { bv0 = v; bk0 = col + 1; }
            v = c2 - cn0; if (v > bv1) { bv1 = v; bk1 = col; }
            v = c3 - cn1; if (v > bv1) { bv1 = v; bk1 = col + 1; }
        }
    }

    // ---- reduce across the 4 lanes of each row-group (lowest k on ties) ----
    #pragma unroll
    for (int o = 1; o <= 2; o <<= 1) {
        float ov = __shfl_xor_sync(0xffffffffu, bv0, o);
        int   ok = __shfl_xor_sync(0xffffffffu, bk0, o);
        if (ov > bv0 || (ov == bv0 && ok < bk0)) { bv0 = ov; bk0 = ok; }
        ov = __shfl_xor_sync(0xffffffffu, bv1, o);
        ok = __shfl_xor_sync(0xffffffffu, bk1, o);
        if (ov > bv1 || (ov == bv1 && ok < bk1)) { bv1 = ov; bk1 = ok; }
    }

    int tokl = wid * 16 + grp;
    if (thr == 0) out[IDX_OFF + base + tokl] = (float)bk0;
    if (thr == 2) out[IDX_OFF + base + tokl + 8] = (float)bk1;

    // ---- gather + commit-loss partials: 4 lanes = 2 tokens x 2 halves ----
    int mytok = tokl + ((thr >> 1) << 3);
    int myk   = (thr < 2) ? bk0 : bk1;
    int cbase = (thr & 1) << 4;
    const float* cbr = cb + myk * 32 + cbase;
    const float* h2p = g_h2 + (b << 17) + (cbase << 12) + ij0 + mytok;
    float*       hqp = g_hq + (b << 17) + (cbase << 12) + ij0 + mytok;
    float part = 0.f;
    #pragma unroll
    for (int c = 0; c < 16; ++c) {
        float qv = __ldg(cbr + c);
        float fv = h2p[c << 12];
        float d = qv - fv;
        part = fmaf(d, d, part);
        hqp[c << 12] = qv;
    }

    // deterministic block reduction (16 warps)
    #pragma unroll
    for (int o = 16; o > 0; o >>= 1)
        part += __shfl_down_sync(0xffffffffu, part, o);
    if (lane == 0) sWs[wid] = part;
    __syncthreads();
    if (tid == 0) {
        float s = 0.f;
        #pragma unroll
        for (int q = 0; q < 16; ++q) s += sWs[q];
        g_part[blockIdx.x] = s;
    }
}

// ---------------------------------------------------------------------------
// K4: up2 + conv d1 (parity-folded) via single-pass tf32 mma GEMM + gelu.
// Block = (image b, yi-quad): stages hq rows yi0-1..yi0+4 (zero halo, rna-
// rounded to tf32), computes out[16c][8y][128x], coalesced float4 writeout.
// ---------------------------------------------------------------------------
#define K4_UN   8192
#define K4_BIAS (8192 + 17408)
#define K4_SMEM ((8192 + 17408 + 16) * 4)

__global__ void __launch_bounds__(256) k4_dec1(const float* __restrict__ bias) {
    extern __shared__ float sm4[];
    float* sWA = sm4;                 // 8192: A fragments (all parities)
    float* sHq = sm4 + K4_UN;         // 17408 union: hq tile / out tile
    float* sB  = sm4 + K4_BIAS;       // 16 bias

    int tid = threadIdx.x;
    int wid = tid >> 5, lane = tid & 31;
    int grp = lane >> 2, thr = lane & 3;
    int b = blockIdx.x >> 4, yq = blockIdx.x & 15;
    int yi0 = yq * 4;

    // stage A fragments
    {
        const float4* src = (const float4*)g_W4;
        float4* dst = (float4*)sWA;
        #pragma unroll
        for (int q = 0; q < 8; ++q) dst[tid + q * 256] = __ldg(src + tid + q * 256);
    }
    if (tid < 16) sB[tid] = __ldg(bias + tid);
    // stage hq tile rows yi0-1..yi0+4, cols -4..67 layout (data at +4)
    if (tid < 192) {
        int ci = tid / 6, r6 = tid - ci * 6;
        float* dst = sHq + ci * 456 + r6 * 72;
        int r = yi0 - 1 + r6;
        float4 z = make_float4(0.f, 0.f, 0.f, 0.f);
        *(float4*)(dst) = z;
        *(float4*)(dst + 68) = z;
        if ((unsigned)r < 64u) {
            const float* srow = g_hq + ((b * 32 + ci) << 12) + (r << 6);
            #pragma unroll
            for (int q = 0; q < 16; ++q) {
                float4 v = *(const float4*)(srow + q * 4);
                v.x = tf32r(v.x); v.y = tf32r(v.y);
                v.z = tf32r(v.z); v.w = tf32r(v.w);
                *(float4*)(dst + 4 + q * 4) = v;
            }
        } else {
            #pragma unroll
            for (int q = 0; q < 16; ++q) *(float4*)(dst + 4 + q * 4) = z;
        }
    }
    __syncthreads();

    int p = wid & 3, xh = wid >> 2;
    int py = p >> 1, px = p & 1;

    float acc[4][4][4];
    #pragma unroll
    for (int r = 0; r < 4; ++r)
        #pragma unroll
        for (int n = 0; n < 4; ++n)
            #pragma unroll
            for (int q = 0; q < 4; ++q) acc[r][n][q] = 0.f;

    #pragma unroll
    for (int kk = 0; kk < 16; ++kk) {
        float4 af = *(const float4*)(sWA + ((p * 16 + kk) * 32 + lane) * 4);
        int uv = kk >> 2;
        int du = (uv >> 1) + py - 1, dv = (uv & 1) + px - 1;
        int ci0 = (kk & 3) * 8;
        const float* B0 = sHq + (ci0 + thr) * 456 + (1 + du) * 72 + 4 + dv
                          + xh * 32 + grp;
        uint32_t a0 = __float_as_uint(af.x), a1 = __float_as_uint(af.y);
        uint32_t a2 = __float_as_uint(af.z), a3 = __float_as_uint(af.w);
        #pragma unroll
        for (int row = 0; row < 4; ++row)
            #pragma unroll
            for (int nt = 0; nt < 4; ++nt) {
                uint32_t b0 = __float_as_uint(B0[row * 72 + nt * 8]);
                uint32_t b1 = __float_as_uint(B0[row * 72 + nt * 8 + 1824]);
                mma8(acc[row][nt][0], acc[row][nt][1],
                     acc[row][nt][2], acc[row][nt][3],
                     a0, a1, a2, a3, b0, b1);
            }
    }

    __syncthreads();   // all warps done reading sHq
    float bias_lo = sB[grp], bias_hi = sB[grp + 8];
    float* sOut = sHq;   // reuse union: [8y][16c][136]
    #pragma unroll
    for (int row = 0; row < 4; ++row) {
        int yl = 2 * row + py;
        #pragma unroll
        for (int nt = 0; nt < 4; ++nt) {
            int x = 64 * xh + 16 * nt + 4 * thr + px;
            float* o = sOut + yl * 2176 + x;
            float v0 = acc[row][nt][0] + bias_lo;
            float v1 = acc[row][nt][1] + bias_lo;
            float v2 = acc[row][nt][2] + bias_hi;
            float v3 = acc[row][nt][3] + bias_hi;
            o[grp * 136]           = v0 * normcdff(v0);
            o[grp * 136 + 2]       = v1 * normcdff(v1);
            o[(grp + 8) * 136]     = v2 * normcdff(v2);
            o[(grp + 8) * 136 + 2] = v3 * normcdff(v3);
        }
    }
    __syncthreads();
    // coalesced writeout: 16c x 8y x 128x
    #pragma unroll
    for (int i = 0; i < 16; ++i) {
        int idx = i * 256 + tid;          // float4 id
        int x4 = idx & 31, ch = (idx >> 5) & 15, yy = idx >> 9;
        float4 val = *(const float4*)(sOut + yy * 2176 + ch * 136 + x4 * 4);
        *(float4*)(g_gg + ((b * 16 + ch) << 14) + (((yq << 3) + yy) << 7) + x4 * 4) = val;
    }
}

// ---------------------------------------------------------------------------
// K5: up2 + conv d2 (parity-folded) + clip. Thread = (b, y-pair i, x-quad j):
// 2x4 output pixels from a 3-row x 4-col gg window.
// ---------------------------------------------------------------------------
__global__ void __launch_bounds__(256) k5_dec2(const float* __restrict__ bias,
                                               float* __restrict__ out) {
    __shared__ __align__(16) float sW[256];
    int tid = threadIdx.x;
    sW[tid] = g_Wf2[tid];
    __syncthreads();

    int lin = blockIdx.x * 256 + tid;
    int j = lin & 63, i = (lin >> 6) & 127, b = lin >> 13;
    bool topok = i > 0, botok = i < 127;
    bool eok = j > 0, fok = j < 63;
    float bz = __ldg(bias);

    float a00 = 0.f, a01 = 0.f, a02 = 0.f, a03 = 0.f;
    float a10 = 0.f, a11 = 0.f, a12 = 0.f, a13 = 0.f;

    #pragma unroll 1
    for (int ci = 0; ci < 16; ++ci) {
        const float* base = g_gg + ((b * 16 + ci) << 14) + 2 * j;
        float eA = 0.f, fA = 0.f, eB = 0.f, fB = 0.f, eC = 0.f, fC = 0.f;
        float2 dA = make_float2(0.f, 0.f), dC = dA, dB;
        const float* rB = base + (i << 7);
        dB = *(const float2*)rB;
        if (eok) eB = rB[-1];
        if (fok) fB = rB[2];
        if (topok) {
            const float* rA = base + ((i - 1) << 7);
            dA = *(const float2*)rA;
            if (eok) eA = rA[-1];
            if (fok) fA = rA[2];
        }
        if (botok) {
            const float* rC = base + ((i + 1) << 7);
            dC = *(const float2*)rC;
            if (eok) eC = rC[-1];
            if (fok) fC = rC[2];
        }
        float4 w00 = *(const float4*)(sW + ci * 4);          // p=0 (ye, xe)
        float4 w01 = *(const float4*)(sW + 64 + ci * 4);     // p=1 (ye, xo)
        float4 w10 = *(const float4*)(sW + 128 + ci * 4);    // p=2 (yo, xe)
        float4 w11 = *(const float4*)(sW + 192 + ci * 4);    // p=3 (yo, xo)
        // y = 2i (top=row i-1, bot=row i)
        a00 = fmaf(w00.x, eA,   fmaf(w00.y, dA.x, fmaf(w00.z, eB,   fmaf(w00.w, dB.x, a00))));
        a01 = fmaf(w01.x, dA.x, fmaf(w01.y, dA.y, fmaf(w01.z, dB.x, fmaf(w01.w, dB.y, a01))));
        a02 = fmaf(w00.x, dA.x, fmaf(w00.y, dA.y, fmaf(w00.z, dB.x, fmaf(w00.w, dB.y, a02))));
        a03 = fmaf(w01.x, dA.y, fmaf(w01.y, fA,   fmaf(w01.z, dB.y, fmaf(w01.w, fB,   a03))));
        // y = 2i+1 (top=row i, bot=row i+1)
        a10 = fmaf(w10.x, eB,   fmaf(w10.y, dB.x, fmaf(w10.z, eC,   fmaf(w10.w, dC.x, a10))));
        a11 = fmaf(w11.x, dB.x, fmaf(w11.y, dB.y, fmaf(w11.z, dC.x, fmaf(w11.w, dC.y, a11))));
        a12 = fmaf(w10.x, dB.x, fmaf(w10.y, dB.y, fmaf(w10.z, dC.x, fmaf(w10.w, dC.y, a12))));
        a13 = fmaf(w11.x, dB.y, fmaf(w11.y, fB,   fmaf(w11.z, dC.y, fmaf(w11.w, fC,   a13))));
    }

    float* o = out + (b << 16) + ((2 * i) << 8) + 4 * j;
    float4 r0 = make_float4(fminf(fmaxf(a00 + bz, -1.f), 1.f),
                            fminf(fmaxf(a01 + bz, -1.f), 1.f),
                            fminf(fmaxf(a02 + bz, -1.f), 1.f),
                            fminf(fmaxf(a03 + bz, -1.f), 1.f));
    *(float4*)o = r0;
    float4 r1 = make_float4(fminf(fmaxf(a10 + bz, -1.f), 1.f),
                            fminf(fmaxf(a11 + bz, -1.f), 1.f),
                            fminf(fmaxf(a12 + bz, -1.f), 1.f),
                            fminf(fmaxf(a13 + bz, -1.f), 1.f));
    *(float4*)(o + 256) = r1;
}

// ---------------------------------------------------------------------------
// K6: final commit-loss reduction (deterministic tree over 512 partials).
// ---------------------------------------------------------------------------
__global__ void __launch_bounds__(256) k6_loss(float* __restrict__ out) {
    __shared__ float sm[256];
    int tid = threadIdx.x;
    sm[tid] = g_part[tid] + g_part[tid + 256];
    __syncthreads();
    #pragma unroll
    for (int o = 128; o > 0; o >>= 1) {
        if (tid < o) sm[tid] += sm[tid + o];
        __syncthreads();
    }
    if (tid == 0) out[LOSS_OFF] = sm[0] * (1.0f / 4194304.0f);
}

// ---------------------------------------------------------------------------
extern "C" void kernel_launch(void* const* d_in, const int* in_sizes, int n_in,
                              void* d_out, int out_size) {
    const float* x   = (const float*)d_in[0];
    const float* e1w = (const float*)d_in[1];
    const float* e1b = (const float*)d_in[2];
    const float* e2w = (const float*)d_in[3];
    const float* e2b = (const float*)d_in[4];
    const float* cb  = (const float*)d_in[5];
    const float* d1w = (const float*)d_in[6];
    const float* d1b = (const float*)d_in[7];
    const float* d2w = (const float*)d_in[8];
    const float* d2b = (const float*)d_in[9];
    float* out = (float*)d_out;

    static int s_attr_done = 0;
    if (!s_attr_done) {
        cudaFuncSetAttribute(k3_vq, cudaFuncAttributeMaxDynamicSharedMemorySize,
                             K3_SMEM);
        cudaFuncSetAttribute(k4_dec1, cudaFuncAttributeMaxDynamicSharedMemorySize,
                             K4_SMEM);
        s_attr_done = 1;
    }

    k1_conv1<<<2211, 256>>>(x, e1w, e1b, cb, d1w, d2w);   // conv1 + setup tail
    k2_conv2<<<2048, 128>>>(e2w, e2b);
    k3_vq<<<512, 512, K3_SMEM>>>(cb, out);
    k4_dec1<<<512, 256, K4_SMEM>>>(d1b);
    k5_dec2<<<1024, 256>>>(d2b, out);
    k6_loss<<<1, 256>>>(out);
}

// round 10
// speedup vs baseline: 1.5581x; 1.0526x over previous
#include <cuda_runtime.h>
#include <math.h>
#include <stdint.h>

// ---------------------------------------------------------------------------
// SimpleVQAutoEncoder on GB300 — FFMA2 encoder + mma.sync tf32 VQ + tf32 decoder
//
//   K1: [blocks <2048] conv1+maxpool2+gelu (FFMA2 pairs) -> g_h1
//       [blocks>=2048] setup: codebook norms/frags, decoder weight frags
//   K2: conv2(16->32,3x3,SAME) + maxpool2 (FFMA2)      -> g_h2 [32,32,64,64]
//   K3: VQ mma.sync tf32 3-pass split (hh+lh+hl)       -> g_hq, indices, g_part
//   K4: up2 + conv d1(32->16) folded, tf32 mma GEMM    -> g_gg [32,16,128,128]
//   K5: up2 + conv d2(16->1)  folded + clip, 8px/thr   -> out y
//   K6: reduce commit-loss partials                    -> out[last]
//
// Output layout (float32): [ y (32*256*256) | indices (32*64*64) | loss (1) ]
// ---------------------------------------------------------------------------

#define IDX_OFF   2097152
#define LOSS_OFF  2228224

typedef unsigned long long u64;

__device__ __forceinline__ u64 ffma2(u64 a, u64 b, u64 c) {
    u64 d;
    asm("fma.rn.f32x2 %0, %1, %2, %3;" : "=l"(d) : "l"(a), "l"(b), "l"(c));
    return d;
}
__device__ __forceinline__ u64 packff(float lo, float hi) {
    u64 d;
    asm("mov.b64 %0, {%1, %2};" : "=l"(d) : "f"(lo), "f"(hi));
    return d;
}
__device__ __forceinline__ float2 unpackff(u64 v) {
    float lo, hi;
    asm("mov.b64 {%0, %1}, %2;" : "=f"(lo), "=f"(hi) : "l"(v));
    return make_float2(lo, hi);
}
__device__ __forceinline__ float tf32r(float v) {
    uint32_t t;
    asm("cvt.rna.tf32.f32 %0, %1;" : "=r"(t) : "f"(v));
    return __uint_as_float(t);
}

// m16n8k8 tf32 mma (sm_80+ PTX, valid at base sm_103 target)
__device__ __forceinline__ void mma8(float& c0, float& c1, float& c2, float& c3,
                                     uint32_t a0, uint32_t a1, uint32_t a2,
                                     uint32_t a3, uint32_t b0, uint32_t b1) {
    asm volatile(
        "mma.sync.aligned.m16n8k8.row.col.f32.tf32.tf32.f32 "
        "{%0,%1,%2,%3}, {%4,%5,%6,%7}, {%8,%9}, {%0,%1,%2,%3};"
        : "+f"(c0), "+f"(c1), "+f"(c2), "+f"(c3)
        : "r"(a0), "r"(a1), "r"(a2), "r"(a3), "r"(b0), "r"(b1));
}

// Intermediates (device globals: no allocation allowed)
__device__ float g_h1[32 * 16 * 128 * 128];   // 33.5 MB
__device__ float g_h2[32 * 32 * 64 * 64];     // 16.8 MB
__device__ float g_hq[32 * 32 * 64 * 64];     // 16.8 MB
__device__ float g_gg[32 * 16 * 128 * 128];   // 33.5 MB
__device__ float g_cnh[512];                  // 0.5*||codebook_k||^2
__device__ float g_cbF[64 * 32 * 16];         // packed VQ codebook frags
__device__ float g_W4[4 * 16 * 32 * 4];       // tf32 d1 weight A-fragments
__device__ float g_Wf2[4 * 16 * 4];           // folded d2 [p][ci][uv]
__device__ float g_part[512];                 // commit-loss partials

// ---------------------------------------------------------------------------
// Setup body (runs in K1's tail blocks).
// - g_W4: decoder-1 folded weights in m16n8k8 A-fragment order, tf32-rounded.
// - g_cbF: VQ codebook hi/lo fragment planes.
// - g_cnh half-norms, g_Wf2 folded d2 weights.
// Nearest-up2 folding: output (y,x) reads a 2x2 hq patch; the 3x3 taps
// collapse per output parity (py,px) onto the 4 corners.
// ---------------------------------------------------------------------------
__device__ void setup_body(int t, const float* __restrict__ cb,
                           const float* __restrict__ d1w,
                           const float* __restrict__ d2w) {
    if (t < 8192) {
        int j = t & 3, lane = (t >> 2) & 31, kk = (t >> 7) & 15, p = t >> 11;
        int grp = lane >> 2, thr = lane & 3;
        int c = grp + (j & 1) * 8;
        int K = kk * 8 + thr + (j >> 1) * 4;
        int ci = K & 31, uv = K >> 5;
        int u = uv >> 1, v = uv & 1;
        int py = p >> 1, px = p & 1;
        float s = 0.f;
        #pragma unroll
        for (int dy = 0; dy < 3; ++dy) {
            int ug = (py == 0) ? (dy >= 1) : (dy >= 2);
            if (ug != u) continue;
            #pragma unroll
            for (int dx = 0; dx < 3; ++dx) {
                int vg = (px == 0) ? (dx >= 1) : (dx >= 2);
                if (vg != v) continue;
                s += d1w[((c * 32 + ci) * 3 + dy) * 3 + dx];
            }
        }
        g_W4[t] = tf32r(s);
    } else if (t < 8704) {
        int k = t - 8192;
        float s = 0.f;
        #pragma unroll
        for (int c = 0; c < 32; ++c) { float v = cb[k * 32 + c]; s = fmaf(v, v, s); }
        g_cnh[k] = 0.5f * s;
    } else if (t < 8960) {
        int e = t - 8704;
        int uv = e & 3, ci = (e >> 2) & 15, p = e >> 6;
        int py = p >> 1, px = p & 1, u = uv >> 1, v = uv & 1;
        float s = 0.f;
        #pragma unroll
        for (int dy = 0; dy < 3; ++dy) {
            int ug = (py == 0) ? (dy >= 1) : (dy >= 2);
            if (ug != u) continue;
            #pragma unroll
            for (int dx = 0; dx < 3; ++dx) {
                int vg = (px == 0) ? (dx >= 1) : (dx >= 2);
                if (vg != v) continue;
                s += d2w[ci * 9 + dy * 3 + dx];
            }
        }
        g_Wf2[(p * 16 + ci) * 4 + uv] = s;
    } else if (t < 41728) {
        int v = t - 8960;                 // 0..32767
        int e = v & 3, lane = (v >> 2) & 31, q = (v >> 7) & 3, nt = v >> 9;
        int grp = lane >> 2, thr = lane & 3;
        int j = q * 4 + e;
        int jj = j & 7;
        int ks = jj >> 1, half = jj & 1;
        int c = ks * 8 + thr + (half ? 4 : 0);
        float val = cb[(nt * 8 + grp) * 32 + c];
        float hi = __uint_as_float(__float_as_uint(val) & 0xFFFFE000u);
        g_cbF[v] = (j < 8) ? hi : (val - hi);
    }
}

// ---------------------------------------------------------------------------
// K1: conv1 + maxpool2 + exact gelu, FFMA2 channel pairs.
// Thread = (b, i, j) pooled pixel, 16 channels (8 pairs).
// Blocks >= 2048 run the setup body instead.
// ---------------------------------------------------------------------------
__global__ void __launch_bounds__(256) k1_conv1(const float* __restrict__ x,
                                                const float* __restrict__ w,
                                                const float* __restrict__ bias,
                                                const float* __restrict__ cb,
                                                const float* __restrict__ d1w,
                                                const float* __restrict__ d2w) {
    int tid = threadIdx.x;
    if (blockIdx.x >= 2048) {
        setup_body((blockIdx.x - 2048) * 256 + tid, cb, d1w, d2w);
        return;
    }

    __shared__ __align__(8) float2 sw2[72];   // [pair*9+tap] = (w[2p], w[2p+1])
    __shared__ float sb[16];
    if (tid < 72) {
        int pr = tid / 9, tap = tid - pr * 9;
        sw2[tid] = make_float2(__ldg(w + (2 * pr) * 9 + tap),
                               __ldg(w + (2 * pr + 1) * 9 + tap));
    }
    if (tid < 16) sb[tid] = __ldg(bias + tid);
    __syncthreads();

    int lin = blockIdx.x * 256 + tid;
    int j = lin & 127, i = (lin >> 7) & 127, b = lin >> 14;
    const float* xb = x + (b << 16);

    u64 xv[4][4];
    #pragma unroll
    for (int r = 0; r < 4; ++r) {
        int ry = 2 * i - 1 + r;
        bool rok = (unsigned)ry < 256u;
        #pragma unroll
        for (int cc = 0; cc < 4; ++cc) {
            int cx = 2 * j - 1 + cc;
            float v = (rok && (unsigned)cx < 256u) ? __ldg(xb + ry * 256 + cx) : 0.f;
            xv[r][cc] = packff(v, v);
        }
    }

    #pragma unroll
    for (int pr = 0; pr < 8; ++pr) {
        u64 wv[9];
        #pragma unroll
        for (int k = 0; k < 9; ++k) wv[k] = *(const u64*)(sw2 + pr * 9 + k);
        u64 acc[4];
        #pragma unroll
        for (int q = 0; q < 4; ++q) acc[q] = 0ull;
        #pragma unroll
        for (int dy = 0; dy < 3; ++dy)
            #pragma unroll
            for (int dx = 0; dx < 3; ++dx) {
                u64 wk = wv[dy * 3 + dx];
                acc[0] = ffma2(wk, xv[dy][dx], acc[0]);
                acc[1] = ffma2(wk, xv[dy][dx + 1], acc[1]);
                acc[2] = ffma2(wk, xv[dy + 1][dx], acc[2]);
                acc[3] = ffma2(wk, xv[dy + 1][dx + 1], acc[3]);
            }
        float2 m0 = unpackff(acc[0]);
        float2 m1 = unpackff(acc[1]);
        float2 m2 = unpackff(acc[2]);
        float2 m3 = unpackff(acc[3]);
        float lo = fmaxf(fmaxf(m0.x, m1.x), fmaxf(m2.x, m3.x)) + sb[2 * pr];
        float hi = fmaxf(fmaxf(m0.y, m1.y), fmaxf(m2.y, m3.y)) + sb[2 * pr + 1];
        g_h1[((b * 16 + 2 * pr) << 14) + (i << 7) + j]     = lo * normcdff(lo);
        g_h1[((b * 16 + 2 * pr + 1) << 14) + (i << 7) + j] = hi * normcdff(hi);
    }
}

// ---------------------------------------------------------------------------
// K2: conv2(16->32) + maxpool2, FFMA2 on channel pairs, prepacked patch.
// ---------------------------------------------------------------------------
__global__ void __launch_bounds__(128) k2_conv2(const float* __restrict__ w,
                                                const float* __restrict__ bias) {
    __shared__ __align__(16) float swt[2304];  // [ci*9+tap][16c]
    __shared__ float sb[16];
    int tid = threadIdx.x;
    int lin = blockIdx.x * 128 + tid;
    int j = lin & 63, i = (lin >> 6) & 63, half = (lin >> 12) & 1, b = lin >> 13;

    for (int t = tid; t < 2304; t += 128) {
        int ci = t / 144, r = t - ci * 144;
        int tap = r >> 4, c = r & 15;
        swt[t] = __ldg(w + (half * 16 + c) * 144 + ci * 9 + tap);
    }
    if (tid < 16) sb[tid] = __ldg(bias + half * 16 + tid);
    __syncthreads();

    int ry[4], cx[4];
    bool rok[4], cok[4];
    #pragma unroll
    for (int r = 0; r < 4; ++r) {
        ry[r] = 2 * i - 1 + r; rok[r] = (unsigned)ry[r] < 128u;
        cx[r] = 2 * j - 1 + r; cok[r] = (unsigned)cx[r] < 128u;
    }

    u64 acc[4][8];
    #pragma unroll
    for (int p = 0; p < 4; ++p)
        #pragma unroll
        for (int q = 0; q < 8; ++q) acc[p][q] = 0ull;

    #pragma unroll 1
    for (int ci = 0; ci < 16; ++ci) {
        const float* src = g_h1 + ((b * 16 + ci) << 14);
        u64 patch[4][4];
        #pragma unroll
        for (int r = 0; r < 4; ++r)
            #pragma unroll
            for (int cc = 0; cc < 4; ++cc) {
                float v = (rok[r] && cok[cc]) ? src[(ry[r] << 7) + cx[cc]] : 0.f;
                patch[r][cc] = packff(v, v);
            }

        #pragma unroll
        for (int dy = 0; dy < 3; ++dy)
            #pragma unroll
            for (int dx = 0; dx < 3; ++dx) {
                const ulonglong2* W2 =
                    (const ulonglong2*)(swt + (ci * 9 + dy * 3 + dx) * 16);
                ulonglong2 wA = W2[0], wB = W2[1], wC = W2[2], wD = W2[3];
                #pragma unroll
                for (int p = 0; p < 4; ++p) {
                    u64 vp = patch[(p >> 1) + dy][(p & 1) + dx];
                    acc[p][0] = ffma2(wA.x, vp, acc[p][0]);
                    acc[p][1] = ffma2(wA.y, vp, acc[p][1]);
                    acc[p][2] = ffma2(wB.x, vp, acc[p][2]);
                    acc[p][3] = ffma2(wB.y, vp, acc[p][3]);
                    acc[p][4] = ffma2(wC.x, vp, acc[p][4]);
                    acc[p][5] = ffma2(wC.y, vp, acc[p][5]);
                    acc[p][6] = ffma2(wD.x, vp, acc[p][6]);
                    acc[p][7] = ffma2(wD.y, vp, acc[p][7]);
                }
            }
    }

    float* dst = g_h2 + ((b * 32 + half * 16) << 12) + (i << 6) + j;
    #pragma unroll
    for (int q = 0; q < 8; ++q) {
        float2 m0 = unpackff(acc[0][q]);
        float2 m1 = unpackff(acc[1][q]);
        float2 m2 = unpackff(acc[2][q]);
        float2 m3 = unpackff(acc[3][q]);
        float lo = fmaxf(fmaxf(m0.x, m1.x), fmaxf(m2.x, m3.x)) + sb[2 * q];
        float hi = fmaxf(fmaxf(m0.y, m1.y), fmaxf(m2.y, m3.y)) + sb[2 * q + 1];
        dst[(2 * q) << 12]     = lo;
        dst[(2 * q + 1) << 12] = hi;
    }
}

// ---------------------------------------------------------------------------
// K3: VQ via mma.sync tf32 3-pass split (hh + lh + hl).
// 512 threads/CTA (16 warps x m16 tokens = 256 tokens), 2 CTAs/SM.
// Codebook in 2 chunks of 256 codes; plane-interleaved frags in smem ->
// conflict-free LDS.128. argmax of f.c - 0.5||c||^2, lowest-index tie-break.
// ---------------------------------------------------------------------------
#define K3_CN   16384
#define K3_WS   (16384 + 512)
#define K3_SMEM ((16384 + 512 + 16) * 4)

__global__ void __launch_bounds__(512, 2) k3_vq(const float* __restrict__ cb,
                                                float* __restrict__ out) {
    extern __shared__ float sm3[];
    float* sF  = sm3;               // 16384 floats: one 256-code chunk
    float* sCn = sm3 + K3_CN;       // 512 half-norms
    float* sWs = sm3 + K3_WS;       // 16 warp partials

    int tid = threadIdx.x;
    int wid = tid >> 5, lane = tid & 31;
    int grp = lane >> 2, thr = lane & 3;
    int base = blockIdx.x * 256;           // global token base
    int b = base >> 12, ij0 = base & 4095;

    // ---- A fragments (16 tokens x K=32) from global into regs, hi/lo ----
    const float* fbase = g_h2 + (b << 17) + ij0 + wid * 16 + grp;
    uint32_t ahi[16], alo[16];
    #pragma unroll
    for (int ks = 0; ks < 4; ++ks) {
        int c0 = ks * 8 + thr, c1 = c0 + 4;
        float v00 = fbase[c0 << 12];
        float v10 = fbase[(c0 << 12) + 8];
        float v01 = fbase[c1 << 12];
        float v11 = fbase[(c1 << 12) + 8];
        uint32_t h;
        h = __float_as_uint(v00) & 0xFFFFE000u;
        ahi[ks * 4 + 0] = h; alo[ks * 4 + 0] = __float_as_uint(v00 - __uint_as_float(h));
        h = __float_as_uint(v10) & 0xFFFFE000u;
        ahi[ks * 4 + 1] = h; alo[ks * 4 + 1] = __float_as_uint(v10 - __uint_as_float(h));
        h = __float_as_uint(v01) & 0xFFFFE000u;
        ahi[ks * 4 + 2] = h; alo[ks * 4 + 2] = __float_as_uint(v01 - __uint_as_float(h));
        h = __float_as_uint(v11) & 0xFFFFE000u;
        ahi[ks * 4 + 3] = h; alo[ks * 4 + 3] = __float_as_uint(v11 - __uint_as_float(h));
    }
    if (tid < 512) sCn[tid] = g_cnh[tid];

    float bv0 = -1e30f, bv1 = -1e30f;
    int bk0 = 0, bk1 = 0;

    #pragma unroll 1
    for (int ch = 0; ch < 2; ++ch) {
        __syncthreads();   // previous chunk fully consumed
        {
            const float4* src = (const float4*)(g_cbF + ch * 16384);
            float4* dst = (float4*)sF;
            #pragma unroll
            for (int t = 0; t < 8; ++t)
                dst[tid + t * 512] = __ldg(src + tid + t * 512);
        }
        __syncthreads();

        #pragma unroll 2
        for (int nt = 0; nt < 32; ++nt) {
            const float4* fp = (const float4*)sF + (nt * 4) * 32 + lane;
            float c0 = 0.f, c1 = 0.f, c2 = 0.f, c3 = 0.f;
            // hi planes (b = hi): hh + lh passes
            {
                float4 h0 = fp[0], h1 = fp[32];
                uint32_t b0, b1;
                b0 = __float_as_uint(h0.x); b1 = __float_as_uint(h0.y);
                mma8(c0, c1, c2, c3, ahi[0], ahi[1], ahi[2], ahi[3], b0, b1);
                mma8(c0, c1, c2, c3, alo[0], alo[1], alo[2], alo[3], b0, b1);
                b0 = __float_as_uint(h0.z); b1 = __float_as_uint(h0.w);
                mma8(c0, c1, c2, c3, ahi[4], ahi[5], ahi[6], ahi[7], b0, b1);
                mma8(c0, c1, c2, c3, alo[4], alo[5], alo[6], alo[7], b0, b1);
                b0 = __float_as_uint(h1.x); b1 = __float_as_uint(h1.y);
                mma8(c0, c1, c2, c3, ahi[8], ahi[9], ahi[10], ahi[11], b0, b1);
                mma8(c0, c1, c2, c3, alo[8], alo[9], alo[10], alo[11], b0, b1);
                b0 = __float_as_uint(h1.z); b1 = __float_as_uint(h1.w);
                mma8(c0, c1, c2, c3, ahi[12], ahi[13], ahi[14], ahi[15], b0, b1);
                mma8(c0, c1, c2, c3, alo[12], alo[13], alo[14], alo[15], b0, b1);
            }
            // lo planes (b = lo): hl pass only (ll dropped)
            {
                float4 l0 = fp[64], l1 = fp[96];
                uint32_t b0, b1;
                b0 = __float_as_uint(l0.x); b1 = __float_as_uint(l0.y);
                mma8(c0, c1, c2, c3, ahi[0], ahi[1], ahi[2], ahi[3], b0, b1);
                b0 = __float_as_uint(l0.z); b1 = __float_as_uint(l0.w);
                mma8(c0, c1, c2, c3, ahi[4], ahi[5], ahi[6], ahi[7], b0, b1);
                b0 = __float_as_uint(l1.x); b1 = __float_as_uint(l1.y);
                mma8(c0, c1, c2, c3, ahi[8], ahi[9], ahi[10], ahi[11], b0, b1);
                b0 = __float_as_uint(l1.z); b1 = __float_as_uint(l1.w);
                mma8(c0, c1, c2, c3, ahi[12], ahi[13], ahi[14], ahi[15], b0, b1);
            }

            int col = ch * 256 + nt * 8 + 2 * thr;
            float cn0 = sCn[col], cn1 = sCn[col + 1];
            float v;
            v = c0 - cn0; if (v > bv0) { bv0 = v; bk0 = col; }
            v = c1 - cn1; if (v > bv0) { bv0 = v; bk0 = col + 1; }
            v = c2 - cn0; if (v > bv1) { bv1 = v; bk1 = col; }
            v = c3 - cn1; if (v > bv1) { bv1 = v; bk1 = col + 1; }
        }
    }

    // ---- reduce across the 4 lanes of each row-group (lowest k on ties) ----
    #pragma unroll
    for (int o = 1; o <= 2; o <<= 1) {
        float ov = __shfl_xor_sync(0xffffffffu, bv0, o);
        int   ok = __shfl_xor_sync(0xffffffffu, bk0, o);
        if (ov > bv0 || (ov == bv0 && ok < bk0)) { bv0 = ov; bk0 = ok; }
        ov = __shfl_xor_sync(0xffffffffu, bv1, o);
        ok = __shfl_xor_sync(0xffffffffu, bk1, o);
        if (ov > bv1 || (ov == bv1 && ok < bk1)) { bv1 = ov; bk1 = ok; }
    }

    int tokl = wid * 16 + grp;
    if (thr == 0) out[IDX_OFF + base + tokl] = (float)bk0;
    if (thr == 2) out[IDX_OFF + base + tokl + 8] = (float)bk1;

    // ---- gather + commit-loss partials: 4 lanes = 2 tokens x 2 halves ----
    int mytok = tokl + ((thr >> 1) << 3);
    int myk   = (thr < 2) ? bk0 : bk1;
    int cbase = (thr & 1) << 4;
    const float* cbr = cb + myk * 32 + cbase;
    const float* h2p = g_h2 + (b << 17) + (cbase << 12) + ij0 + mytok;
    float*       hqp = g_hq + (b << 17) + (cbase << 12) + ij0 + mytok;
    float part = 0.f;
    #pragma unroll
    for (int c = 0; c < 16; ++c) {
        float qv = __ldg(cbr + c);
        float fv = h2p[c << 12];
        float d = qv - fv;
        part = fmaf(d, d, part);
        hqp[c << 12] = qv;
    }

    // deterministic block reduction (16 warps)
    #pragma unroll
    for (int o = 16; o > 0; o >>= 1)
        part += __shfl_down_sync(0xffffffffu, part, o);
    if (lane == 0) sWs[wid] = part;
    __syncthreads();
    if (tid == 0) {
        float s = 0.f;
        #pragma unroll
        for (int q = 0; q < 16; ++q) s += sWs[q];
        g_part[blockIdx.x] = s;
    }
}

// ---------------------------------------------------------------------------
// K4: up2 + conv d1 (parity-folded) via tf32 mma GEMM + gelu.
// Block = (b, yq, x-half): output tile 16c x 8y x 64x. Warp = (parity p,
// row-half rh): acc 32 regs. A frags read from global (L1-hot); hq tile
// (rna-rounded tf32) staged in smem with stride 264 (thr*264+grp -> distinct
// banks). 2 CTAs/SM.
// ---------------------------------------------------------------------------
__global__ void __launch_bounds__(256, 2) k4_dec1(const float* __restrict__ bias) {
    __shared__ __align__(16) float sm4[9232];
    float* sHq = sm4;            // union: hq tile (32*264=8448) / out (9216)
    float* sB  = sm4 + 9216;     // 16 bias

    int tid = threadIdx.x;
    int wid = tid >> 5, lane = tid & 31;
    int grp = lane >> 2, thr = lane & 3;
    int bk = blockIdx.x;
    int b = bk >> 5, yq = (bk >> 1) & 15, bxh = bk & 1;
    int yi0 = yq * 4;

    if (tid < 16) sB[tid] = __ldg(bias + tid);
    // stage hq rows yi0-1..yi0+4 (6 rows), 40 tile cols, col0 = 32*bxh - 4
    if (tid < 192) {
        int ci = tid / 6, r6 = tid - ci * 6;
        float* dst = sHq + ci * 264 + r6 * 40;
        int r = yi0 - 1 + r6;
        float4 z = make_float4(0.f, 0.f, 0.f, 0.f);
        if ((unsigned)r < 64u) {
            const float* srow = g_hq + ((b * 32 + ci) << 12) + (r << 6);
            if (bxh == 0) {
                *(float4*)dst = z;                       // pos 0..3 (cols <0)
                #pragma unroll
                for (int q = 0; q < 9; ++q) {            // cols 0..35 -> pos 4..39
                    float4 v = *(const float4*)(srow + q * 4);
                    v.x = tf32r(v.x); v.y = tf32r(v.y);
                    v.z = tf32r(v.z); v.w = tf32r(v.w);
                    *(float4*)(dst + 4 + q * 4) = v;
                }
            } else {
                #pragma unroll
                for (int q = 0; q < 9; ++q) {            // cols 28..63 -> pos 0..35
                    float4 v = *(const float4*)(srow + 28 + q * 4);
                    v.x = tf32r(v.x); v.y = tf32r(v.y);
                    v.z = tf32r(v.z); v.w = tf32r(v.w);
                    *(float4*)(dst + q * 4) = v;
                }
                *(float4*)(dst + 36) = z;                // pos 36..39 (cols >=64)
            }
        } else {
            #pragma unroll
            for (int q = 0; q < 10; ++q) *(float4*)(dst + q * 4) = z;
        }
    }
    __syncthreads();

    int p = wid & 3, rh = wid >> 2;
    int py = p >> 1, px = p & 1;

    float acc[2][4][4];
    #pragma unroll
    for (int r = 0; r < 2; ++r)
        #pragma unroll
        for (int n = 0; n < 4; ++n)
            #pragma unroll
            for (int q = 0; q < 4; ++q) acc[r][n][q] = 0.f;

    #pragma unroll
    for (int kk = 0; kk < 16; ++kk) {
        float4 af = __ldg((const float4*)(g_W4 + ((p * 16 + kk) * 32 + lane) * 4));
        int uv = kk >> 2;
        int du = (uv >> 1) + py - 1, dv = (uv & 1) + px - 1;
        int ci0 = (kk & 3) * 8;
        const float* B0 = sHq + (ci0 + thr) * 264 + (1 + du + 2 * rh) * 40
                          + 4 + dv + grp;
        uint32_t a0 = __float_as_uint(af.x), a1 = __float_as_uint(af.y);
        uint32_t a2 = __float_as_uint(af.z), a3 = __float_as_uint(af.w);
        #pragma unroll
        for (int r = 0; r < 2; ++r)
            #pragma unroll
            for (int nt = 0; nt < 4; ++nt) {
                uint32_t b0 = __float_as_uint(B0[r * 40 + nt * 8]);
                uint32_t b1 = __float_as_uint(B0[r * 40 + nt * 8 + 1056]);
                mma8(acc[r][nt][0], acc[r][nt][1], acc[r][nt][2], acc[r][nt][3],
                     a0, a1, a2, a3, b0, b1);
            }
    }

    __syncthreads();   // all warps done reading sHq
    float bias_lo = sB[grp], bias_hi = sB[grp + 8];
    float* sOut = sHq;   // reuse union: [8y][16c][72]
    #pragma unroll
    for (int r = 0; r < 2; ++r) {
        int yl = 2 * (2 * rh + r) + py;
        #pragma unroll
        for (int nt = 0; nt < 4; ++nt) {
            int x = 16 * nt + 4 * thr + px;
            float* o = sOut + yl * 1152 + x;
            float v0 = acc[r][nt][0] + bias_lo;
            float v1 = acc[r][nt][1] + bias_lo;
            float v2 = acc[r][nt][2] + bias_hi;
            float v3 = acc[r][nt][3] + bias_hi;
            o[grp * 72]           = v0 * normcdff(v0);
            o[grp * 72 + 2]       = v1 * normcdff(v1);
            o[(grp + 8) * 72]     = v2 * normcdff(v2);
            o[(grp + 8) * 72 + 2] = v3 * normcdff(v3);
        }
    }
    __syncthreads();
    // coalesced writeout: 16c x 8y x 64x
    #pragma unroll
    for (int q = 0; q < 8; ++q) {
        int idx = q * 256 + tid;          // float4 id
        int x4 = idx & 15, ch = (idx >> 4) & 15, yy = idx >> 8;
        float4 val = *(const float4*)(sOut + yy * 1152 + ch * 72 + x4 * 4);
        *(float4*)(g_gg + ((b * 16 + ch) << 14) + (((yq << 3) + yy) << 7)
                   + (bxh << 6) + x4 * 4) = val;
    }
}

// ---------------------------------------------------------------------------
// K5: up2 + conv d2 (parity-folded) + clip. Thread = (b, y-pair i, x-quad j):
// 2x4 output pixels from a 3-row x 4-col gg window.
// ---------------------------------------------------------------------------
__global__ void __launch_bounds__(256) k5_dec2(const float* __restrict__ bias,
                                               float* __restrict__ out) {
    __shared__ __align__(16) float sW[256];
    int tid = threadIdx.x;
    sW[tid] = g_Wf2[tid];
    __syncthreads();

    int lin = blockIdx.x * 256 + tid;
    int j = lin & 63, i = (lin >> 6) & 127, b = lin >> 13;
    bool topok = i > 0, botok = i < 127;
    bool eok = j > 0, fok = j < 63;
    float bz = __ldg(bias);

    float a00 = 0.f, a01 = 0.f, a02 = 0.f, a03 = 0.f;
    float a10 = 0.f, a11 = 0.f, a12 = 0.f, a13 = 0.f;

    #pragma unroll 1
    for (int ci = 0; ci < 16; ++ci) {
        const float* base = g_gg + ((b * 16 + ci) << 14) + 2 * j;
        float eA = 0.f, fA = 0.f, eB = 0.f, fB = 0.f, eC = 0.f, fC = 0.f;
        float2 dA = make_float2(0.f, 0.f), dC = dA, dB;
        const float* rB = base + (i << 7);
        dB = *(const float2*)rB;
        if (eok) eB = rB[-1];
        if (fok) fB = rB[2];
        if (topok) {
            const float* rA = base + ((i - 1) << 7);
            dA = *(const float2*)rA;
            if (eok) eA = rA[-1];
            if (fok) fA = rA[2];
        }
        if (botok) {
            const float* rC = base + ((i + 1) << 7);
            dC = *(const float2*)rC;
            if (eok) eC = rC[-1];
            if (fok) fC = rC[2];
        }
        float4 w00 = *(const float4*)(sW + ci * 4);          // p=0 (ye, xe)
        float4 w01 = *(const float4*)(sW + 64 + ci * 4);     // p=1 (ye, xo)
        float4 w10 = *(const float4*)(sW + 128 + ci * 4);    // p=2 (yo, xe)
        float4 w11 = *(const float4*)(sW + 192 + ci * 4);    // p=3 (yo, xo)
        // y = 2i (top=row i-1, bot=row i)
        a00 = fmaf(w00.x, eA,   fmaf(w00.y, dA.x, fmaf(w00.z, eB,   fmaf(w00.w, dB.x, a00))));
        a01 = fmaf(w01.x, dA.x, fmaf(w01.y, dA.y, fmaf(w01.z, dB.x, fmaf(w01.w, dB.y, a01))));
        a02 = fmaf(w00.x, dA.x, fmaf(w00.y, dA.y, fmaf(w00.z, dB.x, fmaf(w00.w, dB.y, a02))));
        a03 = fmaf(w01.x, dA.y, fmaf(w01.y, fA,   fmaf(w01.z, dB.y, fmaf(w01.w, fB,   a03))));
        // y = 2i+1 (top=row i, bot=row i+1)
        a10 = fmaf(w10.x, eB,   fmaf(w10.y, dB.x, fmaf(w10.z, eC,   fmaf(w10.w, dC.x, a10))));
        a11 = fmaf(w11.x, dB.x, fmaf(w11.y, dB.y, fmaf(w11.z, dC.x, fmaf(w11.w, dC.y, a11))));
        a12 = fmaf(w10.x, dB.x, fmaf(w10.y, dB.y, fmaf(w10.z, dC.x, fmaf(w10.w, dC.y, a12))));
        a13 = fmaf(w11.x, dB.y, fmaf(w11.y, fB,   fmaf(w11.z, dC.y, fmaf(w11.w, fC,   a13))));
    }

    float* o = out + (b << 16) + ((2 * i) << 8) + 4 * j;
    float4 r0 = make_float4(fminf(fmaxf(a00 + bz, -1.f), 1.f),
                            fminf(fmaxf(a01 + bz, -1.f), 1.f),
                            fminf(fmaxf(a02 + bz, -1.f), 1.f),
                            fminf(fmaxf(a03 + bz, -1.f), 1.f));
    *(float4*)o = r0;
    float4 r1 = make_float4(fminf(fmaxf(a10 + bz, -1.f), 1.f),
                            fminf(fmaxf(a11 + bz, -1.f), 1.f),
                            fminf(fmaxf(a12 + bz, -1.f), 1.f),
                            fminf(fmaxf(a13 + bz, -1.f), 1.f));
    *(float4*)(o + 256) = r1;
}

// ---------------------------------------------------------------------------
// K6: final commit-loss reduction (deterministic tree over 512 partials).
// ---------------------------------------------------------------------------
__global__ void __launch_bounds__(256) k6_loss(float* __restrict__ out) {
    __shared__ float sm[256];
    int tid = threadIdx.x;
    sm[tid] = g_part[tid] + g_part[tid + 256];
    __syncthreads();
    #pragma unroll
    for (int o = 128; o > 0; o >>= 1) {
        if (tid < o) sm[tid] += sm[tid + o];
        __syncthreads();
    }
    if (tid == 0) out[LOSS_OFF] = sm[0] * (1.0f / 4194304.0f);
}

// ---------------------------------------------------------------------------
extern "C" void kernel_launch(void* const* d_in, const int* in_sizes, int n_in,
                              void* d_out, int out_size) {
    const float* x   = (const float*)d_in[0];
    const float* e1w = (const float*)d_in[1];
    const float* e1b = (const float*)d_in[2];
    const float* e2w = (const float*)d_in[3];
    const float* e2b = (const float*)d_in[4];
    const float* cb  = (const float*)d_in[5];
    const float* d1w = (const float*)d_in[6];
    const float* d1b = (const float*)d_in[7];
    const float* d2w = (const float*)d_in[8];
    const float* d2b = (const float*)d_in[9];
    float* out = (float*)d_out;

    static int s_attr_done = 0;
    if (!s_attr_done) {
        cudaFuncSetAttribute(k3_vq, cudaFuncAttributeMaxDynamicSharedMemorySize,
                             K3_SMEM);
        s_attr_done = 1;
    }

    k1_conv1<<<2211, 256>>>(x, e1w, e1b, cb, d1w, d2w);   // conv1 + setup tail
    k2_conv2<<<2048, 128>>>(e2w, e2b);
    k3_vq<<<512, 512, K3_SMEM>>>(cb, out);
    k4_dec1<<<1024, 256>>>(d1b);
    k5_dec2<<<1024, 256>>>(d2b, out);
    k6_loss<<<1, 256>>>(out);
}

// round 11
// speedup vs baseline: 1.6160x; 1.0372x over previous
#include <cuda_runtime.h>
#include <math.h>
#include <stdint.h>

// ---------------------------------------------------------------------------
// SimpleVQAutoEncoder on GB300 — FFMA2 encoder + mma.sync tf32 VQ + tf32 decoder
//
//   K1: [blocks <2048] conv1+maxpool2+gelu (FFMA2 pairs) -> g_h1
//       [blocks>=2048] setup: codebook norms/frags, decoder weight frags
//   K2: conv2(16->32,3x3,SAME) + maxpool2 (FFMA2)      -> g_h2 [32,32,64,64]
//   K3: VQ mma.sync tf32 3-pass split (hh+lh+hl)       -> g_hq, indices, g_part
//   K4: up2 + conv d1(32->16) folded, tf32 mma GEMM    -> g_gg [32,16,128,128]
//   K5: up2 + conv d2(16->1) folded + clip; last block reduces commit loss
//
// Output layout (float32): [ y (32*256*256) | indices (32*64*64) | loss (1) ]
// ---------------------------------------------------------------------------

#define IDX_OFF   2097152
#define LOSS_OFF  2228224

typedef unsigned long long u64;

__device__ __forceinline__ u64 ffma2(u64 a, u64 b, u64 c) {
    u64 d;
    asm("fma.rn.f32x2 %0, %1, %2, %3;" : "=l"(d) : "l"(a), "l"(b), "l"(c));
    return d;
}
__device__ __forceinline__ u64 packff(float lo, float hi) {
    u64 d;
    asm("mov.b64 %0, {%1, %2};" : "=l"(d) : "f"(lo), "f"(hi));
    return d;
}
__device__ __forceinline__ float2 unpackff(u64 v) {
    float lo, hi;
    asm("mov.b64 {%0, %1}, %2;" : "=f"(lo), "=f"(hi) : "l"(v));
    return make_float2(lo, hi);
}
__device__ __forceinline__ float tf32r(float v) {
    uint32_t t;
    asm("cvt.rna.tf32.f32 %0, %1;" : "=r"(t) : "f"(v));
    return __uint_as_float(t);
}
// cheap exact-to-ulp gelu (decoder only; encoder keeps normcdff)
__device__ __forceinline__ float gelu_fast(float v) {
    return 0.5f * v * (1.0f + erff(v * 0.70710678118654752f));
}

// m16n8k8 tf32 mma (sm_80+ PTX, valid at base sm_103 target)
__device__ __forceinline__ void mma8(float& c0, float& c1, float& c2, float& c3,
                                     uint32_t a0, uint32_t a1, uint32_t a2,
                                     uint32_t a3, uint32_t b0, uint32_t b1) {
    asm volatile(
        "mma.sync.aligned.m16n8k8.row.col.f32.tf32.tf32.f32 "
        "{%0,%1,%2,%3}, {%4,%5,%6,%7}, {%8,%9}, {%0,%1,%2,%3};"
        : "+f"(c0), "+f"(c1), "+f"(c2), "+f"(c3)
        : "r"(a0), "r"(a1), "r"(a2), "r"(a3), "r"(b0), "r"(b1));
}

// Intermediates (device globals: no allocation allowed)
__device__ float g_h1[32 * 16 * 128 * 128];   // 33.5 MB
__device__ float g_h2[32 * 32 * 64 * 64];     // 16.8 MB
__device__ float g_hq[32 * 32 * 64 * 64];     // 16.8 MB
__device__ float g_gg[32 * 16 * 128 * 128];   // 33.5 MB
__device__ float g_cnh[512];                  // 0.5*||codebook_k||^2
__device__ float g_cbF[64 * 32 * 16];         // packed VQ codebook frags
__device__ float g_W4[4 * 16 * 32 * 4];       // tf32 d1 weight A-fragments
__device__ float g_Wf2[4 * 16 * 4];           // folded d2 [p][ci][uv]
__device__ float g_part[512];                 // commit-loss partials

// ---------------------------------------------------------------------------
// Setup body (runs in K1's tail blocks).
// Nearest-up2 folding: output (y,x) reads a 2x2 hq patch; the 3x3 taps
// collapse per output parity (py,px) onto the 4 corners.
// ---------------------------------------------------------------------------
__device__ void setup_body(int t, const float* __restrict__ cb,
                           const float* __restrict__ d1w,
                           const float* __restrict__ d2w) {
    if (t < 8192) {
        int j = t & 3, lane = (t >> 2) & 31, kk = (t >> 7) & 15, p = t >> 11;
        int grp = lane >> 2, thr = lane & 3;
        int c = grp + (j & 1) * 8;
        int K = kk * 8 + thr + (j >> 1) * 4;
        int ci = K & 31, uv = K >> 5;
        int u = uv >> 1, v = uv & 1;
        int py = p >> 1, px = p & 1;
        float s = 0.f;
        #pragma unroll
        for (int dy = 0; dy < 3; ++dy) {
            int ug = (py == 0) ? (dy >= 1) : (dy >= 2);
            if (ug != u) continue;
            #pragma unroll
            for (int dx = 0; dx < 3; ++dx) {
                int vg = (px == 0) ? (dx >= 1) : (dx >= 2);
                if (vg != v) continue;
                s += d1w[((c * 32 + ci) * 3 + dy) * 3 + dx];
            }
        }
        g_W4[t] = tf32r(s);
    } else if (t < 8704) {
        int k = t - 8192;
        float s = 0.f;
        #pragma unroll
        for (int c = 0; c < 32; ++c) { float v = cb[k * 32 + c]; s = fmaf(v, v, s); }
        g_cnh[k] = 0.5f * s;
    } else if (t < 8960) {
        int e = t - 8704;
        int uv = e & 3, ci = (e >> 2) & 15, p = e >> 6;
        int py = p >> 1, px = p & 1, u = uv >> 1, v = uv & 1;
        float s = 0.f;
        #pragma unroll
        for (int dy = 0; dy < 3; ++dy) {
            int ug = (py == 0) ? (dy >= 1) : (dy >= 2);
            if (ug != u) continue;
            #pragma unroll
            for (int dx = 0; dx < 3; ++dx) {
                int vg = (px == 0) ? (dx >= 1) : (dx >= 2);
                if (vg != v) continue;
                s += d2w[ci * 9 + dy * 3 + dx];
            }
        }
        g_Wf2[(p * 16 + ci) * 4 + uv] = s;
    } else if (t < 41728) {
        int v = t - 8960;                 // 0..32767
        int e = v & 3, lane = (v >> 2) & 31, q = (v >> 7) & 3, nt = v >> 9;
        int grp = lane >> 2, thr = lane & 3;
        int j = q * 4 + e;
        int jj = j & 7;
        int ks = jj >> 1, half = jj & 1;
        int c = ks * 8 + thr + (half ? 4 : 0);
        float val = cb[(nt * 8 + grp) * 32 + c];
        float hi = __uint_as_float(__float_as_uint(val) & 0xFFFFE000u);
        g_cbF[v] = (j < 8) ? hi : (val - hi);
    }
}

// ---------------------------------------------------------------------------
// K1: conv1 + maxpool2 + exact gelu, FFMA2 channel pairs.
// Thread = (b, i, j) pooled pixel, 16 channels (8 pairs).
// Blocks >= 2048 run the setup body instead.
// ---------------------------------------------------------------------------
__global__ void __launch_bounds__(256) k1_conv1(const float* __restrict__ x,
                                                const float* __restrict__ w,
                                                const float* __restrict__ bias,
                                                const float* __restrict__ cb,
                                                const float* __restrict__ d1w,
                                                const float* __restrict__ d2w) {
    int tid = threadIdx.x;
    if (blockIdx.x >= 2048) {
        setup_body((blockIdx.x - 2048) * 256 + tid, cb, d1w, d2w);
        return;
    }

    __shared__ __align__(8) float2 sw2[72];   // [pair*9+tap] = (w[2p], w[2p+1])
    __shared__ float sb[16];
    if (tid < 72) {
        int pr = tid / 9, tap = tid - pr * 9;
        sw2[tid] = make_float2(__ldg(w + (2 * pr) * 9 + tap),
                               __ldg(w + (2 * pr + 1) * 9 + tap));
    }
    if (tid < 16) sb[tid] = __ldg(bias + tid);
    __syncthreads();

    int lin = blockIdx.x * 256 + tid;
    int j = lin & 127, i = (lin >> 7) & 127, b = lin >> 14;
    const float* xb = x + (b << 16);

    u64 xv[4][4];
    #pragma unroll
    for (int r = 0; r < 4; ++r) {
        int ry = 2 * i - 1 + r;
        bool rok = (unsigned)ry < 256u;
        #pragma unroll
        for (int cc = 0; cc < 4; ++cc) {
            int cx = 2 * j - 1 + cc;
            float v = (rok && (unsigned)cx < 256u) ? __ldg(xb + ry * 256 + cx) : 0.f;
            xv[r][cc] = packff(v, v);
        }
    }

    #pragma unroll
    for (int pr = 0; pr < 8; ++pr) {
        u64 wv[9];
        #pragma unroll
        for (int k = 0; k < 9; ++k) wv[k] = *(const u64*)(sw2 + pr * 9 + k);
        u64 acc[4];
        #pragma unroll
        for (int q = 0; q < 4; ++q) acc[q] = 0ull;
        #pragma unroll
        for (int dy = 0; dy < 3; ++dy)
            #pragma unroll
            for (int dx = 0; dx < 3; ++dx) {
                u64 wk = wv[dy * 3 + dx];
                acc[0] = ffma2(wk, xv[dy][dx], acc[0]);
                acc[1] = ffma2(wk, xv[dy][dx + 1], acc[1]);
                acc[2] = ffma2(wk, xv[dy + 1][dx], acc[2]);
                acc[3] = ffma2(wk, xv[dy + 1][dx + 1], acc[3]);
            }
        float2 m0 = unpackff(acc[0]);
        float2 m1 = unpackff(acc[1]);
        float2 m2 = unpackff(acc[2]);
        float2 m3 = unpackff(acc[3]);
        float lo = fmaxf(fmaxf(m0.x, m1.x), fmaxf(m2.x, m3.x)) + sb[2 * pr];
        float hi = fmaxf(fmaxf(m0.y, m1.y), fmaxf(m2.y, m3.y)) + sb[2 * pr + 1];
        g_h1[((b * 16 + 2 * pr) << 14) + (i << 7) + j]     = lo * normcdff(lo);
        g_h1[((b * 16 + 2 * pr + 1) << 14) + (i << 7) + j] = hi * normcdff(hi);
    }
}

// ---------------------------------------------------------------------------
// K2: conv2(16->32) + maxpool2, FFMA2 on channel pairs, prepacked patch.
// ---------------------------------------------------------------------------
__global__ void __launch_bounds__(128) k2_conv2(const float* __restrict__ w,
                                                const float* __restrict__ bias) {
    __shared__ __align__(16) float swt[2304];  // [ci*9+tap][16c]
    __shared__ float sb[16];
    int tid = threadIdx.x;
    int lin = blockIdx.x * 128 + tid;
    int j = lin & 63, i = (lin >> 6) & 63, half = (lin >> 12) & 1, b = lin >> 13;

    for (int t = tid; t < 2304; t += 128) {
        int ci = t / 144, r = t - ci * 144;
        int tap = r >> 4, c = r & 15;
        swt[t] = __ldg(w + (half * 16 + c) * 144 + ci * 9 + tap);
    }
    if (tid < 16) sb[tid] = __ldg(bias + half * 16 + tid);
    __syncthreads();

    int ry[4], cx[4];
    bool rok[4], cok[4];
    #pragma unroll
    for (int r = 0; r < 4; ++r) {
        ry[r] = 2 * i - 1 + r; rok[r] = (unsigned)ry[r] < 128u;
        cx[r] = 2 * j - 1 + r; cok[r] = (unsigned)cx[r] < 128u;
    }

    u64 acc[4][8];
    #pragma unroll
    for (int p = 0; p < 4; ++p)
        #pragma unroll
        for (int q = 0; q < 8; ++q) acc[p][q] = 0ull;

    #pragma unroll 1
    for (int ci = 0; ci < 16; ++ci) {
        const float* src = g_h1 + ((b * 16 + ci) << 14);
        u64 patch[4][4];
        #pragma unroll
        for (int r = 0; r < 4; ++r)
            #pragma unroll
            for (int cc = 0; cc < 4; ++cc) {
                float v = (rok[r] && cok[cc]) ? src[(ry[r] << 7) + cx[cc]] : 0.f;
                patch[r][cc] = packff(v, v);
            }

        #pragma unroll
        for (int dy = 0; dy < 3; ++dy)
            #pragma unroll
            for (int dx = 0; dx < 3; ++dx) {
                const ulonglong2* W2 =
                    (const ulonglong2*)(swt + (ci * 9 + dy * 3 + dx) * 16);
                ulonglong2 wA = W2[0], wB = W2[1], wC = W2[2], wD = W2[3];
                #pragma unroll
                for (int p = 0; p < 4; ++p) {
                    u64 vp = patch[(p >> 1) + dy][(p & 1) + dx];
                    acc[p][0] = ffma2(wA.x, vp, acc[p][0]);
                    acc[p][1] = ffma2(wA.y, vp, acc[p][1]);
                    acc[p][2] = ffma2(wB.x, vp, acc[p][2]);
                    acc[p][3] = ffma2(wB.y, vp, acc[p][3]);
                    acc[p][4] = ffma2(wC.x, vp, acc[p][4]);
                    acc[p][5] = ffma2(wC.y, vp, acc[p][5]);
                    acc[p][6] = ffma2(wD.x, vp, acc[p][6]);
                    acc[p][7] = ffma2(wD.y, vp, acc[p][7]);
                }
            }
    }

    float* dst = g_h2 + ((b * 32 + half * 16) << 12) + (i << 6) + j;
    #pragma unroll
    for (int q = 0; q < 8; ++q) {
        float2 m0 = unpackff(acc[0][q]);
        float2 m1 = unpackff(acc[1][q]);
        float2 m2 = unpackff(acc[2][q]);
        float2 m3 = unpackff(acc[3][q]);
        float lo = fmaxf(fmaxf(m0.x, m1.x), fmaxf(m2.x, m3.x)) + sb[2 * q];
        float hi = fmaxf(fmaxf(m0.y, m1.y), fmaxf(m2.y, m3.y)) + sb[2 * q + 1];
        dst[(2 * q) << 12]     = lo;
        dst[(2 * q + 1) << 12] = hi;
    }
}

// ---------------------------------------------------------------------------
// K3: VQ via mma.sync tf32 3-pass split (hh + lh + hl).
// 512 threads/CTA (16 warps x m16 tokens = 256 tokens), 2 CTAs/SM.
// Codebook in 2 chunks of 256 codes; plane-interleaved frags in smem ->
// conflict-free LDS.128. argmax of f.c - 0.5||c||^2, lowest-index tie-break.
// ---------------------------------------------------------------------------
#define K3_CN   16384
#define K3_WS   (16384 + 512)
#define K3_SMEM ((16384 + 512 + 16) * 4)

__global__ void __launch_bounds__(512, 2) k3_vq(const float* __restrict__ cb,
                                                float* __restrict__ out) {
    extern __shared__ float sm3[];
    float* sF  = sm3;               // 16384 floats: one 256-code chunk
    float* sCn = sm3 + K3_CN;       // 512 half-norms
    float* sWs = sm3 + K3_WS;       // 16 warp partials

    int tid = threadIdx.x;
    int wid = tid >> 5, lane = tid & 31;
    int grp = lane >> 2, thr = lane & 3;
    int base = blockIdx.x * 256;           // global token base
    int b = base >> 12, ij0 = base & 4095;

    // ---- A fragments (16 tokens x K=32) from global into regs, hi/lo ----
    const float* fbase = g_h2 + (b << 17) + ij0 + wid * 16 + grp;
    uint32_t ahi[16], alo[16];
    #pragma unroll
    for (int ks = 0; ks < 4; ++ks) {
        int c0 = ks * 8 + thr, c1 = c0 + 4;
        float v00 = fbase[c0 << 12];
        float v10 = fbase[(c0 << 12) + 8];
        float v01 = fbase[c1 << 12];
        float v11 = fbase[(c1 << 12) + 8];
        uint32_t h;
        h = __float_as_uint(v00) & 0xFFFFE000u;
        ahi[ks * 4 + 0] = h; alo[ks * 4 + 0] = __float_as_uint(v00 - __uint_as_float(h));
        h = __float_as_uint(v10) & 0xFFFFE000u;
        ahi[ks * 4 + 1] = h; alo[ks * 4 + 1] = __float_as_uint(v10 - __uint_as_float(h));
        h = __float_as_uint(v01) & 0xFFFFE000u;
        ahi[ks * 4 + 2] = h; alo[ks * 4 + 2] = __float_as_uint(v01 - __uint_as_float(h));
        h = __float_as_uint(v11) & 0xFFFFE000u;
        ahi[ks * 4 + 3] = h; alo[ks * 4 + 3] = __float_as_uint(v11 - __uint_as_float(h));
    }
    if (tid < 512) sCn[tid] = g_cnh[tid];

    float bv0 = -1e30f, bv1 = -1e30f;
    int bk0 = 0, bk1 = 0;

    #pragma unroll 1
    for (int ch = 0; ch < 2; ++ch) {
        __syncthreads();   // previous chunk fully consumed
        {
            const float4* src = (const float4*)(g_cbF + ch * 16384);
            float4* dst = (float4*)sF;
            #pragma unroll
            for (int t = 0; t < 8; ++t)
                dst[tid + t * 512] = __ldg(src + tid + t * 512);
        }
        __syncthreads();

        #pragma unroll 2
        for (int nt = 0; nt < 32; ++nt) {
            const float4* fp = (const float4*)sF + (nt * 4) * 32 + lane;
            float c0 = 0.f, c1 = 0.f, c2 = 0.f, c3 = 0.f;
            // hi planes (b = hi): hh + lh passes
            {
                float4 h0 = fp[0], h1 = fp[32];
                uint32_t b0, b1;
                b0 = __float_as_uint(h0.x); b1 = __float_as_uint(h0.y);
                mma8(c0, c1, c2, c3, ahi[0], ahi[1], ahi[2], ahi[3], b0, b1);
                mma8(c0, c1, c2, c3, alo[0], alo[1], alo[2], alo[3], b0, b1);
                b0 = __float_as_uint(h0.z); b1 = __float_as_uint(h0.w);
                mma8(c0, c1, c2, c3, ahi[4], ahi[5], ahi[6], ahi[7], b0, b1);
                mma8(c0, c1, c2, c3, alo[4], alo[5], alo[6], alo[7], b0, b1);
                b0 = __float_as_uint(h1.x); b1 = __float_as_uint(h1.y);
                mma8(c0, c1, c2, c3, ahi[8], ahi[9], ahi[10], ahi[11], b0, b1);
                mma8(c0, c1, c2, c3, alo[8], alo[9], alo[10], alo[11], b0, b1);
                b0 = __float_as_uint(h1.z); b1 = __float_as_uint(h1.w);
                mma8(c0, c1, c2, c3, ahi[12], ahi[13], ahi[14], ahi[15], b0, b1);
                mma8(c0, c1, c2, c3, alo[12], alo[13], alo[14], alo[15], b0, b1);
            }
            // lo planes (b = lo): hl pass only (ll dropped)
            {
                float4 l0 = fp[64], l1 = fp[96];
                uint32_t b0, b1;
                b0 = __float_as_uint(l0.x); b1 = __float_as_uint(l0.y);
                mma8(c0, c1, c2, c3, ahi[0], ahi[1], ahi[2], ahi[3], b0, b1);
                b0 = __float_as_uint(l0.z); b1 = __float_as_uint(l0.w);
                mma8(c0, c1, c2, c3, ahi[4], ahi[5], ahi[6], ahi[7], b0, b1);
                b0 = __float_as_uint(l1.x); b1 = __float_as_uint(l1.y);
                mma8(c0, c1, c2, c3, ahi[8], ahi[9], ahi[10], ahi[11], b0, b1);
                b0 = __float_as_uint(l1.z); b1 = __float_as_uint(l1.w);
                mma8(c0, c1, c2, c3, ahi[12], ahi[13], ahi[14], ahi[15], b0, b1);
            }

            int col = ch * 256 + nt * 8 + 2 * thr;
            float cn0 = sCn[col], cn1 = sCn[col + 1];
            float v;
            v = c0 - cn0; if (v > bv0) { bv0 = v; bk0 = col; }
            v = c1 - cn1; if (v > bv0) { bv0 = v; bk0 = col + 1; }
            v = c2 - cn0; if (v > bv1) { bv1 = v; bk1 = col; }
            v = c3 - cn1; if (v > bv1) { bv1 = v; bk1 = col + 1; }
        }
    }

    // ---- reduce across the 4 lanes of each row-group (lowest k on ties) ----
    #pragma unroll
    for (int o = 1; o <= 2; o <<= 1) {
        float ov = __shfl_xor_sync(0xffffffffu, bv0, o);
        int   ok = __shfl_xor_sync(0xffffffffu, bk0, o);
        if (ov > bv0 || (ov == bv0 && ok < bk0)) { bv0 = ov; bk0 = ok; }
        ov = __shfl_xor_sync(0xffffffffu, bv1, o);
        ok = __shfl_xor_sync(0xffffffffu, bk1, o);
        if (ov > bv1 || (ov == bv1 && ok < bk1)) { bv1 = ov; bk1 = ok; }
    }

    int tokl = wid * 16 + grp;
    if (thr == 0) out[IDX_OFF + base + tokl] = (float)bk0;
    if (thr == 2) out[IDX_OFF + base + tokl + 8] = (float)bk1;

    // ---- gather + commit-loss partials: 4 lanes = 2 tokens x 2 halves ----
    int mytok = tokl + ((thr >> 1) << 3);
    int myk   = (thr < 2) ? bk0 : bk1;
    int cbase = (thr & 1) << 4;
    const float* cbr = cb + myk * 32 + cbase;
    const float* h2p = g_h2 + (b << 17) + (cbase << 12) + ij0 + mytok;
    float*       hqp = g_hq + (b << 17) + (cbase << 12) + ij0 + mytok;
    float part = 0.f;
    #pragma unroll
    for (int c = 0; c < 16; ++c) {
        float qv = __ldg(cbr + c);
        float fv = h2p[c << 12];
        float d = qv - fv;
        part = fmaf(d, d, part);
        hqp[c << 12] = qv;
    }

    // deterministic block reduction (16 warps)
    #pragma unroll
    for (int o = 16; o > 0; o >>= 1)
        part += __shfl_down_sync(0xffffffffu, part, o);
    if (lane == 0) sWs[wid] = part;
    __syncthreads();
    if (tid == 0) {
        float s = 0.f;
        #pragma unroll
        for (int q = 0; q < 16; ++q) s += sWs[q];
        g_part[blockIdx.x] = s;
    }
}

// ---------------------------------------------------------------------------
// K4: up2 + conv d1 (parity-folded) via tf32 mma GEMM + gelu (erff-based).
// Block = (b, yq, x-half): output tile 16c x 8y x 64x. Warp = (parity p,
// row-half rh): acc 32 regs. A frags from global (L1-hot); hq tile
// (rna-rounded tf32) in smem stride 264 (conflict-free). 2 CTAs/SM.
// ---------------------------------------------------------------------------
__global__ void __launch_bounds__(256, 2) k4_dec1(const float* __restrict__ bias) {
    __shared__ __align__(16) float sm4[9232];
    float* sHq = sm4;            // union: hq tile (32*264=8448) / out (9216)
    float* sB  = sm4 + 9216;     // 16 bias

    int tid = threadIdx.x;
    int wid = tid >> 5, lane = tid & 31;
    int grp = lane >> 2, thr = lane & 3;
    int bk = blockIdx.x;
    int b = bk >> 5, yq = (bk >> 1) & 15, bxh = bk & 1;
    int yi0 = yq * 4;

    if (tid < 16) sB[tid] = __ldg(bias + tid);
    // stage hq rows yi0-1..yi0+4 (6 rows), 40 tile cols, col0 = 32*bxh - 4
    if (tid < 192) {
        int ci = tid / 6, r6 = tid - ci * 6;
        float* dst = sHq + ci * 264 + r6 * 40;
        int r = yi0 - 1 + r6;
        float4 z = make_float4(0.f, 0.f, 0.f, 0.f);
        if ((unsigned)r < 64u) {
            const float* srow = g_hq + ((b * 32 + ci) << 12) + (r << 6);
            if (bxh == 0) {
                *(float4*)dst = z;                       // pos 0..3 (cols <0)
                #pragma unroll
                for (int q = 0; q < 9; ++q) {            // cols 0..35 -> pos 4..39
                    float4 v = *(const float4*)(srow + q * 4);
                    v.x = tf32r(v.x); v.y = tf32r(v.y);
                    v.z = tf32r(v.z); v.w = tf32r(v.w);
                    *(float4*)(dst + 4 + q * 4) = v;
                }
            } else {
                #pragma unroll
                for (int q = 0; q < 9; ++q) {            // cols 28..63 -> pos 0..35
                    float4 v = *(const float4*)(srow + 28 + q * 4);
                    v.x = tf32r(v.x); v.y = tf32r(v.y);
                    v.z = tf32r(v.z); v.w = tf32r(v.w);
                    *(float4*)(dst + q * 4) = v;
                }
                *(float4*)(dst + 36) = z;                // pos 36..39 (cols >=64)
            }
        } else {
            #pragma unroll
            for (int q = 0; q < 10; ++q) *(float4*)(dst + q * 4) = z;
        }
    }
    __syncthreads();

    int p = wid & 3, rh = wid >> 2;
    int py = p >> 1, px = p & 1;

    float acc[2][4][4];
    #pragma unroll
    for (int r = 0; r < 2; ++r)
        #pragma unroll
        for (int n = 0; n < 4; ++n)
            #pragma unroll
            for (int q = 0; q < 4; ++q) acc[r][n][q] = 0.f;

    #pragma unroll
    for (int kk = 0; kk < 16; ++kk) {
        float4 af = __ldg((const float4*)(g_W4 + ((p * 16 + kk) * 32 + lane) * 4));
        int uv = kk >> 2;
        int du = (uv >> 1) + py - 1, dv = (uv & 1) + px - 1;
        int ci0 = (kk & 3) * 8;
        const float* B0 = sHq + (ci0 + thr) * 264 + (1 + du + 2 * rh) * 40
                          + 4 + dv + grp;
        uint32_t a0 = __float_as_uint(af.x), a1 = __float_as_uint(af.y);
        uint32_t a2 = __float_as_uint(af.z), a3 = __float_as_uint(af.w);
        #pragma unroll
        for (int r = 0; r < 2; ++r)
            #pragma unroll
            for (int nt = 0; nt < 4; ++nt) {
                uint32_t b0 = __float_as_uint(B0[r * 40 + nt * 8]);
                uint32_t b1 = __float_as_uint(B0[r * 40 + nt * 8 + 1056]);
                mma8(acc[r][nt][0], acc[r][nt][1], acc[r][nt][2], acc[r][nt][3],
                     a0, a1, a2, a3, b0, b1);
            }
    }

    __syncthreads();   // all warps done reading sHq
    float bias_lo = sB[grp], bias_hi = sB[grp + 8];
    float* sOut = sHq;   // reuse union: [8y][16c][72]
    #pragma unroll
    for (int r = 0; r < 2; ++r) {
        int yl = 2 * (2 * rh + r) + py;
        #pragma unroll
        for (int nt = 0; nt < 4; ++nt) {
            int x = 16 * nt + 4 * thr + px;
            float* o = sOut + yl * 1152 + x;
            float v0 = acc[r][nt][0] + bias_lo;
            float v1 = acc[r][nt][1] + bias_lo;
            float v2 = acc[r][nt][2] + bias_hi;
            float v3 = acc[r][nt][3] + bias_hi;
            o[grp * 72]           = gelu_fast(v0);
            o[grp * 72 + 2]       = gelu_fast(v1);
            o[(grp + 8) * 72]     = gelu_fast(v2);
            o[(grp + 8) * 72 + 2] = gelu_fast(v3);
        }
    }
    __syncthreads();
    // coalesced writeout: 16c x 8y x 64x
    #pragma unroll
    for (int q = 0; q < 8; ++q) {
        int idx = q * 256 + tid;          // float4 id
        int x4 = idx & 15, ch = (idx >> 4) & 15, yy = idx >> 8;
        float4 val = *(const float4*)(sOut + yy * 1152 + ch * 72 + x4 * 4);
        *(float4*)(g_gg + ((b * 16 + ch) << 14) + (((yq << 3) + yy) << 7)
                   + (bxh << 6) + x4 * 4) = val;
    }
}

// ---------------------------------------------------------------------------
// K5: up2 + conv d2 (parity-folded) + clip, 2x4 px/thread.
// Block 1024 reduces the commit-loss partials instead (k6 folded in).
// ---------------------------------------------------------------------------
__global__ void __launch_bounds__(256) k5_dec2(const float* __restrict__ bias,
                                               float* __restrict__ out) {
    int tid = threadIdx.x;

    if (blockIdx.x == 1024) {
        __shared__ float sm[256];
        sm[tid] = g_part[tid] + g_part[tid + 256];
        __syncthreads();
        #pragma unroll
        for (int o = 128; o > 0; o >>= 1) {
            if (tid < o) sm[tid] += sm[tid + o];
            __syncthreads();
        }
        if (tid == 0) out[LOSS_OFF] = sm[0] * (1.0f / 4194304.0f);
        return;
    }

    __shared__ __align__(16) float sW[256];
    sW[tid] = g_Wf2[tid];
    __syncthreads();

    int lin = blockIdx.x * 256 + tid;
    int j = lin & 63, i = (lin >> 6) & 127, b = lin >> 13;
    bool topok = i > 0, botok = i < 127;
    bool eok = j > 0, fok = j < 63;
    float bz = __ldg(bias);

    float a00 = 0.f, a01 = 0.f, a02 = 0.f, a03 = 0.f;
    float a10 = 0.f, a11 = 0.f, a12 = 0.f, a13 = 0.f;

    #pragma unroll 1
    for (int ci = 0; ci < 16; ++ci) {
        const float* base = g_gg + ((b * 16 + ci) << 14) + 2 * j;
        float eA = 0.f, fA = 0.f, eB = 0.f, fB = 0.f, eC = 0.f, fC = 0.f;
        float2 dA = make_float2(0.f, 0.f), dC = dA, dB;
        const float* rB = base + (i << 7);
        dB = *(const float2*)rB;
        if (eok) eB = rB[-1];
        if (fok) fB = rB[2];
        if (topok) {
            const float* rA = base + ((i - 1) << 7);
            dA = *(const float2*)rA;
            if (eok) eA = rA[-1];
            if (fok) fA = rA[2];
        }
        if (botok) {
            const float* rC = base + ((i + 1) << 7);
            dC = *(const float2*)rC;
            if (eok) eC = rC[-1];
            if (fok) fC = rC[2];
        }
        float4 w00 = *(const float4*)(sW + ci * 4);          // p=0 (ye, xe)
        float4 w01 = *(const float4*)(sW + 64 + ci * 4);     // p=1 (ye, xo)
        float4 w10 = *(const float4*)(sW + 128 + ci * 4);    // p=2 (yo, xe)
        float4 w11 = *(const float4*)(sW + 192 + ci * 4);    // p=3 (yo, xo)
        // y = 2i (top=row i-1, bot=row i)
        a00 = fmaf(w00.x, eA,   fmaf(w00.y, dA.x, fmaf(w00.z, eB,   fmaf(w00.w, dB.x, a00))));
        a01 = fmaf(w01.x, dA.x, fmaf(w01.y, dA.y, fmaf(w01.z, dB.x, fmaf(w01.w, dB.y, a01))));
        a02 = fmaf(w00.x, dA.x, fmaf(w00.y, dA.y, fmaf(w00.z, dB.x, fmaf(w00.w, dB.y, a02))));
        a03 = fmaf(w01.x, dA.y, fmaf(w01.y, fA,   fmaf(w01.z, dB.y, fmaf(w01.w, fB,   a03))));
        // y = 2i+1 (top=row i, bot=row i+1)
        a10 = fmaf(w10.x, eB,   fmaf(w10.y, dB.x, fmaf(w10.z, eC,   fmaf(w10.w, dC.x, a10))));
        a11 = fmaf(w11.x, dB.x, fmaf(w11.y, dB.y, fmaf(w11.z, dC.x, fmaf(w11.w, dC.y, a11))));
        a12 = fmaf(w10.x, dB.x, fmaf(w10.y, dB.y, fmaf(w10.z, dC.x, fmaf(w10.w, dC.y, a12))));
        a13 = fmaf(w11.x, dB.y, fmaf(w11.y, fB,   fmaf(w11.z, dC.y, fmaf(w11.w, fC,   a13))));
    }

    float* o = out + (b << 16) + ((2 * i) << 8) + 4 * j;
    float4 r0 = make_float4(fminf(fmaxf(a00 + bz, -1.f), 1.f),
                            fminf(fmaxf(a01 + bz, -1.f), 1.f),
                            fminf(fmaxf(a02 + bz, -1.f), 1.f),
                            fminf(fmaxf(a03 + bz, -1.f), 1.f));
    *(float4*)o = r0;
    float4 r1 = make_float4(fminf(fmaxf(a10 + bz, -1.f), 1.f),
                            fminf(fmaxf(a11 + bz, -1.f), 1.f),
                            fminf(fmaxf(a12 + bz, -1.f), 1.f),
                            fminf(fmaxf(a13 + bz, -1.f), 1.f));
    *(float4*)(o + 256) = r1;
}

// ---------------------------------------------------------------------------
extern "C" void kernel_launch(void* const* d_in, const int* in_sizes, int n_in,
                              void* d_out, int out_size) {
    const float* x   = (const float*)d_in[0];
    const float* e1w = (const float*)d_in[1];
    const float* e1b = (const float*)d_in[2];
    const float* e2w = (const float*)d_in[3];
    const float* e2b = (const float*)d_in[4];
    const float* cb  = (const float*)d_in[5];
    const float* d1w = (const float*)d_in[6];
    const float* d1b = (const float*)d_in[7];
    const float* d2w = (const float*)d_in[8];
    const float* d2b = (const float*)d_in[9];
    float* out = (float*)d_out;

    static int s_attr_done = 0;
    if (!s_attr_done) {
        cudaFuncSetAttribute(k3_vq, cudaFuncAttributeMaxDynamicSharedMemorySize,
                             K3_SMEM);
        s_attr_done = 1;
    }

    k1_conv1<<<2211, 256>>>(x, e1w, e1b, cb, d1w, d2w);   // conv1 + setup tail
    k2_conv2<<<2048, 128>>>(e2w, e2b);
    k3_vq<<<512, 512, K3_SMEM>>>(cb, out);
    k4_dec1<<<1024, 256>>>(d1b);
    k5_dec2<<<1025, 256>>>(d2b, out);                      // + loss reduce block
}

// round 12
// speedup vs baseline: 1.6481x; 1.0199x over previous
#include <cuda_runtime.h>
#include <math.h>
#include <stdint.h>

// ---------------------------------------------------------------------------
// SimpleVQAutoEncoder on GB300 — FFMA2 encoder + mma.sync tf32 VQ + tf32 decoder
//
//   K1: [blocks <2048] conv1+maxpool2+gelu (FFMA2 pairs) -> g_h1
//       [blocks>=2048] setup: codebook norms/frags, decoder weight frags
//   K2: conv2(16->32,3x3,SAME) + maxpool2 (FFMA2)      -> g_h2 [32,32,64,64]
//   K3: VQ mma.sync tf32 3-pass split, ILP-2 tile pairs-> g_hq, indices, g_part
//   K4: up2 + conv d1(32->16) folded, tf32 mma GEMM    -> g_gg [32,16,128,128]
//   K5: up2 + conv d2(16->1) folded + clip; last block reduces commit loss
//
// Output layout (float32): [ y (32*256*256) | indices (32*64*64) | loss (1) ]
// ---------------------------------------------------------------------------

#define IDX_OFF   2097152
#define LOSS_OFF  2228224

typedef unsigned long long u64;

__device__ __forceinline__ u64 ffma2(u64 a, u64 b, u64 c) {
    u64 d;
    asm("fma.rn.f32x2 %0, %1, %2, %3;" : "=l"(d) : "l"(a), "l"(b), "l"(c));
    return d;
}
__device__ __forceinline__ u64 packff(float lo, float hi) {
    u64 d;
    asm("mov.b64 %0, {%1, %2};" : "=l"(d) : "f"(lo), "f"(hi));
    return d;
}
__device__ __forceinline__ float2 unpackff(u64 v) {
    float lo, hi;
    asm("mov.b64 {%0, %1}, %2;" : "=f"(lo), "=f"(hi) : "l"(v));
    return make_float2(lo, hi);
}
__device__ __forceinline__ float tf32r(float v) {
    uint32_t t;
    asm("cvt.rna.tf32.f32 %0, %1;" : "=r"(t) : "f"(v));
    return __uint_as_float(t);
}
// cheap exact-to-ulp gelu (decoder only; encoder keeps normcdff)
__device__ __forceinline__ float gelu_fast(float v) {
    return 0.5f * v * (1.0f + erff(v * 0.70710678118654752f));
}

// m16n8k8 tf32 mma (sm_80+ PTX, valid at base sm_103 target)
__device__ __forceinline__ void mma8(float& c0, float& c1, float& c2, float& c3,
                                     uint32_t a0, uint32_t a1, uint32_t a2,
                                     uint32_t a3, uint32_t b0, uint32_t b1) {
    asm volatile(
        "mma.sync.aligned.m16n8k8.row.col.f32.tf32.tf32.f32 "
        "{%0,%1,%2,%3}, {%4,%5,%6,%7}, {%8,%9}, {%0,%1,%2,%3};"
        : "+f"(c0), "+f"(c1), "+f"(c2), "+f"(c3)
        : "r"(a0), "r"(a1), "r"(a2), "r"(a3), "r"(b0), "r"(b1));
}

// Intermediates (device globals: no allocation allowed)
__device__ float g_h1[32 * 16 * 128 * 128];   // 33.5 MB
__device__ float g_h2[32 * 32 * 64 * 64];     // 16.8 MB
__device__ float g_hq[32 * 32 * 64 * 64];     // 16.8 MB
__device__ float g_gg[32 * 16 * 128 * 128];   // 33.5 MB
__device__ float g_cnh[512];                  // 0.5*||codebook_k||^2
__device__ float g_cbF[64 * 32 * 16];         // packed VQ codebook frags
__device__ float g_W4[4 * 16 * 32 * 4];       // tf32 d1 weight A-fragments
__device__ float g_Wf2[4 * 16 * 4];           // folded d2 [p][ci][uv]
__device__ float g_part[1024];                // commit-loss partials

// ---------------------------------------------------------------------------
// Setup body (runs in K1's tail blocks).
// Nearest-up2 folding: output (y,x) reads a 2x2 hq patch; the 3x3 taps
// collapse per output parity (py,px) onto the 4 corners.
// ---------------------------------------------------------------------------
__device__ void setup_body(int t, const float* __restrict__ cb,
                           const float* __restrict__ d1w,
                           const float* __restrict__ d2w) {
    if (t < 8192) {
        int j = t & 3, lane = (t >> 2) & 31, kk = (t >> 7) & 15, p = t >> 11;
        int grp = lane >> 2, thr = lane & 3;
        int c = grp + (j & 1) * 8;
        int K = kk * 8 + thr + (j >> 1) * 4;
        int ci = K & 31, uv = K >> 5;
        int u = uv >> 1, v = uv & 1;
        int py = p >> 1, px = p & 1;
        float s = 0.f;
        #pragma unroll
        for (int dy = 0; dy < 3; ++dy) {
            int ug = (py == 0) ? (dy >= 1) : (dy >= 2);
            if (ug != u) continue;
            #pragma unroll
            for (int dx = 0; dx < 3; ++dx) {
                int vg = (px == 0) ? (dx >= 1) : (dx >= 2);
                if (vg != v) continue;
                s += d1w[((c * 32 + ci) * 3 + dy) * 3 + dx];
            }
        }
        g_W4[t] = tf32r(s);
    } else if (t < 8704) {
        int k = t - 8192;
        float s = 0.f;
        #pragma unroll
        for (int c = 0; c < 32; ++c) { float v = cb[k * 32 + c]; s = fmaf(v, v, s); }
        g_cnh[k] = 0.5f * s;
    } else if (t < 8960) {
        int e = t - 8704;
        int uv = e & 3, ci = (e >> 2) & 15, p = e >> 6;
        int py = p >> 1, px = p & 1, u = uv >> 1, v = uv & 1;
        float s = 0.f;
        #pragma unroll
        for (int dy = 0; dy < 3; ++dy) {
            int ug = (py == 0) ? (dy >= 1) : (dy >= 2);
            if (ug != u) continue;
            #pragma unroll
            for (int dx = 0; dx < 3; ++dx) {
                int vg = (px == 0) ? (dx >= 1) : (dx >= 2);
                if (vg != v) continue;
                s += d2w[ci * 9 + dy * 3 + dx];
            }
        }
        g_Wf2[(p * 16 + ci) * 4 + uv] = s;
    } else if (t < 41728) {
        int v = t - 8960;                 // 0..32767
        int e = v & 3, lane = (v >> 2) & 31, q = (v >> 7) & 3, nt = v >> 9;
        int grp = lane >> 2, thr = lane & 3;
        int j = q * 4 + e;
        int jj = j & 7;
        int ks = jj >> 1, half = jj & 1;
        int c = ks * 8 + thr + (half ? 4 : 0);
        float val = cb[(nt * 8 + grp) * 32 + c];
        float hi = __uint_as_float(__float_as_uint(val) & 0xFFFFE000u);
        g_cbF[v] = (j < 8) ? hi : (val - hi);
    }
}

// ---------------------------------------------------------------------------
// K1: conv1 + maxpool2 + exact gelu, FFMA2 channel pairs.
// Thread = (b, i, j) pooled pixel, 16 channels (8 pairs).
// Blocks >= 2048 run the setup body instead.
// ---------------------------------------------------------------------------
__global__ void __launch_bounds__(256) k1_conv1(const float* __restrict__ x,
                                                const float* __restrict__ w,
                                                const float* __restrict__ bias,
                                                const float* __restrict__ cb,
                                                const float* __restrict__ d1w,
                                                const float* __restrict__ d2w) {
    int tid = threadIdx.x;
    if (blockIdx.x >= 2048) {
        setup_body((blockIdx.x - 2048) * 256 + tid, cb, d1w, d2w);
        return;
    }

    __shared__ __align__(8) float2 sw2[72];   // [pair*9+tap] = (w[2p], w[2p+1])
    __shared__ float sb[16];
    if (tid < 72) {
        int pr = tid / 9, tap = tid - pr * 9;
        sw2[tid] = make_float2(__ldg(w + (2 * pr) * 9 + tap),
                               __ldg(w + (2 * pr + 1) * 9 + tap));
    }
    if (tid < 16) sb[tid] = __ldg(bias + tid);
    __syncthreads();

    int lin = blockIdx.x * 256 + tid;
    int j = lin & 127, i = (lin >> 7) & 127, b = lin >> 14;
    const float* xb = x + (b << 16);

    u64 xv[4][4];
    #pragma unroll
    for (int r = 0; r < 4; ++r) {
        int ry = 2 * i - 1 + r;
        bool rok = (unsigned)ry < 256u;
        #pragma unroll
        for (int cc = 0; cc < 4; ++cc) {
            int cx = 2 * j - 1 + cc;
            float v = (rok && (unsigned)cx < 256u) ? __ldg(xb + ry * 256 + cx) : 0.f;
            xv[r][cc] = packff(v, v);
        }
    }

    #pragma unroll
    for (int pr = 0; pr < 8; ++pr) {
        u64 wv[9];
        #pragma unroll
        for (int k = 0; k < 9; ++k) wv[k] = *(const u64*)(sw2 + pr * 9 + k);
        u64 acc[4];
        #pragma unroll
        for (int q = 0; q < 4; ++q) acc[q] = 0ull;
        #pragma unroll
        for (int dy = 0; dy < 3; ++dy)
            #pragma unroll
            for (int dx = 0; dx < 3; ++dx) {
                u64 wk = wv[dy * 3 + dx];
                acc[0] = ffma2(wk, xv[dy][dx], acc[0]);
                acc[1] = ffma2(wk, xv[dy][dx + 1], acc[1]);
                acc[2] = ffma2(wk, xv[dy + 1][dx], acc[2]);
                acc[3] = ffma2(wk, xv[dy + 1][dx + 1], acc[3]);
            }
        float2 m0 = unpackff(acc[0]);
        float2 m1 = unpackff(acc[1]);
        float2 m2 = unpackff(acc[2]);
        float2 m3 = unpackff(acc[3]);
        float lo = fmaxf(fmaxf(m0.x, m1.x), fmaxf(m2.x, m3.x)) + sb[2 * pr];
        float hi = fmaxf(fmaxf(m0.y, m1.y), fmaxf(m2.y, m3.y)) + sb[2 * pr + 1];
        g_h1[((b * 16 + 2 * pr) << 14) + (i << 7) + j]     = lo * normcdff(lo);
        g_h1[((b * 16 + 2 * pr + 1) << 14) + (i << 7) + j] = hi * normcdff(hi);
    }
}

// ---------------------------------------------------------------------------
// K2: conv2(16->32) + maxpool2, FFMA2 on channel pairs, prepacked patch.
// ---------------------------------------------------------------------------
__global__ void __launch_bounds__(128) k2_conv2(const float* __restrict__ w,
                                                const float* __restrict__ bias) {
    __shared__ __align__(16) float swt[2304];  // [ci*9+tap][16c]
    __shared__ float sb[16];
    int tid = threadIdx.x;
    int lin = blockIdx.x * 128 + tid;
    int j = lin & 63, i = (lin >> 6) & 63, half = (lin >> 12) & 1, b = lin >> 13;

    for (int t = tid; t < 2304; t += 128) {
        int ci = t / 144, r = t - ci * 144;
        int tap = r >> 4, c = r & 15;
        swt[t] = __ldg(w + (half * 16 + c) * 144 + ci * 9 + tap);
    }
    if (tid < 16) sb[tid] = __ldg(bias + half * 16 + tid);
    __syncthreads();

    int ry[4], cx[4];
    bool rok[4], cok[4];
    #pragma unroll
    for (int r = 0; r < 4; ++r) {
        ry[r] = 2 * i - 1 + r; rok[r] = (unsigned)ry[r] < 128u;
        cx[r] = 2 * j - 1 + r; cok[r] = (unsigned)cx[r] < 128u;
    }

    u64 acc[4][8];
    #pragma unroll
    for (int p = 0; p < 4; ++p)
        #pragma unroll
        for (int q = 0; q < 8; ++q) acc[p][q] = 0ull;

    #pragma unroll 1
    for (int ci = 0; ci < 16; ++ci) {
        const float* src = g_h1 + ((b * 16 + ci) << 14);
        u64 patch[4][4];
        #pragma unroll
        for (int r = 0; r < 4; ++r)
            #pragma unroll
            for (int cc = 0; cc < 4; ++cc) {
                float v = (rok[r] && cok[cc]) ? src[(ry[r] << 7) + cx[cc]] : 0.f;
                patch[r][cc] = packff(v, v);
            }

        #pragma unroll
        for (int dy = 0; dy < 3; ++dy)
            #pragma unroll
            for (int dx = 0; dx < 3; ++dx) {
                const ulonglong2* W2 =
                    (const ulonglong2*)(swt + (ci * 9 + dy * 3 + dx) * 16);
                ulonglong2 wA = W2[0], wB = W2[1], wC = W2[2], wD = W2[3];
                #pragma unroll
                for (int p = 0; p < 4; ++p) {
                    u64 vp = patch[(p >> 1) + dy][(p & 1) + dx];
                    acc[p][0] = ffma2(wA.x, vp, acc[p][0]);
                    acc[p][1] = ffma2(wA.y, vp, acc[p][1]);
                    acc[p][2] = ffma2(wB.x, vp, acc[p][2]);
                    acc[p][3] = ffma2(wB.y, vp, acc[p][3]);
                    acc[p][4] = ffma2(wC.x, vp, acc[p][4]);
                    acc[p][5] = ffma2(wC.y, vp, acc[p][5]);
                    acc[p][6] = ffma2(wD.x, vp, acc[p][6]);
                    acc[p][7] = ffma2(wD.y, vp, acc[p][7]);
                }
            }
    }

    float* dst = g_h2 + ((b * 32 + half * 16) << 12) + (i << 6) + j;
    #pragma unroll
    for (int q = 0; q < 8; ++q) {
        float2 m0 = unpackff(acc[0][q]);
        float2 m1 = unpackff(acc[1][q]);
        float2 m2 = unpackff(acc[2][q]);
        float2 m3 = unpackff(acc[3][q]);
        float lo = fmaxf(fmaxf(m0.x, m1.x), fmaxf(m2.x, m3.x)) + sb[2 * q];
        float hi = fmaxf(fmaxf(m0.y, m1.y), fmaxf(m2.y, m3.y)) + sb[2 * q + 1];
        dst[(2 * q) << 12]     = lo;
        dst[(2 * q + 1) << 12] = hi;
    }
}

// ---------------------------------------------------------------------------
// K3: VQ via mma.sync tf32 3-pass split (hh + lh + hl), ILP-2 tile pairing:
// tiles nt and nt+1 accumulate into independent register sets with
// interleaved MMA issue (per-tile order unchanged -> bit-identical indices).
// 256 threads/CTA (8 warps x m16 tokens = 128 tokens), 3 CTAs/SM.
// argmax of f.c - 0.5||c||^2, lowest-index tie-break.
// ---------------------------------------------------------------------------
#define K3_CN   16384
#define K3_WS   (16384 + 512)
#define K3_SMEM ((16384 + 512 + 16) * 4)

__global__ void __launch_bounds__(256, 3) k3_vq(const float* __restrict__ cb,
                                                float* __restrict__ out) {
    extern __shared__ float sm3[];
    float* sF  = sm3;               // 16384 floats: one 256-code chunk
    float* sCn = sm3 + K3_CN;       // 512 half-norms
    float* sWs = sm3 + K3_WS;       // 8 warp partials

    int tid = threadIdx.x;
    int wid = tid >> 5, lane = tid & 31;
    int grp = lane >> 2, thr = lane & 3;
    int base = blockIdx.x * 128;           // global token base
    int b = base >> 12, ij0 = base & 4095;

    // ---- A fragments (16 tokens x K=32) from global into regs, hi/lo ----
    const float* fbase = g_h2 + (b << 17) + ij0 + wid * 16 + grp;
    uint32_t ahi[16], alo[16];
    #pragma unroll
    for (int ks = 0; ks < 4; ++ks) {
        int c0 = ks * 8 + thr, c1 = c0 + 4;
        float v00 = fbase[c0 << 12];
        float v10 = fbase[(c0 << 12) + 8];
        float v01 = fbase[c1 << 12];
        float v11 = fbase[(c1 << 12) + 8];
        uint32_t h;
        h = __float_as_uint(v00) & 0xFFFFE000u;
        ahi[ks * 4 + 0] = h; alo[ks * 4 + 0] = __float_as_uint(v00 - __uint_as_float(h));
        h = __float_as_uint(v10) & 0xFFFFE000u;
        ahi[ks * 4 + 1] = h; alo[ks * 4 + 1] = __float_as_uint(v10 - __uint_as_float(h));
        h = __float_as_uint(v01) & 0xFFFFE000u;
        ahi[ks * 4 + 2] = h; alo[ks * 4 + 2] = __float_as_uint(v01 - __uint_as_float(h));
        h = __float_as_uint(v11) & 0xFFFFE000u;
        ahi[ks * 4 + 3] = h; alo[ks * 4 + 3] = __float_as_uint(v11 - __uint_as_float(h));
    }
    sCn[tid] = g_cnh[tid];
    sCn[tid + 256] = g_cnh[tid + 256];

    float bv0 = -1e30f, bv1 = -1e30f;
    int bk0 = 0, bk1 = 0;

    #pragma unroll 1
    for (int ch = 0; ch < 2; ++ch) {
        __syncthreads();   // previous chunk fully consumed
        {
            const float4* src = (const float4*)(g_cbF + ch * 16384);
            float4* dst = (float4*)sF;
            #pragma unroll
            for (int t = 0; t < 16; ++t)
                dst[tid + t * 256] = __ldg(src + tid + t * 256);
        }
        __syncthreads();

        #pragma unroll 1
        for (int nt = 0; nt < 32; nt += 2) {
            const float4* fpA = (const float4*)sF + (nt * 4) * 32 + lane;
            const float4* fpB = fpA + 128;
            float cA0 = 0.f, cA1 = 0.f, cA2 = 0.f, cA3 = 0.f;
            float cB0 = 0.f, cB1 = 0.f, cB2 = 0.f, cB3 = 0.f;
            // hi planes (b = hi): hh + lh, ks0..3, tiles interleaved
            {
                float4 hA = fpA[0], hB = fpB[0];
                mma8(cA0,cA1,cA2,cA3, ahi[0],ahi[1],ahi[2],ahi[3],
                     __float_as_uint(hA.x), __float_as_uint(hA.y));
                mma8(cB0,cB1,cB2,cB3, ahi[0],ahi[1],ahi[2],ahi[3],
                     __float_as_uint(hB.x), __float_as_uint(hB.y));
                mma8(cA0,cA1,cA2,cA3, alo[0],alo[1],alo[2],alo[3],
                     __float_as_uint(hA.x), __float_as_uint(hA.y));
                mma8(cB0,cB1,cB2,cB3, alo[0],alo[1],alo[2],alo[3],
                     __float_as_uint(hB.x), __float_as_uint(hB.y));
                mma8(cA0,cA1,cA2,cA3, ahi[4],ahi[5],ahi[6],ahi[7],
                     __float_as_uint(hA.z), __float_as_uint(hA.w));
                mma8(cB0,cB1,cB2,cB3, ahi[4],ahi[5],ahi[6],ahi[7],
                     __float_as_uint(hB.z), __float_as_uint(hB.w));
                mma8(cA0,cA1,cA2,cA3, alo[4],alo[5],alo[6],alo[7],
                     __float_as_uint(hA.z), __float_as_uint(hA.w));
                mma8(cB0,cB1,cB2,cB3, alo[4],alo[5],alo[6],alo[7],
                     __float_as_uint(hB.z), __float_as_uint(hB.w));
            }
            {
                float4 hA = fpA[32], hB = fpB[32];
                mma8(cA0,cA1,cA2,cA3, ahi[8],ahi[9],ahi[10],ahi[11],
                     __float_as_uint(hA.x), __float_as_uint(hA.y));
                mma8(cB0,cB1,cB2,cB3, ahi[8],ahi[9],ahi[10],ahi[11],
                     __float_as_uint(hB.x), __float_as_uint(hB.y));
                mma8(cA0,cA1,cA2,cA3, alo[8],alo[9],alo[10],alo[11],
                     __float_as_uint(hA.x), __float_as_uint(hA.y));
                mma8(cB0,cB1,cB2,cB3, alo[8],alo[9],alo[10],alo[11],
                     __float_as_uint(hB.x), __float_as_uint(hB.y));
                mma8(cA0,cA1,cA2,cA3, ahi[12],ahi[13],ahi[14],ahi[15],
                     __float_as_uint(hA.z), __float_as_uint(hA.w));
                mma8(cB0,cB1,cB2,cB3, ahi[12],ahi[13],ahi[14],ahi[15],
                     __float_as_uint(hB.z), __float_as_uint(hB.w));
                mma8(cA0,cA1,cA2,cA3, alo[12],alo[13],alo[14],alo[15],
                     __float_as_uint(hA.z), __float_as_uint(hA.w));
                mma8(cB0,cB1,cB2,cB3, alo[12],alo[13],alo[14],alo[15],
                     __float_as_uint(hB.z), __float_as_uint(hB.w));
            }
            // lo planes (b = lo): hl only, ks0..3
            {
                float4 lA = fpA[64], lB = fpB[64];
                mma8(cA0,cA1,cA2,cA3, ahi[0],ahi[1],ahi[2],ahi[3],
                     __float_as_uint(lA.x), __float_as_uint(lA.y));
                mma8(cB0,cB1,cB2,cB3, ahi[0],ahi[1],ahi[2],ahi[3],
                     __float_as_uint(lB.x), __float_as_uint(lB.y));
                mma8(cA0,cA1,cA2,cA3, ahi[4],ahi[5],ahi[6],ahi[7],
                     __float_as_uint(lA.z), __float_as_uint(lA.w));
                mma8(cB0,cB1,cB2,cB3, ahi[4],ahi[5],ahi[6],ahi[7],
                     __float_as_uint(lB.z), __float_as_uint(lB.w));
            }
            {
                float4 lA = fpA[96], lB = fpB[96];
                mma8(cA0,cA1,cA2,cA3, ahi[8],ahi[9],ahi[10],ahi[11],
                     __float_as_uint(lA.x), __float_as_uint(lA.y));
                mma8(cB0,cB1,cB2,cB3, ahi[8],ahi[9],ahi[10],ahi[11],
                     __float_as_uint(lB.x), __float_as_uint(lB.y));
                mma8(cA0,cA1,cA2,cA3, ahi[12],ahi[13],ahi[14],ahi[15],
                     __float_as_uint(lA.z), __float_as_uint(lA.w));
                mma8(cB0,cB1,cB2,cB3, ahi[12],ahi[13],ahi[14],ahi[15],
                     __float_as_uint(lB.z), __float_as_uint(lB.w));
            }

            // epilogue tile A then tile B (ascending columns preserved)
            int colA = ch * 256 + nt * 8 + 2 * thr;
            float cn0 = sCn[colA], cn1 = sCn[colA + 1];
            float v;
            v = cA0 - cn0; if (v > bv0) { bv0 = v; bk0 = colA; }
            v = cA1 - cn1; if (v > bv0) { bv0 = v; bk0 = colA + 1; }
            v = cA2 - cn0; if (v > bv1) { bv1 = v; bk1 = colA; }
            v = cA3 - cn1; if (v > bv1) { bv1 = v; bk1 = colA + 1; }
            int colB = colA + 8;
            float cn2 = sCn[colB], cn3 = sCn[colB + 1];
            v = cB0 - cn2; if (v > bv0) { bv0 = v; bk0 = colB; }
            v = cB1 - cn3; if (v > bv0) { bv0 = v; bk0 = colB + 1; }
            v = cB2 - cn2; if (v > bv1) { bv1 = v; bk1 = colB; }
            v = cB3 - cn3; if (v > bv1) { bv1 = v; bk1 = colB + 1; }
        }
    }

    // ---- reduce across the 4 lanes of each row-group (lowest k on ties) ----
    #pragma unroll
    for (int o = 1; o <= 2; o <<= 1) {
        float ov = __shfl_xor_sync(0xffffffffu, bv0, o);
        int   ok = __shfl_xor_sync(0xffffffffu, bk0, o);
        if (ov > bv0 || (ov == bv0 && ok < bk0)) { bv0 = ov; bk0 = ok; }
        ov = __shfl_xor_sync(0xffffffffu, bv1, o);
        ok = __shfl_xor_sync(0xffffffffu, bk1, o);
        if (ov > bv1 || (ov == bv1 && ok < bk1)) { bv1 = ov; bk1 = ok; }
    }

    int tokl = wid * 16 + grp;
    if (thr == 0) out[IDX_OFF + base + tokl] = (float)bk0;
    if (thr == 2) out[IDX_OFF + base + tokl + 8] = (float)bk1;

    // ---- gather + commit-loss partials: 4 lanes = 2 tokens x 2 halves ----
    int mytok = tokl + ((thr >> 1) << 3);
    int myk   = (thr < 2) ? bk0 : bk1;
    int cbase = (thr & 1) << 4;
    const float* cbr = cb + myk * 32 + cbase;
    const float* h2p = g_h2 + (b << 17) + (cbase << 12) + ij0 + mytok;
    float*       hqp = g_hq + (b << 17) + (cbase << 12) + ij0 + mytok;
    float part = 0.f;
    #pragma unroll
    for (int c = 0; c < 16; ++c) {
        float qv = __ldg(cbr + c);
        float fv = h2p[c << 12];
        float d = qv - fv;
        part = fmaf(d, d, part);
        hqp[c << 12] = qv;
    }

    // deterministic block reduction (8 warps)
    #pragma unroll
    for (int o = 16; o > 0; o >>= 1)
        part += __shfl_down_sync(0xffffffffu, part, o);
    if (lane == 0) sWs[wid] = part;
    __syncthreads();
    if (tid == 0) {
        float s = 0.f;
        #pragma unroll
        for (int q = 0; q < 8; ++q) s += sWs[q];
        g_part[blockIdx.x] = s;
    }
}

// ---------------------------------------------------------------------------
// K4: up2 + conv d1 (parity-folded) via tf32 mma GEMM + gelu (erff-based).
// Block = (b, yq, x-half): output tile 16c x 8y x 64x. Warp = (parity p,
// row-half rh): acc 32 regs. A frags from global (L1-hot); hq tile
// (rna-rounded tf32) in smem stride 264 (conflict-free). 2 CTAs/SM.
// ---------------------------------------------------------------------------
__global__ void __launch_bounds__(256, 2) k4_dec1(const float* __restrict__ bias) {
    __shared__ __align__(16) float sm4[9232];
    float* sHq = sm4;            // union: hq tile (32*264=8448) / out (9216)
    float* sB  = sm4 + 9216;     // 16 bias

    int tid = threadIdx.x;
    int wid = tid >> 5, lane = tid & 31;
    int grp = lane >> 2, thr = lane & 3;
    int bk = blockIdx.x;
    int b = bk >> 5, yq = (bk >> 1) & 15, bxh = bk & 1;
    int yi0 = yq * 4;

    if (tid < 16) sB[tid] = __ldg(bias + tid);
    // stage hq rows yi0-1..yi0+4 (6 rows), 40 tile cols, col0 = 32*bxh - 4
    if (tid < 192) {
        int ci = tid / 6, r6 = tid - ci * 6;
        float* dst = sHq + ci * 264 + r6 * 40;
        int r = yi0 - 1 + r6;
        float4 z = make_float4(0.f, 0.f, 0.f, 0.f);
        if ((unsigned)r < 64u) {
            const float* srow = g_hq + ((b * 32 + ci) << 12) + (r << 6);
            if (bxh == 0) {
                *(float4*)dst = z;                       // pos 0..3 (cols <0)
                #pragma unroll
                for (int q = 0; q < 9; ++q) {            // cols 0..35 -> pos 4..39
                    float4 v = *(const float4*)(srow + q * 4);
                    v.x = tf32r(v.x); v.y = tf32r(v.y);
                    v.z = tf32r(v.z); v.w = tf32r(v.w);
                    *(float4*)(dst + 4 + q * 4) = v;
                }
            } else {
                #pragma unroll
                for (int q = 0; q < 9; ++q) {            // cols 28..63 -> pos 0..35
                    float4 v = *(const float4*)(srow + 28 + q * 4);
                    v.x = tf32r(v.x); v.y = tf32r(v.y);
                    v.z = tf32r(v.z); v.w = tf32r(v.w);
                    *(float4*)(dst + q * 4) = v;
                }
                *(float4*)(dst + 36) = z;                // pos 36..39 (cols >=64)
            }
        } else {
            #pragma unroll
            for (int q = 0; q < 10; ++q) *(float4*)(dst + q * 4) = z;
        }
    }
    __syncthreads();

    int p = wid & 3, rh = wid >> 2;
    int py = p >> 1, px = p & 1;

    float acc[2][4][4];
    #pragma unroll
    for (int r = 0; r < 2; ++r)
        #pragma unroll
        for (int n = 0; n < 4; ++n)
            #pragma unroll
            for (int q = 0; q < 4; ++q) acc[r][n][q] = 0.f;

    #pragma unroll
    for (int kk = 0; kk < 16; ++kk) {
        float4 af = __ldg((const float4*)(g_W4 + ((p * 16 + kk) * 32 + lane) * 4));
        int uv = kk >> 2;
        int du = (uv >> 1) + py - 1, dv = (uv & 1) + px - 1;
        int ci0 = (kk & 3) * 8;
        const float* B0 = sHq + (ci0 + thr) * 264 + (1 + du + 2 * rh) * 40
                          + 4 + dv + grp;
        uint32_t a0 = __float_as_uint(af.x), a1 = __float_as_uint(af.y);
        uint32_t a2 = __float_as_uint(af.z), a3 = __float_as_uint(af.w);
        #pragma unroll
        for (int r = 0; r < 2; ++r)
            #pragma unroll
            for (int nt = 0; nt < 4; ++nt) {
                uint32_t b0 = __float_as_uint(B0[r * 40 + nt * 8]);
                uint32_t b1 = __float_as_uint(B0[r * 40 + nt * 8 + 1056]);
                mma8(acc[r][nt][0], acc[r][nt][1], acc[r][nt][2], acc[r][nt][3],
                     a0, a1, a2, a3, b0, b1);
            }
    }

    __syncthreads();   // all warps done reading sHq
    float bias_lo = sB[grp], bias_hi = sB[grp + 8];
    float* sOut = sHq;   // reuse union: [8y][16c][72]
    #pragma unroll
    for (int r = 0; r < 2; ++r) {
        int yl = 2 * (2 * rh + r) + py;
        #pragma unroll
        for (int nt = 0; nt < 4; ++nt) {
            int x = 16 * nt + 4 * thr + px;
            float* o = sOut + yl * 1152 + x;
            float v0 = acc[r][nt][0] + bias_lo;
            float v1 = acc[r][nt][1] + bias_lo;
            float v2 = acc[r][nt][2] + bias_hi;
            float v3 = acc[r][nt][3] + bias_hi;
            o[grp * 72]           = gelu_fast(v0);
            o[grp * 72 + 2]       = gelu_fast(v1);
            o[(grp + 8) * 72]     = gelu_fast(v2);
            o[(grp + 8) * 72 + 2] = gelu_fast(v3);
        }
    }
    __syncthreads();
    // coalesced writeout: 16c x 8y x 64x
    #pragma unroll
    for (int q = 0; q < 8; ++q) {
        int idx = q * 256 + tid;          // float4 id
        int x4 = idx & 15, ch = (idx >> 4) & 15, yy = idx >> 8;
        float4 val = *(const float4*)(sOut + yy * 1152 + ch * 72 + x4 * 4);
        *(float4*)(g_gg + ((b * 16 + ch) << 14) + (((yq << 3) + yy) << 7)
                   + (bxh << 6) + x4 * 4) = val;
    }
}

// ---------------------------------------------------------------------------
// K5: up2 + conv d2 (parity-folded) + clip, 2x4 px/thread.
// Block 1024 reduces the commit-loss partials instead (k6 folded in).
// ---------------------------------------------------------------------------
__global__ void __launch_bounds__(256) k5_dec2(const float* __restrict__ bias,
                                               float* __restrict__ out) {
    int tid = threadIdx.x;

    if (blockIdx.x == 1024) {
        __shared__ float sm[256];
        sm[tid] = (g_part[tid] + g_part[tid + 256]) +
                  (g_part[tid + 512] + g_part[tid + 768]);
        __syncthreads();
        #pragma unroll
        for (int o = 128; o > 0; o >>= 1) {
            if (tid < o) sm[tid] += sm[tid + o];
            __syncthreads();
        }
        if (tid == 0) out[LOSS_OFF] = sm[0] * (1.0f / 4194304.0f);
        return;
    }

    __shared__ __align__(16) float sW[256];
    sW[tid] = g_Wf2[tid];
    __syncthreads();

    int lin = blockIdx.x * 256 + tid;
    int j = lin & 63, i = (lin >> 6) & 127, b = lin >> 13;
    bool topok = i > 0, botok = i < 127;
    bool eok = j > 0, fok = j < 63;
    float bz = __ldg(bias);

    float a00 = 0.f, a01 = 0.f, a02 = 0.f, a03 = 0.f;
    float a10 = 0.f, a11 = 0.f, a12 = 0.f, a13 = 0.f;

    #pragma unroll 1
    for (int ci = 0; ci < 16; ++ci) {
        const float* base = g_gg + ((b * 16 + ci) << 14) + 2 * j;
        float eA = 0.f, fA = 0.f, eB = 0.f, fB = 0.f, eC = 0.f, fC = 0.f;
        float2 dA = make_float2(0.f, 0.f), dC = dA, dB;
        const float* rB = base + (i << 7);
        dB = *(const float2*)rB;
        if (eok) eB = rB[-1];
        if (fok) fB = rB[2];
        if (topok) {
            const float* rA = base + ((i - 1) << 7);
            dA = *(const float2*)rA;
            if (eok) eA = rA[-1];
            if (fok) fA = rA[2];
        }
        if (botok) {
            const float* rC = base + ((i + 1) << 7);
            dC = *(const float2*)rC;
            if (eok) eC = rC[-1];
            if (fok) fC = rC[2];
        }
        float4 w00 = *(const float4*)(sW + ci * 4);          // p=0 (ye, xe)
        float4 w01 = *(const float4*)(sW + 64 + ci * 4);     // p=1 (ye, xo)
        float4 w10 = *(const float4*)(sW + 128 + ci * 4);    // p=2 (yo, xe)
        float4 w11 = *(const float4*)(sW + 192 + ci * 4);    // p=3 (yo, xo)
        // y = 2i (top=row i-1, bot=row i)
        a00 = fmaf(w00.x, eA,   fmaf(w00.y, dA.x, fmaf(w00.z, eB,   fmaf(w00.w, dB.x, a00))));
        a01 = fmaf(w01.x, dA.x, fmaf(w01.y, dA.y, fmaf(w01.z, dB.x, fmaf(w01.w, dB.y, a01))));
        a02 = fmaf(w00.x, dA.x, fmaf(w00.y, dA.y, fmaf(w00.z, dB.x, fmaf(w00.w, dB.y, a02))));
        a03 = fmaf(w01.x, dA.y, fmaf(w01.y, fA,   fmaf(w01.z, dB.y, fmaf(w01.w, fB,   a03))));
        // y = 2i+1 (top=row i, bot=row i+1)
        a10 = fmaf(w10.x, eB,   fmaf(w10.y, dB.x, fmaf(w10.z, eC,   fmaf(w10.w, dC.x, a10))));
        a11 = fmaf(w11.x, dB.x, fmaf(w11.y, dB.y, fmaf(w11.z, dC.x, fmaf(w11.w, dC.y, a11))));
        a12 = fmaf(w10.x, dB.x, fmaf(w10.y, dB.y, fmaf(w10.z, dC.x, fmaf(w10.w, dC.y, a12))));
        a13 = fmaf(w11.x, dB.y, fmaf(w11.y, fB,   fmaf(w11.z, dC.y, fmaf(w11.w, fC,   a13))));
    }

    float* o = out + (b << 16) + ((2 * i) << 8) + 4 * j;
    float4 r0 = make_float4(fminf(fmaxf(a00 + bz, -1.f), 1.f),
                            fminf(fmaxf(a01 + bz, -1.f), 1.f),
                            fminf(fmaxf(a02 + bz, -1.f), 1.f),
                            fminf(fmaxf(a03 + bz, -1.f), 1.f));
    *(float4*)o = r0;
    float4 r1 = make_float4(fminf(fmaxf(a10 + bz, -1.f), 1.f),
                            fminf(fmaxf(a11 + bz, -1.f), 1.f),
                            fminf(fmaxf(a12 + bz, -1.f), 1.f),
                            fminf(fmaxf(a13 + bz, -1.f), 1.f));
    *(float4*)(o + 256) = r1;
}

// ---------------------------------------------------------------------------
extern "C" void kernel_launch(void* const* d_in, const int* in_sizes, int n_in,
                              void* d_out, int out_size) {
    const float* x   = (const float*)d_in[0];
    const float* e1w = (const float*)d_in[1];
    const float* e1b = (const float*)d_in[2];
    const float* e2w = (const float*)d_in[3];
    const float* e2b = (const float*)d_in[4];
    const float* cb  = (const float*)d_in[5];
    const float* d1w = (const float*)d_in[6];
    const float* d1b = (const float*)d_in[7];
    const float* d2w = (const float*)d_in[8];
    const float* d2b = (const float*)d_in[9];
    float* out = (float*)d_out;

    static int s_attr_done = 0;
    if (!s_attr_done) {
        cudaFuncSetAttribute(k3_vq, cudaFuncAttributeMaxDynamicSharedMemorySize,
                             K3_SMEM);
        s_attr_done = 1;
    }

    k1_conv1<<<2211, 256>>>(x, e1w, e1b, cb, d1w, d2w);   // conv1 + setup tail
    k2_conv2<<<2048, 128>>>(e2w, e2b);
    k3_vq<<<1024, 256, K3_SMEM>>>(cb, out);
    k4_dec1<<<1024, 256>>>(d1b);
    k5_dec2<<<1025, 256>>>(d2b, out);                      // + loss reduce block
}

// round 13
// speedup vs baseline: 1.6818x; 1.0204x over previous
#include <cuda_runtime.h>
#include <math.h>
#include <stdint.h>

// ---------------------------------------------------------------------------
// SimpleVQAutoEncoder on GB300 — FFMA2 encoder + mma.sync tf32 VQ + tf32 decoder
//
//   K1: [blocks <2048] conv1+maxpool2+gelu (FFMA2 pairs) -> g_h1
//       [blocks>=2048] setup: codebook norms/frags, decoder weight frags
//   K2: conv2(16->32,3x3,SAME) + maxpool2 (FFMA2)      -> g_h2 [32,32,64,64]
//   K3: VQ mma.sync tf32 3-pass split, ILP-2 tile pairs-> g_hq, indices, g_part
//   K4: up2 + conv d1(32->16) folded, tf32 mma GEMM    -> g_gg [32,16,128,128]
//   K5: up2 + conv d2(16->1) folded + clip; last block reduces commit loss
//
// Output layout (float32): [ y (32*256*256) | indices (32*64*64) | loss (1) ]
// ---------------------------------------------------------------------------

#define IDX_OFF   2097152
#define LOSS_OFF  2228224

typedef unsigned long long u64;

__device__ __forceinline__ u64 ffma2(u64 a, u64 b, u64 c) {
    u64 d;
    asm("fma.rn.f32x2 %0, %1, %2, %3;" : "=l"(d) : "l"(a), "l"(b), "l"(c));
    return d;
}
__device__ __forceinline__ u64 packff(float lo, float hi) {
    u64 d;
    asm("mov.b64 %0, {%1, %2};" : "=l"(d) : "f"(lo), "f"(hi));
    return d;
}
__device__ __forceinline__ float2 unpackff(u64 v) {
    float lo, hi;
    asm("mov.b64 {%0, %1}, %2;" : "=f"(lo), "=f"(hi) : "l"(v));
    return make_float2(lo, hi);
}
__device__ __forceinline__ float tf32r(float v) {
    uint32_t t;
    asm("cvt.rna.tf32.f32 %0, %1;" : "=r"(t) : "f"(v));
    return __uint_as_float(t);
}
// erf-based gelu: mathematically identical to x*normcdf(x), ~1 ulp different
__device__ __forceinline__ float gelu_fast(float v) {
    return 0.5f * v * (1.0f + erff(v * 0.70710678118654752f));
}

// m16n8k8 tf32 mma (sm_80+ PTX, valid at base sm_103 target)
__device__ __forceinline__ void mma8(float& c0, float& c1, float& c2, float& c3,
                                     uint32_t a0, uint32_t a1, uint32_t a2,
                                     uint32_t a3, uint32_t b0, uint32_t b1) {
    asm volatile(
        "mma.sync.aligned.m16n8k8.row.col.f32.tf32.tf32.f32 "
        "{%0,%1,%2,%3}, {%4,%5,%6,%7}, {%8,%9}, {%0,%1,%2,%3};"
        : "+f"(c0), "+f"(c1), "+f"(c2), "+f"(c3)
        : "r"(a0), "r"(a1), "r"(a2), "r"(a3), "r"(b0), "r"(b1));
}

// Intermediates (device globals: no allocation allowed)
__device__ float g_h1[32 * 16 * 128 * 128];   // 33.5 MB
__device__ float g_h2[32 * 32 * 64 * 64];     // 16.8 MB
__device__ float g_hq[32 * 32 * 64 * 64];     // 16.8 MB
__device__ float g_gg[32 * 16 * 128 * 128];   // 33.5 MB
__device__ float g_cnh[512];                  // 0.5*||codebook_k||^2
__device__ float g_cbF[64 * 32 * 16];         // packed VQ codebook frags
__device__ float g_W4[4 * 16 * 32 * 4];       // tf32 d1 weight A-fragments
__device__ float g_Wf2[4 * 16 * 4];           // folded d2 [p][ci][uv]
__device__ float g_part[1024];                // commit-loss partials

// ---------------------------------------------------------------------------
// Setup body (runs in K1's tail blocks).
// Nearest-up2 folding: output (y,x) reads a 2x2 hq patch; the 3x3 taps
// collapse per output parity (py,px) onto the 4 corners.
// ---------------------------------------------------------------------------
__device__ void setup_body(int t, const float* __restrict__ cb,
                           const float* __restrict__ d1w,
                           const float* __restrict__ d2w) {
    if (t < 8192) {
        int j = t & 3, lane = (t >> 2) & 31, kk = (t >> 7) & 15, p = t >> 11;
        int grp = lane >> 2, thr = lane & 3;
        int c = grp + (j & 1) * 8;
        int K = kk * 8 + thr + (j >> 1) * 4;
        int ci = K & 31, uv = K >> 5;
        int u = uv >> 1, v = uv & 1;
        int py = p >> 1, px = p & 1;
        float s = 0.f;
        #pragma unroll
        for (int dy = 0; dy < 3; ++dy) {
            int ug = (py == 0) ? (dy >= 1) : (dy >= 2);
            if (ug != u) continue;
            #pragma unroll
            for (int dx = 0; dx < 3; ++dx) {
                int vg = (px == 0) ? (dx >= 1) : (dx >= 2);
                if (vg != v) continue;
                s += d1w[((c * 32 + ci) * 3 + dy) * 3 + dx];
            }
        }
        g_W4[t] = tf32r(s);
    } else if (t < 8704) {
        int k = t - 8192;
        float s = 0.f;
        #pragma unroll
        for (int c = 0; c < 32; ++c) { float v = cb[k * 32 + c]; s = fmaf(v, v, s); }
        g_cnh[k] = 0.5f * s;
    } else if (t < 8960) {
        int e = t - 8704;
        int uv = e & 3, ci = (e >> 2) & 15, p = e >> 6;
        int py = p >> 1, px = p & 1, u = uv >> 1, v = uv & 1;
        float s = 0.f;
        #pragma unroll
        for (int dy = 0; dy < 3; ++dy) {
            int ug = (py == 0) ? (dy >= 1) : (dy >= 2);
            if (ug != u) continue;
            #pragma unroll
            for (int dx = 0; dx < 3; ++dx) {
                int vg = (px == 0) ? (dx >= 1) : (dx >= 2);
                if (vg != v) continue;
                s += d2w[ci * 9 + dy * 3 + dx];
            }
        }
        g_Wf2[(p * 16 + ci) * 4 + uv] = s;
    } else if (t < 41728) {
        int v = t - 8960;                 // 0..32767
        int e = v & 3, lane = (v >> 2) & 31, q = (v >> 7) & 3, nt = v >> 9;
        int grp = lane >> 2, thr = lane & 3;
        int j = q * 4 + e;
        int jj = j & 7;
        int ks = jj >> 1, half = jj & 1;
        int c = ks * 8 + thr + (half ? 4 : 0);
        float val = cb[(nt * 8 + grp) * 32 + c];
        float hi = __uint_as_float(__float_as_uint(val) & 0xFFFFE000u);
        g_cbF[v] = (j < 8) ? hi : (val - hi);
    }
}

// ---------------------------------------------------------------------------
// K1: conv1 + maxpool2 + gelu (erff), FFMA2 channel pairs.
// Thread = (b, i, j) pooled pixel, 16 channels (8 pairs).
// Blocks >= 2048 run the setup body instead.
// ---------------------------------------------------------------------------
__global__ void __launch_bounds__(256) k1_conv1(const float* __restrict__ x,
                                                const float* __restrict__ w,
                                                const float* __restrict__ bias,
                                                const float* __restrict__ cb,
                                                const float* __restrict__ d1w,
                                                const float* __restrict__ d2w) {
    int tid = threadIdx.x;
    if (blockIdx.x >= 2048) {
        setup_body((blockIdx.x - 2048) * 256 + tid, cb, d1w, d2w);
        return;
    }

    __shared__ __align__(8) float2 sw2[72];   // [pair*9+tap] = (w[2p], w[2p+1])
    __shared__ float sb[16];
    if (tid < 72) {
        int pr = tid / 9, tap = tid - pr * 9;
        sw2[tid] = make_float2(__ldg(w + (2 * pr) * 9 + tap),
                               __ldg(w + (2 * pr + 1) * 9 + tap));
    }
    if (tid < 16) sb[tid] = __ldg(bias + tid);
    __syncthreads();

    int lin = blockIdx.x * 256 + tid;
    int j = lin & 127, i = (lin >> 7) & 127, b = lin >> 14;
    const float* xb = x + (b << 16);

    u64 xv[4][4];
    #pragma unroll
    for (int r = 0; r < 4; ++r) {
        int ry = 2 * i - 1 + r;
        bool rok = (unsigned)ry < 256u;
        #pragma unroll
        for (int cc = 0; cc < 4; ++cc) {
            int cx = 2 * j - 1 + cc;
            float v = (rok && (unsigned)cx < 256u) ? __ldg(xb + ry * 256 + cx) : 0.f;
            xv[r][cc] = packff(v, v);
        }
    }

    #pragma unroll
    for (int pr = 0; pr < 8; ++pr) {
        u64 wv[9];
        #pragma unroll
        for (int k = 0; k < 9; ++k) wv[k] = *(const u64*)(sw2 + pr * 9 + k);
        u64 acc[4];
        #pragma unroll
        for (int q = 0; q < 4; ++q) acc[q] = 0ull;
        #pragma unroll
        for (int dy = 0; dy < 3; ++dy)
            #pragma unroll
            for (int dx = 0; dx < 3; ++dx) {
                u64 wk = wv[dy * 3 + dx];
                acc[0] = ffma2(wk, xv[dy][dx], acc[0]);
                acc[1] = ffma2(wk, xv[dy][dx + 1], acc[1]);
                acc[2] = ffma2(wk, xv[dy + 1][dx], acc[2]);
                acc[3] = ffma2(wk, xv[dy + 1][dx + 1], acc[3]);
            }
        float2 m0 = unpackff(acc[0]);
        float2 m1 = unpackff(acc[1]);
        float2 m2 = unpackff(acc[2]);
        float2 m3 = unpackff(acc[3]);
        float lo = fmaxf(fmaxf(m0.x, m1.x), fmaxf(m2.x, m3.x)) + sb[2 * pr];
        float hi = fmaxf(fmaxf(m0.y, m1.y), fmaxf(m2.y, m3.y)) + sb[2 * pr + 1];
        g_h1[((b * 16 + 2 * pr) << 14) + (i << 7) + j]     = gelu_fast(lo);
        g_h1[((b * 16 + 2 * pr + 1) << 14) + (i << 7) + j] = gelu_fast(hi);
    }
}

// ---------------------------------------------------------------------------
// K2: conv2(16->32) + maxpool2, FFMA2 on channel pairs, prepacked patch.
// ---------------------------------------------------------------------------
__global__ void __launch_bounds__(128) k2_conv2(const float* __restrict__ w,
                                                const float* __restrict__ bias) {
    __shared__ __align__(16) float swt[2304];  // [ci*9+tap][16c]
    __shared__ float sb[16];
    int tid = threadIdx.x;
    int lin = blockIdx.x * 128 + tid;
    int j = lin & 63, i = (lin >> 6) & 63, half = (lin >> 12) & 1, b = lin >> 13;

    for (int t = tid; t < 2304; t += 128) {
        int ci = t / 144, r = t - ci * 144;
        int tap = r >> 4, c = r & 15;
        swt[t] = __ldg(w + (half * 16 + c) * 144 + ci * 9 + tap);
    }
    if (tid < 16) sb[tid] = __ldg(bias + half * 16 + tid);
    __syncthreads();

    int ry[4], cx[4];
    bool rok[4], cok[4];
    #pragma unroll
    for (int r = 0; r < 4; ++r) {
        ry[r] = 2 * i - 1 + r; rok[r] = (unsigned)ry[r] < 128u;
        cx[r] = 2 * j - 1 + r; cok[r] = (unsigned)cx[r] < 128u;
    }

    u64 acc[4][8];
    #pragma unroll
    for (int p = 0; p < 4; ++p)
        #pragma unroll
        for (int q = 0; q < 8; ++q) acc[p][q] = 0ull;

    #pragma unroll 1
    for (int ci = 0; ci < 16; ++ci) {
        const float* src = g_h1 + ((b * 16 + ci) << 14);
        u64 patch[4][4];
        #pragma unroll
        for (int r = 0; r < 4; ++r)
            #pragma unroll
            for (int cc = 0; cc < 4; ++cc) {
                float v = (rok[r] && cok[cc]) ? src[(ry[r] << 7) + cx[cc]] : 0.f;
                patch[r][cc] = packff(v, v);
            }

        #pragma unroll
        for (int dy = 0; dy < 3; ++dy)
            #pragma unroll
            for (int dx = 0; dx < 3; ++dx) {
                const ulonglong2* W2 =
                    (const ulonglong2*)(swt + (ci * 9 + dy * 3 + dx) * 16);
                ulonglong2 wA = W2[0], wB = W2[1], wC = W2[2], wD = W2[3];
                #pragma unroll
                for (int p = 0; p < 4; ++p) {
                    u64 vp = patch[(p >> 1) + dy][(p & 1) + dx];
                    acc[p][0] = ffma2(wA.x, vp, acc[p][0]);
                    acc[p][1] = ffma2(wA.y, vp, acc[p][1]);
                    acc[p][2] = ffma2(wB.x, vp, acc[p][2]);
                    acc[p][3] = ffma2(wB.y, vp, acc[p][3]);
                    acc[p][4] = ffma2(wC.x, vp, acc[p][4]);
                    acc[p][5] = ffma2(wC.y, vp, acc[p][5]);
                    acc[p][6] = ffma2(wD.x, vp, acc[p][6]);
                    acc[p][7] = ffma2(wD.y, vp, acc[p][7]);
                }
            }
    }

    float* dst = g_h2 + ((b * 32 + half * 16) << 12) + (i << 6) + j;
    #pragma unroll
    for (int q = 0; q < 8; ++q) {
        float2 m0 = unpackff(acc[0][q]);
        float2 m1 = unpackff(acc[1][q]);
        float2 m2 = unpackff(acc[2][q]);
        float2 m3 = unpackff(acc[3][q]);
        float lo = fmaxf(fmaxf(m0.x, m1.x), fmaxf(m2.x, m3.x)) + sb[2 * q];
        float hi = fmaxf(fmaxf(m0.y, m1.y), fmaxf(m2.y, m3.y)) + sb[2 * q + 1];
        dst[(2 * q) << 12]     = lo;
        dst[(2 * q + 1) << 12] = hi;
    }
}

// ---------------------------------------------------------------------------
// K3: VQ via mma.sync tf32 3-pass split (hh + lh + hl), ILP-2 tile pairing:
// tiles nt and nt+1 accumulate into independent register sets with
// interleaved MMA issue (per-tile order unchanged -> bit-identical indices).
// 256 threads/CTA (8 warps x m16 tokens = 128 tokens), 3 CTAs/SM.
// argmax of f.c - 0.5||c||^2, lowest-index tie-break.
// ---------------------------------------------------------------------------
#define K3_CN   16384
#define K3_WS   (16384 + 512)
#define K3_SMEM ((16384 + 512 + 16) * 4)

__global__ void __launch_bounds__(256, 3) k3_vq(const float* __restrict__ cb,
                                                float* __restrict__ out) {
    extern __shared__ float sm3[];
    float* sF  = sm3;               // 16384 floats: one 256-code chunk
    float* sCn = sm3 + K3_CN;       // 512 half-norms
    float* sWs = sm3 + K3_WS;       // 8 warp partials

    int tid = threadIdx.x;
    int wid = tid >> 5, lane = tid & 31;
    int grp = lane >> 2, thr = lane & 3;
    int base = blockIdx.x * 128;           // global token base
    int b = base >> 12, ij0 = base & 4095;

    // ---- A fragments (16 tokens x K=32) from global into regs, hi/lo ----
    const float* fbase = g_h2 + (b << 17) + ij0 + wid * 16 + grp;
    uint32_t ahi[16], alo[16];
    #pragma unroll
    for (int ks = 0; ks < 4; ++ks) {
        int c0 = ks * 8 + thr, c1 = c0 + 4;
        float v00 = fbase[c0 << 12];
        float v10 = fbase[(c0 << 12) + 8];
        float v01 = fbase[c1 << 12];
        float v11 = fbase[(c1 << 12) + 8];
        uint32_t h;
        h = __float_as_uint(v00) & 0xFFFFE000u;
        ahi[ks * 4 + 0] = h; alo[ks * 4 + 0] = __float_as_uint(v00 - __uint_as_float(h));
        h = __float_as_uint(v10) & 0xFFFFE000u;
        ahi[ks * 4 + 1] = h; alo[ks * 4 + 1] = __float_as_uint(v10 - __uint_as_float(h));
        h = __float_as_uint(v01) & 0xFFFFE000u;
        ahi[ks * 4 + 2] = h; alo[ks * 4 + 2] = __float_as_uint(v01 - __uint_as_float(h));
        h = __float_as_uint(v11) & 0xFFFFE000u;
        ahi[ks * 4 + 3] = h; alo[ks * 4 + 3] = __float_as_uint(v11 - __uint_as_float(h));
    }
    sCn[tid] = g_cnh[tid];
    sCn[tid + 256] = g_cnh[tid + 256];

    float bv0 = -1e30f, bv1 = -1e30f;
    int bk0 = 0, bk1 = 0;

    #pragma unroll 1
    for (int ch = 0; ch < 2; ++ch) {
        __syncthreads();   // previous chunk fully consumed
        {
            const float4* src = (const float4*)(g_cbF + ch * 16384);
            float4* dst = (float4*)sF;
            #pragma unroll
            for (int t = 0; t < 16; ++t)
                dst[tid + t * 256] = __ldg(src + tid + t * 256);
        }
        __syncthreads();

        #pragma unroll 1
        for (int nt = 0; nt < 32; nt += 2) {
            const float4* fpA = (const float4*)sF + (nt * 4) * 32 + lane;
            const float4* fpB = fpA + 128;
            float cA0 = 0.f, cA1 = 0.f, cA2 = 0.f, cA3 = 0.f;
            float cB0 = 0.f, cB1 = 0.f, cB2 = 0.f, cB3 = 0.f;
            // hi planes (b = hi): hh + lh, ks0..3, tiles interleaved
            {
                float4 hA = fpA[0], hB = fpB[0];
                mma8(cA0,cA1,cA2,cA3, ahi[0],ahi[1],ahi[2],ahi[3],
                     __float_as_uint(hA.x), __float_as_uint(hA.y));
                mma8(cB0,cB1,cB2,cB3, ahi[0],ahi[1],ahi[2],ahi[3],
                     __float_as_uint(hB.x), __float_as_uint(hB.y));
                mma8(cA0,cA1,cA2,cA3, alo[0],alo[1],alo[2],alo[3],
                     __float_as_uint(hA.x), __float_as_uint(hA.y));
                mma8(cB0,cB1,cB2,cB3, alo[0],alo[1],alo[2],alo[3],
                     __float_as_uint(hB.x), __float_as_uint(hB.y));
                mma8(cA0,cA1,cA2,cA3, ahi[4],ahi[5],ahi[6],ahi[7],
                     __float_as_uint(hA.z), __float_as_uint(hA.w));
                mma8(cB0,cB1,cB2,cB3, ahi[4],ahi[5],ahi[6],ahi[7],
                     __float_as_uint(hB.z), __float_as_uint(hB.w));
                mma8(cA0,cA1,cA2,cA3, alo[4],alo[5],alo[6],alo[7],
                     __float_as_uint(hA.z), __float_as_uint(hA.w));
                mma8(cB0,cB1,cB2,cB3, alo[4],alo[5],alo[6],alo[7],
                     __float_as_uint(hB.z), __float_as_uint(hB.w));
            }
            {
                float4 hA = fpA[32], hB = fpB[32];
                mma8(cA0,cA1,cA2,cA3, ahi[8],ahi[9],ahi[10],ahi[11],
                     __float_as_uint(hA.x), __float_as_uint(hA.y));
                mma8(cB0,cB1,cB2,cB3, ahi[8],ahi[9],ahi[10],ahi[11],
                     __float_as_uint(hB.x), __float_as_uint(hB.y));
                mma8(cA0,cA1,cA2,cA3, alo[8],alo[9],alo[10],alo[11],
                     __float_as_uint(hA.x), __float_as_uint(hA.y));
                mma8(cB0,cB1,cB2,cB3, alo[8],alo[9],alo[10],alo[11],
                     __float_as_uint(hB.x), __float_as_uint(hB.y));
                mma8(cA0,cA1,cA2,cA3, ahi[12],ahi[13],ahi[14],ahi[15],
                     __float_as_uint(hA.z), __float_as_uint(hA.w));
                mma8(cB0,cB1,cB2,cB3, ahi[12],ahi[13],ahi[14],ahi[15],
                     __float_as_uint(hB.z), __float_as_uint(hB.w));
                mma8(cA0,cA1,cA2,cA3, alo[12],alo[13],alo[14],alo[15],
                     __float_as_uint(hA.z), __float_as_uint(hA.w));
                mma8(cB0,cB1,cB2,cB3, alo[12],alo[13],alo[14],alo[15],
                     __float_as_uint(hB.z), __float_as_uint(hB.w));
            }
            // lo planes (b = lo): hl only, ks0..3
            {
                float4 lA = fpA[64], lB = fpB[64];
                mma8(cA0,cA1,cA2,cA3, ahi[0],ahi[1],ahi[2],ahi[3],
                     __float_as_uint(lA.x), __float_as_uint(lA.y));
                mma8(cB0,cB1,cB2,cB3, ahi[0],ahi[1],ahi[2],ahi[3],
                     __float_as_uint(lB.x), __float_as_uint(lB.y));
                mma8(cA0,cA1,cA2,cA3, ahi[4],ahi[5],ahi[6],ahi[7],
                     __float_as_uint(lA.z), __float_as_uint(lA.w));
                mma8(cB0,cB1,cB2,cB3, ahi[4],ahi[5],ahi[6],ahi[7],
                     __float_as_uint(lB.z), __float_as_uint(lB.w));
            }
            {
                float4 lA = fpA[96], lB = fpB[96];
                mma8(cA0,cA1,cA2,cA3, ahi[8],ahi[9],ahi[10],ahi[11],
                     __float_as_uint(lA.x), __float_as_uint(lA.y));
                mma8(cB0,cB1,cB2,cB3, ahi[8],ahi[9],ahi[10],ahi[11],
                     __float_as_uint(lB.x), __float_as_uint(lB.y));
                mma8(cA0,cA1,cA2,cA3, ahi[12],ahi[13],ahi[14],ahi[15],
                     __float_as_uint(lA.z), __float_as_uint(lA.w));
                mma8(cB0,cB1,cB2,cB3, ahi[12],ahi[13],ahi[14],ahi[15],
                     __float_as_uint(lB.z), __float_as_uint(lB.w));
            }

            // epilogue tile A then tile B (ascending columns preserved)
            int colA = ch * 256 + nt * 8 + 2 * thr;
            float cn0 = sCn[colA], cn1 = sCn[colA + 1];
            float v;
            v = cA0 - cn0; if (v > bv0) { bv0 = v; bk0 = colA; }
            v = cA1 - cn1; if (v > bv0) { bv0 = v; bk0 = colA + 1; }
            v = cA2 - cn0; if (v > bv1) { bv1 = v; bk1 = colA; }
            v = cA3 - cn1; if (v > bv1) { bv1 = v; bk1 = colA + 1; }
            int colB = colA + 8;
            float cn2 = sCn[colB], cn3 = sCn[colB + 1];
            v = cB0 - cn2; if (v > bv0) { bv0 = v; bk0 = colB; }
            v = cB1 - cn3; if (v > bv0) { bv0 = v; bk0 = colB + 1; }
            v = cB2 - cn2; if (v > bv1) { bv1 = v; bk1 = colB; }
            v = cB3 - cn3; if (v > bv1) { bv1 = v; bk1 = colB + 1; }
        }
    }

    // ---- reduce across the 4 lanes of each row-group (lowest k on ties) ----
    #pragma unroll
    for (int o = 1; o <= 2; o <<= 1) {
        float ov = __shfl_xor_sync(0xffffffffu, bv0, o);
        int   ok = __shfl_xor_sync(0xffffffffu, bk0, o);
        if (ov > bv0 || (ov == bv0 && ok < bk0)) { bv0 = ov; bk0 = ok; }
        ov = __shfl_xor_sync(0xffffffffu, bv1, o);
        ok = __shfl_xor_sync(0xffffffffu, bk1, o);
        if (ov > bv1 || (ov == bv1 && ok < bk1)) { bv1 = ov; bk1 = ok; }
    }

    int tokl = wid * 16 + grp;
    if (thr == 0) out[IDX_OFF + base + tokl] = (float)bk0;
    if (thr == 2) out[IDX_OFF + base + tokl + 8] = (float)bk1;

    // ---- gather + commit-loss partials: 4 lanes = 2 tokens x 2 halves ----
    int mytok = tokl + ((thr >> 1) << 3);
    int myk   = (thr < 2) ? bk0 : bk1;
    int cbase = (thr & 1) << 4;
    const float* cbr = cb + myk * 32 + cbase;
    const float* h2p = g_h2 + (b << 17) + (cbase << 12) + ij0 + mytok;
    float*       hqp = g_hq + (b << 17) + (cbase << 12) + ij0 + mytok;
    float part = 0.f;
    #pragma unroll
    for (int c = 0; c < 16; ++c) {
        float qv = __ldg(cbr + c);
        float fv = h2p[c << 12];
        float d = qv - fv;
        part = fmaf(d, d, part);
        hqp[c << 12] = qv;
    }

    // deterministic block reduction (8 warps)
    #pragma unroll
    for (int o = 16; o > 0; o >>= 1)
        part += __shfl_down_sync(0xffffffffu, part, o);
    if (lane == 0) sWs[wid] = part;
    __syncthreads();
    if (tid == 0) {
        float s = 0.f;
        #pragma unroll
        for (int q = 0; q < 8; ++q) s += sWs[q];
        g_part[blockIdx.x] = s;
    }
}

// ---------------------------------------------------------------------------
// K4: up2 + conv d1 (parity-folded) via tf32 mma GEMM + gelu (erff-based).
// Block = (b, yq, x-half): output tile 16c x 8y x 64x. Warp = (parity p,
// row-half rh): acc 32 regs. A frags from global (L1-hot); hq tile
// (rna-rounded tf32) in smem stride 264 (conflict-free). 3 CTAs/SM.
// ---------------------------------------------------------------------------
__global__ void __launch_bounds__(256, 3) k4_dec1(const float* __restrict__ bias) {
    __shared__ __align__(16) float sm4[9232];
    float* sHq = sm4;            // union: hq tile (32*264=8448) / out (9216)
    float* sB  = sm4 + 9216;     // 16 bias

    int tid = threadIdx.x;
    int wid = tid >> 5, lane = tid & 31;
    int grp = lane >> 2, thr = lane & 3;
    int bk = blockIdx.x;
    int b = bk >> 5, yq = (bk >> 1) & 15, bxh = bk & 1;
    int yi0 = yq * 4;

    if (tid < 16) sB[tid] = __ldg(bias + tid);
    // stage hq rows yi0-1..yi0+4 (6 rows), 40 tile cols, col0 = 32*bxh - 4
    if (tid < 192) {
        int ci = tid / 6, r6 = tid - ci * 6;
        float* dst = sHq + ci * 264 + r6 * 40;
        int r = yi0 - 1 + r6;
        float4 z = make_float4(0.f, 0.f, 0.f, 0.f);
        if ((unsigned)r < 64u) {
            const float* srow = g_hq + ((b * 32 + ci) << 12) + (r << 6);
            if (bxh == 0) {
                *(float4*)dst = z;                       // pos 0..3 (cols <0)
                #pragma unroll
                for (int q = 0; q < 9; ++q) {            // cols 0..35 -> pos 4..39
                    float4 v = *(const float4*)(srow + q * 4);
                    v.x = tf32r(v.x); v.y = tf32r(v.y);
                    v.z = tf32r(v.z); v.w = tf32r(v.w);
                    *(float4*)(dst + 4 + q * 4) = v;
                }
            } else {
                #pragma unroll
                for (int q = 0; q < 9; ++q) {            // cols 28..63 -> pos 0..35
                    float4 v = *(const float4*)(srow + 28 + q * 4);
                    v.x = tf32r(v.x); v.y = tf32r(v.y);
                    v.z = tf32r(v.z); v.w = tf32r(v.w);
                    *(float4*)(dst + q * 4) = v;
                }
                *(float4*)(dst + 36) = z;                // pos 36..39 (cols >=64)
            }
        } else {
            #pragma unroll
            for (int q = 0; q < 10; ++q) *(float4*)(dst + q * 4) = z;
        }
    }
    __syncthreads();

    int p = wid & 3, rh = wid >> 2;
    int py = p >> 1, px = p & 1;

    float acc[2][4][4];
    #pragma unroll
    for (int r = 0; r < 2; ++r)
        #pragma unroll
        for (int n = 0; n < 4; ++n)
            #pragma unroll
            for (int q = 0; q < 4; ++q) acc[r][n][q] = 0.f;

    #pragma unroll
    for (int kk = 0; kk < 16; ++kk) {
        float4 af = __ldg((const float4*)(g_W4 + ((p * 16 + kk) * 32 + lane) * 4));
        int uv = kk >> 2;
        int du = (uv >> 1) + py - 1, dv = (uv & 1) + px - 1;
        int ci0 = (kk & 3) * 8;
        const float* B0 = sHq + (ci0 + thr) * 264 + (1 + du + 2 * rh) * 40
                          + 4 + dv + grp;
        uint32_t a0 = __float_as_uint(af.x), a1 = __float_as_uint(af.y);
        uint32_t a2 = __float_as_uint(af.z), a3 = __float_as_uint(af.w);
        #pragma unroll
        for (int r = 0; r < 2; ++r)
            #pragma unroll
            for (int nt = 0; nt < 4; ++nt) {
                uint32_t b0 = __float_as_uint(B0[r * 40 + nt * 8]);
                uint32_t b1 = __float_as_uint(B0[r * 40 + nt * 8 + 1056]);
                mma8(acc[r][nt][0], acc[r][nt][1], acc[r][nt][2], acc[r][nt][3],
                     a0, a1, a2, a3, b0, b1);
            }
    }

    __syncthreads();   // all warps done reading sHq
    float bias_lo = sB[grp], bias_hi = sB[grp + 8];
    float* sOut = sHq;   // reuse union: [8y][16c][72]
    #pragma unroll
    for (int r = 0; r < 2; ++r) {
        int yl = 2 * (2 * rh + r) + py;
        #pragma unroll
        for (int nt = 0; nt < 4; ++nt) {
            int x = 16 * nt + 4 * thr + px;
            float* o = sOut + yl * 1152 + x;
            float v0 = acc[r][nt][0] + bias_lo;
            float v1 = acc[r][nt][1] + bias_lo;
            float v2 = acc[r][nt][2] + bias_hi;
            float v3 = acc[r][nt][3] + bias_hi;
            o[grp * 72]           = gelu_fast(v0);
            o[grp * 72 + 2]       = gelu_fast(v1);
            o[(grp + 8) * 72]     = gelu_fast(v2);
            o[(grp + 8) * 72 + 2] = gelu_fast(v3);
        }
    }
    __syncthreads();
    // coalesced writeout: 16c x 8y x 64x
    #pragma unroll
    for (int q = 0; q < 8; ++q) {
        int idx = q * 256 + tid;          // float4 id
        int x4 = idx & 15, ch = (idx >> 4) & 15, yy = idx >> 8;
        float4 val = *(const float4*)(sOut + yy * 1152 + ch * 72 + x4 * 4);
        *(float4*)(g_gg + ((b * 16 + ch) << 14) + (((yq << 3) + yy) << 7)
                   + (bxh << 6) + x4 * 4) = val;
    }
}

// ---------------------------------------------------------------------------
// K5: up2 + conv d2 (parity-folded) + clip, 2x4 px/thread.
// Block 1024 reduces the commit-loss partials instead (k6 folded in).
// ---------------------------------------------------------------------------
__global__ void __launch_bounds__(256) k5_dec2(const float* __restrict__ bias,
                                               float* __restrict__ out) {
    int tid = threadIdx.x;

    if (blockIdx.x == 1024) {
        __shared__ float sm[256];
        sm[tid] = (g_part[tid] + g_part[tid + 256]) +
                  (g_part[tid + 512] + g_part[tid + 768]);
        __syncthreads();
        #pragma unroll
        for (int o = 128; o > 0; o >>= 1) {
            if (tid < o) sm[tid] += sm[tid + o];
            __syncthreads();
        }
        if (tid == 0) out[LOSS_OFF] = sm[0] * (1.0f / 4194304.0f);
        return;
    }

    __shared__ __align__(16) float sW[256];
    sW[tid] = g_Wf2[tid];
    __syncthreads();

    int lin = blockIdx.x * 256 + tid;
    int j = lin & 63, i = (lin >> 6) & 127, b = lin >> 13;
    bool topok = i > 0, botok = i < 127;
    bool eok = j > 0, fok = j < 63;
    float bz = __ldg(bias);

    float a00 = 0.f, a01 = 0.f, a02 = 0.f, a03 = 0.f;
    float a10 = 0.f, a11 = 0.f, a12 = 0.f, a13 = 0.f;

    #pragma unroll 1
    for (int ci = 0; ci < 16; ++ci) {
        const float* base = g_gg + ((b * 16 + ci) << 14) + 2 * j;
        float eA = 0.f, fA = 0.f, eB = 0.f, fB = 0.f, eC = 0.f, fC = 0.f;
        float2 dA = make_float2(0.f, 0.f), dC = dA, dB;
        const float* rB = base + (i << 7);
        dB = *(const float2*)rB;
        if (eok) eB = rB[-1];
        if (fok) fB = rB[2];
        if (topok) {
            const float* rA = base + ((i - 1) << 7);
            dA = *(const float2*)rA;
            if (eok) eA = rA[-1];
            if (fok) fA = rA[2];
        }
        if (botok) {
            const float* rC = base + ((i + 1) << 7);
            dC = *(const float2*)rC;
            if (eok) eC = rC[-1];
            if (fok) fC = rC[2];
        }
        float4 w00 = *(const float4*)(sW + ci * 4);          // p=0 (ye, xe)
        float4 w01 = *(const float4*)(sW + 64 + ci * 4);     // p=1 (ye, xo)
        float4 w10 = *(const float4*)(sW + 128 + ci * 4);    // p=2 (yo, xe)
        float4 w11 = *(const float4*)(sW + 192 + ci * 4);    // p=3 (yo, xo)
        // y = 2i (top=row i-1, bot=row i)
        a00 = fmaf(w00.x, eA,   fmaf(w00.y, dA.x, fmaf(w00.z, eB,   fmaf(w00.w, dB.x, a00))));
        a01 = fmaf(w01.x, dA.x, fmaf(w01.y, dA.y, fmaf(w01.z, dB.x, fmaf(w01.w, dB.y, a01))));
        a02 = fmaf(w00.x, dA.x, fmaf(w00.y, dA.y, fmaf(w00.z, dB.x, fmaf(w00.w, dB.y, a02))));
        a03 = fmaf(w01.x, dA.y, fmaf(w01.y, fA,   fmaf(w01.z, dB.y, fmaf(w01.w, fB,   a03))));
        // y = 2i+1 (top=row i, bot=row i+1)
        a10 = fmaf(w10.x, eB,   fmaf(w10.y, dB.x, fmaf(w10.z, eC,   fmaf(w10.w, dC.x, a10))));
        a11 = fmaf(w11.x, dB.x, fmaf(w11.y, dB.y, fmaf(w11.z, dC.x, fmaf(w11.w, dC.y, a11))));
        a12 = fmaf(w10.x, dB.x, fmaf(w10.y, dB.y, fmaf(w10.z, dC.x, fmaf(w10.w, dC.y, a12))));
        a13 = fmaf(w11.x, dB.y, fmaf(w11.y, fB,   fmaf(w11.z, dC.y, fmaf(w11.w, fC,   a13))));
    }

    float* o = out + (b << 16) + ((2 * i) << 8) + 4 * j;
    float4 r0 = make_float4(fminf(fmaxf(a00 + bz, -1.f), 1.f),
                            fminf(fmaxf(a01 + bz, -1.f), 1.f),
                            fminf(fmaxf(a02 + bz, -1.f), 1.f),
                            fminf(fmaxf(a03 + bz, -1.f), 1.f));
    *(float4*)o = r0;
    float4 r1 = make_float4(fminf(fmaxf(a10 + bz, -1.f), 1.f),
                            fminf(fmaxf(a11 + bz, -1.f), 1.f),
                            fminf(fmaxf(a12 + bz, -1.f), 1.f),
                            fminf(fmaxf(a13 + bz, -1.f), 1.f));
    *(float4*)(o + 256) = r1;
}

// ---------------------------------------------------------------------------
extern "C" void kernel_launch(void* const* d_in, const int* in_sizes, int n_in,
                              void* d_out, int out_size) {
    const float* x   = (const float*)d_in[0];
    const float* e1w = (const float*)d_in[1];
    const float* e1b = (const float*)d_in[2];
    const float* e2w = (const float*)d_in[3];
    const float* e2b = (const float*)d_in[4];
    const float* cb  = (const float*)d_in[5];
    const float* d1w = (const float*)d_in[6];
    const float* d1b = (const float*)d_in[7];
    const float* d2w = (const float*)d_in[8];
    const float* d2b = (const float*)d_in[9];
    float* out = (float*)d_out;

    static int s_attr_done = 0;
    if (!s_attr_done) {
        cudaFuncSetAttribute(k3_vq, cudaFuncAttributeMaxDynamicSharedMemorySize,
                             K3_SMEM);
        s_attr_done = 1;
    }

    k1_conv1<<<2211, 256>>>(x, e1w, e1b, cb, d1w, d2w);   // conv1 + setup tail
    k2_conv2<<<2048, 128>>>(e2w, e2b);
    k3_vq<<<1024, 256, K3_SMEM>>>(cb, out);
    k4_dec1<<<1024, 256>>>(d1b);
    k5_dec2<<<1025, 256>>>(d2b, out);                      // + loss reduce block
}

// round 14
// speedup vs baseline: 1.6981x; 1.0097x over previous
#include <cuda_runtime.h>
#include <math.h>
#include <stdint.h>

// ---------------------------------------------------------------------------
// SimpleVQAutoEncoder on GB300 — FFMA2 encoder + mma.sync tf32 VQ + tf32 decoder
//
//   K1: [blocks <2048] conv1+maxpool2+gelu (FFMA2 pairs) -> g_h1
//       [blocks>=2048] setup: codebook norms/frags, decoder weight frags
//   K2: conv2(16->32,3x3,SAME) + maxpool2 (FFMA2)      -> g_h2 [32,32,64,64]
//   K3: VQ mma.sync tf32 3-pass split, ILP-2 tile pairs-> g_hq, indices, g_part
//   K4: up2 + conv d1(32->16) folded, tf32 mma GEMM    -> g_gg [32,16,128,128]
//   K5: up2 + conv d2(16->1) folded + clip; last block reduces commit loss
//
// Output layout (float32): [ y (32*256*256) | indices (32*64*64) | loss (1) ]
// ---------------------------------------------------------------------------

#define IDX_OFF   2097152
#define LOSS_OFF  2228224

typedef unsigned long long u64;

__device__ __forceinline__ u64 ffma2(u64 a, u64 b, u64 c) {
    u64 d;
    asm("fma.rn.f32x2 %0, %1, %2, %3;" : "=l"(d) : "l"(a), "l"(b), "l"(c));
    return d;
}
__device__ __forceinline__ u64 packff(float lo, float hi) {
    u64 d;
    asm("mov.b64 %0, {%1, %2};" : "=l"(d) : "f"(lo), "f"(hi));
    return d;
}
__device__ __forceinline__ float2 unpackff(u64 v) {
    float lo, hi;
    asm("mov.b64 {%0, %1}, %2;" : "=f"(lo), "=f"(hi) : "l"(v));
    return make_float2(lo, hi);
}
__device__ __forceinline__ float tf32r(float v) {
    uint32_t t;
    asm("cvt.rna.tf32.f32 %0, %1;" : "=r"(t) : "f"(v));
    return __uint_as_float(t);
}
// erf-based gelu: mathematically identical to x*normcdf(x), ~1 ulp different
__device__ __forceinline__ float gelu_fast(float v) {
    return 0.5f * v * (1.0f + erff(v * 0.70710678118654752f));
}

// m16n8k8 tf32 mma (sm_80+ PTX, valid at base sm_103 target)
__device__ __forceinline__ void mma8(float& c0, float& c1, float& c2, float& c3,
                                     uint32_t a0, uint32_t a1, uint32_t a2,
                                     uint32_t a3, uint32_t b0, uint32_t b1) {
    asm volatile(
        "mma.sync.aligned.m16n8k8.row.col.f32.tf32.tf32.f32 "
        "{%0,%1,%2,%3}, {%4,%5,%6,%7}, {%8,%9}, {%0,%1,%2,%3};"
        : "+f"(c0), "+f"(c1), "+f"(c2), "+f"(c3)
        : "r"(a0), "r"(a1), "r"(a2), "r"(a3), "r"(b0), "r"(b1));
}

// Intermediates (device globals: no allocation allowed)
__device__ float g_h1[32 * 16 * 128 * 128];   // 33.5 MB
__device__ float g_h2[32 * 32 * 64 * 64];     // 16.8 MB
__device__ float g_hq[32 * 32 * 64 * 64];     // 16.8 MB
__device__ float g_gg[32 * 16 * 128 * 128];   // 33.5 MB
__device__ float g_cnh[512];                  // 0.5*||codebook_k||^2
__device__ float g_cbF[64 * 32 * 16];         // packed VQ codebook frags
__device__ float g_W4[4 * 16 * 32 * 4];       // tf32 d1 weight A-fragments
__device__ float g_Wf2[4 * 16 * 4];           // folded d2 [p][ci][uv]
__device__ float g_part[1024];                // commit-loss partials

// ---------------------------------------------------------------------------
// Setup body (runs in K1's tail blocks).
// Nearest-up2 folding: output (y,x) reads a 2x2 hq patch; the 3x3 taps
// collapse per output parity (py,px) onto the 4 corners.
// ---------------------------------------------------------------------------
__device__ void setup_body(int t, const float* __restrict__ cb,
                           const float* __restrict__ d1w,
                           const float* __restrict__ d2w) {
    if (t < 8192) {
        int j = t & 3, lane = (t >> 2) & 31, kk = (t >> 7) & 15, p = t >> 11;
        int grp = lane >> 2, thr = lane & 3;
        int c = grp + (j & 1) * 8;
        int K = kk * 8 + thr + (j >> 1) * 4;
        int ci = K & 31, uv = K >> 5;
        int u = uv >> 1, v = uv & 1;
        int py = p >> 1, px = p & 1;
        float s = 0.f;
        #pragma unroll
        for (int dy = 0; dy < 3; ++dy) {
            int ug = (py == 0) ? (dy >= 1) : (dy >= 2);
            if (ug != u) continue;
            #pragma unroll
            for (int dx = 0; dx < 3; ++dx) {
                int vg = (px == 0) ? (dx >= 1) : (dx >= 2);
                if (vg != v) continue;
                s += d1w[((c * 32 + ci) * 3 + dy) * 3 + dx];
            }
        }
        g_W4[t] = tf32r(s);
    } else if (t < 8704) {
        int k = t - 8192;
        float s = 0.f;
        #pragma unroll
        for (int c = 0; c < 32; ++c) { float v = cb[k * 32 + c]; s = fmaf(v, v, s); }
        g_cnh[k] = 0.5f * s;
    } else if (t < 8960) {
        int e = t - 8704;
        int uv = e & 3, ci = (e >> 2) & 15, p = e >> 6;
        int py = p >> 1, px = p & 1, u = uv >> 1, v = uv & 1;
        float s = 0.f;
        #pragma unroll
        for (int dy = 0; dy < 3; ++dy) {
            int ug = (py == 0) ? (dy >= 1) : (dy >= 2);
            if (ug != u) continue;
            #pragma unroll
            for (int dx = 0; dx < 3; ++dx) {
                int vg = (px == 0) ? (dx >= 1) : (dx >= 2);
                if (vg != v) continue;
                s += d2w[ci * 9 + dy * 3 + dx];
            }
        }
        g_Wf2[(p * 16 + ci) * 4 + uv] = s;
    } else if (t < 41728) {
        int v = t - 8960;                 // 0..32767
        int e = v & 3, lane = (v >> 2) & 31, q = (v >> 7) & 3, nt = v >> 9;
        int grp = lane >> 2, thr = lane & 3;
        int j = q * 4 + e;
        int jj = j & 7;
        int ks = jj >> 1, half = jj & 1;
        int c = ks * 8 + thr + (half ? 4 : 0);
        float val = cb[(nt * 8 + grp) * 32 + c];
        float hi = __uint_as_float(__float_as_uint(val) & 0xFFFFE000u);
        g_cbF[v] = (j < 8) ? hi : (val - hi);
    }
}

// ---------------------------------------------------------------------------
// K1: conv1 + maxpool2 + gelu (erff), FFMA2 channel pairs.
// Thread = (b, i, j) pooled pixel, 16 channels (8 pairs).
// Blocks >= 2048 run the setup body instead.
// ---------------------------------------------------------------------------
__global__ void __launch_bounds__(256) k1_conv1(const float* __restrict__ x,
                                                const float* __restrict__ w,
                                                const float* __restrict__ bias,
                                                const float* __restrict__ cb,
                                                const float* __restrict__ d1w,
                                                const float* __restrict__ d2w) {
    int tid = threadIdx.x;
    if (blockIdx.x >= 2048) {
        setup_body((blockIdx.x - 2048) * 256 + tid, cb, d1w, d2w);
        return;
    }

    __shared__ __align__(8) float2 sw2[72];   // [pair*9+tap] = (w[2p], w[2p+1])
    __shared__ float sb[16];
    if (tid < 72) {
        int pr = tid / 9, tap = tid - pr * 9;
        sw2[tid] = make_float2(__ldg(w + (2 * pr) * 9 + tap),
                               __ldg(w + (2 * pr + 1) * 9 + tap));
    }
    if (tid < 16) sb[tid] = __ldg(bias + tid);
    __syncthreads();

    int lin = blockIdx.x * 256 + tid;
    int j = lin & 127, i = (lin >> 7) & 127, b = lin >> 14;
    const float* xb = x + (b << 16);

    u64 xv[4][4];
    #pragma unroll
    for (int r = 0; r < 4; ++r) {
        int ry = 2 * i - 1 + r;
        bool rok = (unsigned)ry < 256u;
        #pragma unroll
        for (int cc = 0; cc < 4; ++cc) {
            int cx = 2 * j - 1 + cc;
            float v = (rok && (unsigned)cx < 256u) ? __ldg(xb + ry * 256 + cx) : 0.f;
            xv[r][cc] = packff(v, v);
        }
    }

    #pragma unroll
    for (int pr = 0; pr < 8; ++pr) {
        u64 wv[9];
        #pragma unroll
        for (int k = 0; k < 9; ++k) wv[k] = *(const u64*)(sw2 + pr * 9 + k);
        u64 acc[4];
        #pragma unroll
        for (int q = 0; q < 4; ++q) acc[q] = 0ull;
        #pragma unroll
        for (int dy = 0; dy < 3; ++dy)
            #pragma unroll
            for (int dx = 0; dx < 3; ++dx) {
                u64 wk = wv[dy * 3 + dx];
                acc[0] = ffma2(wk, xv[dy][dx], acc[0]);
                acc[1] = ffma2(wk, xv[dy][dx + 1], acc[1]);
                acc[2] = ffma2(wk, xv[dy + 1][dx], acc[2]);
                acc[3] = ffma2(wk, xv[dy + 1][dx + 1], acc[3]);
            }
        float2 m0 = unpackff(acc[0]);
        float2 m1 = unpackff(acc[1]);
        float2 m2 = unpackff(acc[2]);
        float2 m3 = unpackff(acc[3]);
        float lo = fmaxf(fmaxf(m0.x, m1.x), fmaxf(m2.x, m3.x)) + sb[2 * pr];
        float hi = fmaxf(fmaxf(m0.y, m1.y), fmaxf(m2.y, m3.y)) + sb[2 * pr + 1];
        g_h1[((b * 16 + 2 * pr) << 14) + (i << 7) + j]     = gelu_fast(lo);
        g_h1[((b * 16 + 2 * pr + 1) << 14) + (i << 7) + j] = gelu_fast(hi);
    }
}

// ---------------------------------------------------------------------------
// K2: conv2(16->32) + maxpool2, FFMA2 on channel pairs, prepacked patch.
// ---------------------------------------------------------------------------
__global__ void __launch_bounds__(128) k2_conv2(const float* __restrict__ w,
                                                const float* __restrict__ bias) {
    __shared__ __align__(16) float swt[2304];  // [ci*9+tap][16c]
    __shared__ float sb[16];
    int tid = threadIdx.x;
    int lin = blockIdx.x * 128 + tid;
    int j = lin & 63, i = (lin >> 6) & 63, half = (lin >> 12) & 1, b = lin >> 13;

    for (int t = tid; t < 2304; t += 128) {
        int ci = t / 144, r = t - ci * 144;
        int tap = r >> 4, c = r & 15;
        swt[t] = __ldg(w + (half * 16 + c) * 144 + ci * 9 + tap);
    }
    if (tid < 16) sb[tid] = __ldg(bias + half * 16 + tid);
    __syncthreads();

    int ry[4], cx[4];
    bool rok[4], cok[4];
    #pragma unroll
    for (int r = 0; r < 4; ++r) {
        ry[r] = 2 * i - 1 + r; rok[r] = (unsigned)ry[r] < 128u;
        cx[r] = 2 * j - 1 + r; cok[r] = (unsigned)cx[r] < 128u;
    }

    u64 acc[4][8];
    #pragma unroll
    for (int p = 0; p < 4; ++p)
        #pragma unroll
        for (int q = 0; q < 8; ++q) acc[p][q] = 0ull;

    #pragma unroll 1
    for (int ci = 0; ci < 16; ++ci) {
        const float* src = g_h1 + ((b * 16 + ci) << 14);
        u64 patch[4][4];
        #pragma unroll
        for (int r = 0; r < 4; ++r)
            #pragma unroll
            for (int cc = 0; cc < 4; ++cc) {
                float v = (rok[r] && cok[cc]) ? src[(ry[r] << 7) + cx[cc]] : 0.f;
                patch[r][cc] = packff(v, v);
            }

        #pragma unroll
        for (int dy = 0; dy < 3; ++dy)
            #pragma unroll
            for (int dx = 0; dx < 3; ++dx) {
                const ulonglong2* W2 =
                    (const ulonglong2*)(swt + (ci * 9 + dy * 3 + dx) * 16);
                ulonglong2 wA = W2[0], wB = W2[1], wC = W2[2], wD = W2[3];
                #pragma unroll
                for (int p = 0; p < 4; ++p) {
                    u64 vp = patch[(p >> 1) + dy][(p & 1) + dx];
                    acc[p][0] = ffma2(wA.x, vp, acc[p][0]);
                    acc[p][1] = ffma2(wA.y, vp, acc[p][1]);
                    acc[p][2] = ffma2(wB.x, vp, acc[p][2]);
                    acc[p][3] = ffma2(wB.y, vp, acc[p][3]);
                    acc[p][4] = ffma2(wC.x, vp, acc[p][4]);
                    acc[p][5] = ffma2(wC.y, vp, acc[p][5]);
                    acc[p][6] = ffma2(wD.x, vp, acc[p][6]);
                    acc[p][7] = ffma2(wD.y, vp, acc[p][7]);
                }
            }
    }

    float* dst = g_h2 + ((b * 32 + half * 16) << 12) + (i << 6) + j;
    #pragma unroll
    for (int q = 0; q < 8; ++q) {
        float2 m0 = unpackff(acc[0][q]);
        float2 m1 = unpackff(acc[1][q]);
        float2 m2 = unpackff(acc[2][q]);
        float2 m3 = unpackff(acc[3][q]);
        float lo = fmaxf(fmaxf(m0.x, m1.x), fmaxf(m2.x, m3.x)) + sb[2 * q];
        float hi = fmaxf(fmaxf(m0.y, m1.y), fmaxf(m2.y, m3.y)) + sb[2 * q + 1];
        dst[(2 * q) << 12]     = lo;
        dst[(2 * q + 1) << 12] = hi;
    }
}

// ---------------------------------------------------------------------------
// K3: VQ via mma.sync tf32 3-pass split (hh + lh + hl), ILP-2 tile pairing:
// tiles nt and nt+1 accumulate into independent register sets with
// interleaved MMA issue (per-tile order unchanged -> bit-identical indices).
// 256 threads/CTA (8 warps x m16 tokens = 128 tokens), 3 CTAs/SM.
// argmax of f.c - 0.5||c||^2, lowest-index tie-break.
// ---------------------------------------------------------------------------
#define K3_CN   16384
#define K3_WS   (16384 + 512)
#define K3_SMEM ((16384 + 512 + 16) * 4)

__global__ void __launch_bounds__(256, 3) k3_vq(const float* __restrict__ cb,
                                                float* __restrict__ out) {
    extern __shared__ float sm3[];
    float* sF  = sm3;               // 16384 floats: one 256-code chunk
    float* sCn = sm3 + K3_CN;       // 512 half-norms
    float* sWs = sm3 + K3_WS;       // 8 warp partials

    int tid = threadIdx.x;
    int wid = tid >> 5, lane = tid & 31;
    int grp = lane >> 2, thr = lane & 3;
    int base = blockIdx.x * 128;           // global token base
    int b = base >> 12, ij0 = base & 4095;

    // ---- A fragments (16 tokens x K=32) from global into regs, hi/lo ----
    const float* fbase = g_h2 + (b << 17) + ij0 + wid * 16 + grp;
    uint32_t ahi[16], alo[16];
    #pragma unroll
    for (int ks = 0; ks < 4; ++ks) {
        int c0 = ks * 8 + thr, c1 = c0 + 4;
        float v00 = fbase[c0 << 12];
        float v10 = fbase[(c0 << 12) + 8];
        float v01 = fbase[c1 << 12];
        float v11 = fbase[(c1 << 12) + 8];
        uint32_t h;
        h = __float_as_uint(v00) & 0xFFFFE000u;
        ahi[ks * 4 + 0] = h; alo[ks * 4 + 0] = __float_as_uint(v00 - __uint_as_float(h));
        h = __float_as_uint(v10) & 0xFFFFE000u;
        ahi[ks * 4 + 1] = h; alo[ks * 4 + 1] = __float_as_uint(v10 - __uint_as_float(h));
        h = __float_as_uint(v01) & 0xFFFFE000u;
        ahi[ks * 4 + 2] = h; alo[ks * 4 + 2] = __float_as_uint(v01 - __uint_as_float(h));
        h = __float_as_uint(v11) & 0xFFFFE000u;
        ahi[ks * 4 + 3] = h; alo[ks * 4 + 3] = __float_as_uint(v11 - __uint_as_float(h));
    }
    sCn[tid] = g_cnh[tid];
    sCn[tid + 256] = g_cnh[tid + 256];

    float bv0 = -1e30f, bv1 = -1e30f;
    int bk0 = 0, bk1 = 0;

    #pragma unroll 1
    for (int ch = 0; ch < 2; ++ch) {
        __syncthreads();   // previous chunk fully consumed
        {
            const float4* src = (const float4*)(g_cbF + ch * 16384);
            float4* dst = (float4*)sF;
            #pragma unroll
            for (int t = 0; t < 16; ++t)
                dst[tid + t * 256] = __ldg(src + tid + t * 256);
        }
        __syncthreads();

        #pragma unroll 1
        for (int nt = 0; nt < 32; nt += 2) {
            const float4* fpA = (const float4*)sF + (nt * 4) * 32 + lane;
            const float4* fpB = fpA + 128;
            float cA0 = 0.f, cA1 = 0.f, cA2 = 0.f, cA3 = 0.f;
            float cB0 = 0.f, cB1 = 0.f, cB2 = 0.f, cB3 = 0.f;
            // hi planes (b = hi): hh + lh, ks0..3, tiles interleaved
            {
                float4 hA = fpA[0], hB = fpB[0];
                mma8(cA0,cA1,cA2,cA3, ahi[0],ahi[1],ahi[2],ahi[3],
                     __float_as_uint(hA.x), __float_as_uint(hA.y));
                mma8(cB0,cB1,cB2,cB3, ahi[0],ahi[1],ahi[2],ahi[3],
                     __float_as_uint(hB.x), __float_as_uint(hB.y));
                mma8(cA0,cA1,cA2,cA3, alo[0],alo[1],alo[2],alo[3],
                     __float_as_uint(hA.x), __float_as_uint(hA.y));
                mma8(cB0,cB1,cB2,cB3, alo[0],alo[1],alo[2],alo[3],
                     __float_as_uint(hB.x), __float_as_uint(hB.y));
                mma8(cA0,cA1,cA2,cA3, ahi[4],ahi[5],ahi[6],ahi[7],
                     __float_as_uint(hA.z), __float_as_uint(hA.w));
                mma8(cB0,cB1,cB2,cB3, ahi[4],ahi[5],ahi[6],ahi[7],
                     __float_as_uint(hB.z), __float_as_uint(hB.w));
                mma8(cA0,cA1,cA2,cA3, alo[4],alo[5],alo[6],alo[7],
                     __float_as_uint(hA.z), __float_as_uint(hA.w));
                mma8(cB0,cB1,cB2,cB3, alo[4],alo[5],alo[6],alo[7],
                     __float_as_uint(hB.z), __float_as_uint(hB.w));
            }
            {
                float4 hA = fpA[32], hB = fpB[32];
                mma8(cA0,cA1,cA2,cA3, ahi[8],ahi[9],ahi[10],ahi[11],
                     __float_as_uint(hA.x), __float_as_uint(hA.y));
                mma8(cB0,cB1,cB2,cB3, ahi[8],ahi[9],ahi[10],ahi[11],
                     __float_as_uint(hB.x), __float_as_uint(hB.y));
                mma8(cA0,cA1,cA2,cA3, alo[8],alo[9],alo[10],alo[11],
                     __float_as_uint(hA.x), __float_as_uint(hA.y));
                mma8(cB0,cB1,cB2,cB3, alo[8],alo[9],alo[10],alo[11],
                     __float_as_uint(hB.x), __float_as_uint(hB.y));
                mma8(cA0,cA1,cA2,cA3, ahi[12],ahi[13],ahi[14],ahi[15],
                     __float_as_uint(hA.z), __float_as_uint(hA.w));
                mma8(cB0,cB1,cB2,cB3, ahi[12],ahi[13],ahi[14],ahi[15],
                     __float_as_uint(hB.z), __float_as_uint(hB.w));
                mma8(cA0,cA1,cA2,cA3, alo[12],alo[13],alo[14],alo[15],
                     __float_as_uint(hA.z), __float_as_uint(hA.w));
                mma8(cB0,cB1,cB2,cB3, alo[12],alo[13],alo[14],alo[15],
                     __float_as_uint(hB.z), __float_as_uint(hB.w));
            }
            // lo planes (b = lo): hl only, ks0..3
            {
                float4 lA = fpA[64], lB = fpB[64];
                mma8(cA0,cA1,cA2,cA3, ahi[0],ahi[1],ahi[2],ahi[3],
                     __float_as_uint(lA.x), __float_as_uint(lA.y));
                mma8(cB0,cB1,cB2,cB3, ahi[0],ahi[1],ahi[2],ahi[3],
                     __float_as_uint(lB.x), __float_as_uint(lB.y));
                mma8(cA0,cA1,cA2,cA3, ahi[4],ahi[5],ahi[6],ahi[7],
                     __float_as_uint(lA.z), __float_as_uint(lA.w));
                mma8(cB0,cB1,cB2,cB3, ahi[4],ahi[5],ahi[6],ahi[7],
                     __float_as_uint(lB.z), __float_as_uint(lB.w));
            }
            {
                float4 lA = fpA[96], lB = fpB[96];
                mma8(cA0,cA1,cA2,cA3, ahi[8],ahi[9],ahi[10],ahi[11],
                     __float_as_uint(lA.x), __float_as_uint(lA.y));
                mma8(cB0,cB1,cB2,cB3, ahi[8],ahi[9],ahi[10],ahi[11],
                     __float_as_uint(lB.x), __float_as_uint(lB.y));
                mma8(cA0,cA1,cA2,cA3, ahi[12],ahi[13],ahi[14],ahi[15],
                     __float_as_uint(lA.z), __float_as_uint(lA.w));
                mma8(cB0,cB1,cB2,cB3, ahi[12],ahi[13],ahi[14],ahi[15],
                     __float_as_uint(lB.z), __float_as_uint(lB.w));
            }

            // epilogue tile A then tile B (ascending columns preserved)
            int colA = ch * 256 + nt * 8 + 2 * thr;
            float cn0 = sCn[colA], cn1 = sCn[colA + 1];
            float v;
            v = cA0 - cn0; if (v > bv0) { bv0 = v; bk0 = colA; }
            v = cA1 - cn1; if (v > bv0) { bv0 = v; bk0 = colA + 1; }
            v = cA2 - cn0; if (v > bv1) { bv1 = v; bk1 = colA; }
            v = cA3 - cn1; if (v > bv1) { bv1 = v; bk1 = colA + 1; }
            int colB = colA + 8;
            float cn2 = sCn[colB], cn3 = sCn[colB + 1];
            v = cB0 - cn2; if (v > bv0) { bv0 = v; bk0 = colB; }
            v = cB1 - cn3; if (v > bv0) { bv0 = v; bk0 = colB + 1; }
            v = cB2 - cn2; if (v > bv1) { bv1 = v; bk1 = colB; }
            v = cB3 - cn3; if (v > bv1) { bv1 = v; bk1 = colB + 1; }
        }
    }

    // ---- reduce across the 4 lanes of each row-group (lowest k on ties) ----
    #pragma unroll
    for (int o = 1; o <= 2; o <<= 1) {
        float ov = __shfl_xor_sync(0xffffffffu, bv0, o);
        int   ok = __shfl_xor_sync(0xffffffffu, bk0, o);
        if (ov > bv0 || (ov == bv0 && ok < bk0)) { bv0 = ov; bk0 = ok; }
        ov = __shfl_xor_sync(0xffffffffu, bv1, o);
        ok = __shfl_xor_sync(0xffffffffu, bk1, o);
        if (ov > bv1 || (ov == bv1 && ok < bk1)) { bv1 = ov; bk1 = ok; }
    }

    int tokl = wid * 16 + grp;
    if (thr == 0) out[IDX_OFF + base + tokl] = (float)bk0;
    if (thr == 2) out[IDX_OFF + base + tokl + 8] = (float)bk1;

    // ---- gather + commit-loss partials: 4 lanes = 2 tokens x 2 halves ----
    int mytok = tokl + ((thr >> 1) << 3);
    int myk   = (thr < 2) ? bk0 : bk1;
    int cbase = (thr & 1) << 4;
    const float* cbr = cb + myk * 32 + cbase;
    const float* h2p = g_h2 + (b << 17) + (cbase << 12) + ij0 + mytok;
    float*       hqp = g_hq + (b << 17) + (cbase << 12) + ij0 + mytok;
    float part = 0.f;
    #pragma unroll
    for (int c = 0; c < 16; ++c) {
        float qv = __ldg(cbr + c);
        float fv = h2p[c << 12];
        float d = qv - fv;
        part = fmaf(d, d, part);
        hqp[c << 12] = qv;
    }

    // deterministic block reduction (8 warps)
    #pragma unroll
    for (int o = 16; o > 0; o >>= 1)
        part += __shfl_down_sync(0xffffffffu, part, o);
    if (lane == 0) sWs[wid] = part;
    __syncthreads();
    if (tid == 0) {
        float s = 0.f;
        #pragma unroll
        for (int q = 0; q < 8; ++q) s += sWs[q];
        g_part[blockIdx.x] = s;
    }
}

// ---------------------------------------------------------------------------
// K4: up2 + conv d1 (parity-folded) via tf32 mma GEMM + gelu (erff-based).
// Block = (b, yq, x-half): output tile 16c x 8y x 64x. Warp = (parity p,
// row-half rh): acc 32 regs. A frags from global (L1-hot); hq tile
// (rna-rounded tf32) in smem stride 264 (conflict-free). 2 CTAs/SM
// (proven no-spill config; the 3-CTA/85-reg variant spilled and regressed).
// ---------------------------------------------------------------------------
__global__ void __launch_bounds__(256, 2) k4_dec1(const float* __restrict__ bias) {
    __shared__ __align__(16) float sm4[9232];
    float* sHq = sm4;            // union: hq tile (32*264=8448) / out (9216)
    float* sB  = sm4 + 9216;     // 16 bias

    int tid = threadIdx.x;
    int wid = tid >> 5, lane = tid & 31;
    int grp = lane >> 2, thr = lane & 3;
    int bk = blockIdx.x;
    int b = bk >> 5, yq = (bk >> 1) & 15, bxh = bk & 1;
    int yi0 = yq * 4;

    if (tid < 16) sB[tid] = __ldg(bias + tid);
    // stage hq rows yi0-1..yi0+4 (6 rows), 40 tile cols, col0 = 32*bxh - 4
    if (tid < 192) {
        int ci = tid / 6, r6 = tid - ci * 6;
        float* dst = sHq + ci * 264 + r6 * 40;
        int r = yi0 - 1 + r6;
        float4 z = make_float4(0.f, 0.f, 0.f, 0.f);
        if ((unsigned)r < 64u) {
            const float* srow = g_hq + ((b * 32 + ci) << 12) + (r << 6);
            if (bxh == 0) {
                *(float4*)dst = z;                       // pos 0..3 (cols <0)
                #pragma unroll
                for (int q = 0; q < 9; ++q) {            // cols 0..35 -> pos 4..39
                    float4 v = *(const float4*)(srow + q * 4);
                    v.x = tf32r(v.x); v.y = tf32r(v.y);
                    v.z = tf32r(v.z); v.w = tf32r(v.w);
                    *(float4*)(dst + 4 + q * 4) = v;
                }
            } else {
                #pragma unroll
                for (int q = 0; q < 9; ++q) {            // cols 28..63 -> pos 0..35
                    float4 v = *(const float4*)(srow + 28 + q * 4);
                    v.x = tf32r(v.x); v.y = tf32r(v.y);
                    v.z = tf32r(v.z); v.w = tf32r(v.w);
                    *(float4*)(dst + q * 4) = v;
                }
                *(float4*)(dst + 36) = z;                // pos 36..39 (cols >=64)
            }
        } else {
            #pragma unroll
            for (int q = 0; q < 10; ++q) *(float4*)(dst + q * 4) = z;
        }
    }
    __syncthreads();

    int p = wid & 3, rh = wid >> 2;
    int py = p >> 1, px = p & 1;

    float acc[2][4][4];
    #pragma unroll
    for (int r = 0; r < 2; ++r)
        #pragma unroll
        for (int n = 0; n < 4; ++n)
            #pragma unroll
            for (int q = 0; q < 4; ++q) acc[r][n][q] = 0.f;

    #pragma unroll
    for (int kk = 0; kk < 16; ++kk) {
        float4 af = __ldg((const float4*)(g_W4 + ((p * 16 + kk) * 32 + lane) * 4));
        int uv = kk >> 2;
        int du = (uv >> 1) + py - 1, dv = (uv & 1) + px - 1;
        int ci0 = (kk & 3) * 8;
        const float* B0 = sHq + (ci0 + thr) * 264 + (1 + du + 2 * rh) * 40
                          + 4 + dv + grp;
        uint32_t a0 = __float_as_uint(af.x), a1 = __float_as_uint(af.y);
        uint32_t a2 = __float_as_uint(af.z), a3 = __float_as_uint(af.w);
        #pragma unroll
        for (int r = 0; r < 2; ++r)
            #pragma unroll
            for (int nt = 0; nt < 4; ++nt) {
                uint32_t b0 = __float_as_uint(B0[r * 40 + nt * 8]);
                uint32_t b1 = __float_as_uint(B0[r * 40 + nt * 8 + 1056]);
                mma8(acc[r][nt][0], acc[r][nt][1], acc[r][nt][2], acc[r][nt][3],
                     a0, a1, a2, a3, b0, b1);
            }
    }

    __syncthreads();   // all warps done reading sHq
    float bias_lo = sB[grp], bias_hi = sB[grp + 8];
    float* sOut = sm4;   // reuse union: [8y][16c][72]
    #pragma unroll
    for (int r = 0; r < 2; ++r) {
        int yl = 2 * (2 * rh + r) + py;
        #pragma unroll
        for (int nt = 0; nt < 4; ++nt) {
            int x = 16 * nt + 4 * thr + px;
            float* o = sOut + yl * 1152 + x;
            float v0 = acc[r][nt][0] + bias_lo;
            float v1 = acc[r][nt][1] + bias_lo;
            float v2 = acc[r][nt][2] + bias_hi;
            float v3 = acc[r][nt][3] + bias_hi;
            o[grp * 72]           = gelu_fast(v0);
            o[grp * 72 + 2]       = gelu_fast(v1);
            o[(grp + 8) * 72]     = gelu_fast(v2);
            o[(grp + 8) * 72 + 2] = gelu_fast(v3);
        }
    }
    __syncthreads();
    // coalesced writeout: 16c x 8y x 64x
    #pragma unroll
    for (int q = 0; q < 8; ++q) {
        int idx = q * 256 + tid;          // float4 id
        int x4 = idx & 15, ch = (idx >> 4) & 15, yy = idx >> 8;
        float4 val = *(const float4*)(sOut + yy * 1152 + ch * 72 + x4 * 4);
        *(float4*)(g_gg + ((b * 16 + ch) << 14) + (((yq << 3) + yy) << 7)
                   + (bxh << 6) + x4 * 4) = val;
    }
}

// ---------------------------------------------------------------------------
// K5: up2 + conv d2 (parity-folded) + clip, 2x4 px/thread.
// Block 1024 reduces the commit-loss partials instead (k6 folded in).
// ---------------------------------------------------------------------------
__global__ void __launch_bounds__(256) k5_dec2(const float* __restrict__ bias,
                                               float* __restrict__ out) {
    int tid = threadIdx.x;

    if (blockIdx.x == 1024) {
        __shared__ float sm[256];
        sm[tid] = (g_part[tid] + g_part[tid + 256]) +
                  (g_part[tid + 512] + g_part[tid + 768]);
        __syncthreads();
        #pragma unroll
        for (int o = 128; o > 0; o >>= 1) {
            if (tid < o) sm[tid] += sm[tid + o];
            __syncthreads();
        }
        if (tid == 0) out[LOSS_OFF] = sm[0] * (1.0f / 4194304.0f);
        return;
    }

    __shared__ __align__(16) float sW[256];
    sW[tid] = g_Wf2[tid];
    __syncthreads();

    int lin = blockIdx.x * 256 + tid;
    int j = lin & 63, i = (lin >> 6) & 127, b = lin >> 13;
    bool topok = i > 0, botok = i < 127;
    bool eok = j > 0, fok = j < 63;
    float bz = __ldg(bias);

    float a00 = 0.f, a01 = 0.f, a02 = 0.f, a03 = 0.f;
    float a10 = 0.f, a11 = 0.f, a12 = 0.f, a13 = 0.f;

    #pragma unroll 1
    for (int ci = 0; ci < 16; ++ci) {
        const float* base = g_gg + ((b * 16 + ci) << 14) + 2 * j;
        float eA = 0.f, fA = 0.f, eB = 0.f, fB = 0.f, eC = 0.f, fC = 0.f;
        float2 dA = make_float2(0.f, 0.f), dC = dA, dB;
        const float* rB = base + (i << 7);
        dB = *(const float2*)rB;
        if (eok) eB = rB[-1];
        if (fok) fB = rB[2];
        if (topok) {
            const float* rA = base + ((i - 1) << 7);
            dA = *(const float2*)rA;
            if (eok) eA = rA[-1];
            if (fok) fA = rA[2];
        }
        if (botok) {
            const float* rC = base + ((i + 1) << 7);
            dC = *(const float2*)rC;
            if (eok) eC = rC[-1];
            if (fok) fC = rC[2];
        }
        float4 w00 = *(const float4*)(sW + ci * 4);          // p=0 (ye, xe)
        float4 w01 = *(const float4*)(sW + 64 + ci * 4);     // p=1 (ye, xo)
        float4 w10 = *(const float4*)(sW + 128 + ci * 4);    // p=2 (yo, xe)
        float4 w11 = *(const float4*)(sW + 192 + ci * 4);    // p=3 (yo, xo)
        // y = 2i (top=row i-1, bot=row i)
        a00 = fmaf(w00.x, eA,   fmaf(w00.y, dA.x, fmaf(w00.z, eB,   fmaf(w00.w, dB.x, a00))));
        a01 = fmaf(w01.x, dA.x, fmaf(w01.y, dA.y, fmaf(w01.z, dB.x, fmaf(w01.w, dB.y, a01))));
        a02 = fmaf(w00.x, dA.x, fmaf(w00.y, dA.y, fmaf(w00.z, dB.x, fmaf(w00.w, dB.y, a02))));
        a03 = fmaf(w01.x, dA.y, fmaf(w01.y, fA,   fmaf(w01.z, dB.y, fmaf(w01.w, fB,   a03))));
        // y = 2i+1 (top=row i, bot=row i+1)
        a10 = fmaf(w10.x, eB,   fmaf(w10.y, dB.x, fmaf(w10.z, eC,   fmaf(w10.w, dC.x, a10))));
        a11 = fmaf(w11.x, dB.x, fmaf(w11.y, dB.y, fmaf(w11.z, dC.x, fmaf(w11.w, dC.y, a11))));
        a12 = fmaf(w10.x, dB.x, fmaf(w10.y, dB.y, fmaf(w10.z, dC.x, fmaf(w10.w, dC.y, a12))));
        a13 = fmaf(w11.x, dB.y, fmaf(w11.y, fB,   fmaf(w11.z, dC.y, fmaf(w11.w, fC,   a13))));
    }

    float* o = out + (b << 16) + ((2 * i) << 8) + 4 * j;
    float4 r0 = make_float4(fminf(fmaxf(a00 + bz, -1.f), 1.f),
                            fminf(fmaxf(a01 + bz, -1.f), 1.f),
                            fminf(fmaxf(a02 + bz, -1.f), 1.f),
                            fminf(fmaxf(a03 + bz, -1.f), 1.f));
    *(float4*)o = r0;
    float4 r1 = make_float4(fminf(fmaxf(a10 + bz, -1.f), 1.f),
                            fminf(fmaxf(a11 + bz, -1.f), 1.f),
                            fminf(fmaxf(a12 + bz, -1.f), 1.f),
                            fminf(fmaxf(a13 + bz, -1.f), 1.f));
    *(float4*)(o + 256) = r1;
}

// ---------------------------------------------------------------------------
extern "C" void kernel_launch(void* const* d_in, const int* in_sizes, int n_in,
                              void* d_out, int out_size) {
    const float* x   = (const float*)d_in[0];
    const float* e1w = (const float*)d_in[1];
    const float* e1b = (const float*)d_in[2];
    const float* e2w = (const float*)d_in[3];
    const float* e2b = (const float*)d_in[4];
    const float* cb  = (const float*)d_in[5];
    const float* d1w = (const float*)d_in[6];
    const float* d1b = (const float*)d_in[7];
    const float* d2w = (const float*)d_in[8];
    const float* d2b = (const float*)d_in[9];
    float* out = (float*)d_out;

    static int s_attr_done = 0;
    if (!s_attr_done) {
        cudaFuncSetAttribute(k3_vq, cudaFuncAttributeMaxDynamicSharedMemorySize,
                             K3_SMEM);
        s_attr_done = 1;
    }

    k1_conv1<<<2211, 256>>>(x, e1w, e1b, cb, d1w, d2w);   // conv1 + setup tail
    k2_conv2<<<2048, 128>>>(e2w, e2b);
    k3_vq<<<1024, 256, K3_SMEM>>>(cb, out);
    k4_dec1<<<1024, 256>>>(d1b);
    k5_dec2<<<1025, 256>>>(d2b, out);                      // + loss reduce block
}